// round 2
// baseline (speedup 1.0000x reference)
#include <cuda_runtime.h>
#include <cstdint>

#define NTX    100000
#define NUSER  20000
#define NMERCH 5000
#define NEDGE  400000
#define HDIM   256
#define HHALF  128
#define FIN    32
#define NLAYER 2

// ---------------------------------------------------------------------------
// Workspace: single __device__ global (no allocations allowed in kernel_launch)
// ---------------------------------------------------------------------------
struct WS {
    float xt[2][NTX * HDIM];
    float xu[2][NUSER * HDIM];
    float xm[2][NMERCH * HDIM];
    float mtu[NTX * HDIM];     // mean of user features into tx
    float mtm[NTX * HDIM];     // mean of merch features into tx
    float mm [NMERCH * HDIM];  // mean of tx features into merch
    float mu [NUSER * HDIM];   // mean of tx features into user
    float h1c[NTX * HHALF];
    float h1v[NTX * HHALF];
    int deg   [4][NTX];
    int cursor[4][NTX];
    int rowptr[4][NTX + 1];
    int perm  [4][NEDGE];
};
__device__ WS g_ws;

// relations: 0 = user->tx, 1 = tx->merch, 2 = merch->tx, 3 = tx->user
// ---------------------------------------------------------------------------
// CSR build
// ---------------------------------------------------------------------------
__global__ void build_count(const int* __restrict__ d0, const int* __restrict__ d1,
                            const int* __restrict__ d2, const int* __restrict__ d3) {
    int i = blockIdx.x * blockDim.x + threadIdx.x;
    if (i >= NEDGE) return;
    int rel = blockIdx.y;
    const int* d = (rel == 0) ? d0 : (rel == 1) ? d1 : (rel == 2) ? d2 : d3;
    atomicAdd(&g_ws.deg[rel][d[i]], 1);
}

__global__ void scan4(int n0, int n1, int n2, int n3) {
    int rel = blockIdx.x;
    int n = (rel == 0) ? n0 : (rel == 1) ? n1 : (rel == 2) ? n2 : n3;
    const int* deg = g_ws.deg[rel];
    int* rp = g_ws.rowptr[rel];
    __shared__ int wsum[32];
    __shared__ int s_carry;
    int tid = threadIdx.x, lane = tid & 31, wid = tid >> 5;
    if (tid == 0) s_carry = 0;
    __syncthreads();
    for (int base = 0; base < n; base += 1024) {
        int i = base + tid;
        int v = (i < n) ? deg[i] : 0;
        int x = v;
        #pragma unroll
        for (int off = 1; off < 32; off <<= 1) {
            int u = __shfl_up_sync(0xffffffffu, x, off);
            if (lane >= off) x += u;
        }
        if (lane == 31) wsum[wid] = x;
        __syncthreads();
        if (wid == 0) {
            int w = wsum[lane];
            int y = w;
            #pragma unroll
            for (int off = 1; off < 32; off <<= 1) {
                int u = __shfl_up_sync(0xffffffffu, y, off);
                if (lane >= off) y += u;
            }
            wsum[lane] = y - w;  // exclusive warp offsets
        }
        __syncthreads();
        int incl = x + wsum[wid];
        int c = s_carry;
        __syncthreads();
        if (i < n) rp[i] = c + incl - v;
        if (tid == 1023) s_carry = c + incl;
        __syncthreads();
    }
    if (tid == 0) rp[n] = s_carry;
}

__global__ void build_fill(const int* __restrict__ s0, const int* __restrict__ d0,
                           const int* __restrict__ s1, const int* __restrict__ d1,
                           const int* __restrict__ s2, const int* __restrict__ d2,
                           const int* __restrict__ s3, const int* __restrict__ d3) {
    int i = blockIdx.x * blockDim.x + threadIdx.x;
    if (i >= NEDGE) return;
    int rel = blockIdx.y;
    const int* s = (rel == 0) ? s0 : (rel == 1) ? s1 : (rel == 2) ? s2 : s3;
    const int* d = (rel == 0) ? d0 : (rel == 1) ? d1 : (rel == 2) ? d2 : d3;
    int dst = d[i];
    int pos = g_ws.rowptr[rel][dst] + atomicAdd(&g_ws.cursor[rel][dst], 1);
    g_ws.perm[rel][pos] = s[i];
}

// ---------------------------------------------------------------------------
// Segment-mean: one warp per destination row, register accumulation (no atomics)
// ---------------------------------------------------------------------------
__global__ void seg_mean(const float* __restrict__ xsrc, int rel,
                         float* __restrict__ outm, int n_dst) {
    int w = (blockIdx.x * blockDim.x + threadIdx.x) >> 5;
    int lane = threadIdx.x & 31;
    if (w >= n_dst) return;
    const int* __restrict__ rp = g_ws.rowptr[rel];
    const int* __restrict__ pm = g_ws.perm[rel];
    int beg = rp[w], end = rp[w + 1];
    float4 a0 = make_float4(0.f, 0.f, 0.f, 0.f);
    float4 a1 = make_float4(0.f, 0.f, 0.f, 0.f);
    for (int e = beg; e < end; e++) {
        int s = pm[e];
        const float4* p = (const float4*)(xsrc + (size_t)s * HDIM);
        float4 v0 = p[lane];
        float4 v1 = p[lane + 32];
        a0.x += v0.x; a0.y += v0.y; a0.z += v0.z; a0.w += v0.w;
        a1.x += v1.x; a1.y += v1.y; a1.z += v1.z; a1.w += v1.w;
    }
    float inv = 1.0f / (float)max(end - beg, 1);
    a0.x *= inv; a0.y *= inv; a0.z *= inv; a0.w *= inv;
    a1.x *= inv; a1.y *= inv; a1.z *= inv; a1.w *= inv;
    float4* o = (float4*)(outm + (size_t)w * HDIM);
    o[lane] = a0;
    o[lane + 32] = a1;
}

// ---------------------------------------------------------------------------
// Fused multi-segment GEMM:  C = epi( sum_seg A[seg] @ W[seg] + b0 + b1 )
// epi: (+bias) * outscale, optional ReLU.  K per segment = segK, N = 128/256.
// Tiles 128x128x16, 256 threads, 8x8 microtile.
// ---------------------------------------------------------------------------
#define BM 128
#define BN 128
#define BK 16

struct GemmArgs {
    const float* A[4];
    const float* W[4];
    const float* b0;
    const float* b1;
    float* C;
    int M, N, nseg, segK;
    float outscale;
    int relu;
};

__global__ void __launch_bounds__(256, 2) gemm_fused(GemmArgs g) {
    __shared__ float As[BK][BM + 4];
    __shared__ float Ws[BK][BN + 4];
    int tid = threadIdx.x;
    int tx = tid & 15, ty = tid >> 4;
    int m0 = blockIdx.x * BM, n0 = blockIdx.y * BN;
    float acc[8][8];
    #pragma unroll
    for (int i = 0; i < 8; i++)
        #pragma unroll
        for (int j = 0; j < 8; j++) acc[i][j] = 0.f;

    int ktiles = g.nseg * g.segK / BK;
    int arow = tid >> 1, akk = (tid & 1) * 8;
    int wk = tid >> 4, wn = (tid & 15) * 8;

    for (int kt = 0; kt < ktiles; kt++) {
        int k0 = kt * BK;
        int seg = k0 / g.segK;
        int koff = k0 - seg * g.segK;
        const float* __restrict__ A = g.A[seg];
        const float* __restrict__ W = g.W[seg];

        float4 a0 = make_float4(0.f, 0.f, 0.f, 0.f), a1 = a0;
        int grow = m0 + arow;
        if (grow < g.M) {
            const float* p = A + (size_t)grow * g.segK + koff + akk;
            a0 = *(const float4*)p;
            a1 = *(const float4*)(p + 4);
        }
        As[akk + 0][arow] = a0.x; As[akk + 1][arow] = a0.y;
        As[akk + 2][arow] = a0.z; As[akk + 3][arow] = a0.w;
        As[akk + 4][arow] = a1.x; As[akk + 5][arow] = a1.y;
        As[akk + 6][arow] = a1.z; As[akk + 7][arow] = a1.w;

        const float* q = W + (size_t)(koff + wk) * g.N + n0 + wn;
        *(float4*)&Ws[wk][wn]     = *(const float4*)q;
        *(float4*)&Ws[wk][wn + 4] = *(const float4*)(q + 4);
        __syncthreads();

        #pragma unroll
        for (int k = 0; k < BK; k++) {
            float a[8], b[8];
            *(float4*)&a[0] = *(const float4*)&As[k][ty * 8];
            *(float4*)&a[4] = *(const float4*)&As[k][ty * 8 + 4];
            *(float4*)&b[0] = *(const float4*)&Ws[k][tx * 8];
            *(float4*)&b[4] = *(const float4*)&Ws[k][tx * 8 + 4];
            #pragma unroll
            for (int i = 0; i < 8; i++)
                #pragma unroll
                for (int j = 0; j < 8; j++)
                    acc[i][j] += a[i] * b[j];
        }
        __syncthreads();
    }

    float bias[8];
    #pragma unroll
    for (int j = 0; j < 8; j++) bias[j] = 0.f;
    if (g.b0) {
        #pragma unroll
        for (int j = 0; j < 8; j++) bias[j] += g.b0[n0 + tx * 8 + j];
    }
    if (g.b1) {
        #pragma unroll
        for (int j = 0; j < 8; j++) bias[j] += g.b1[n0 + tx * 8 + j];
    }

    #pragma unroll
    for (int i = 0; i < 8; i++) {
        int grow = m0 + ty * 8 + i;
        if (grow < g.M) {
            float v[8];
            #pragma unroll
            for (int j = 0; j < 8; j++) {
                float x = (acc[i][j] + bias[j]) * g.outscale;
                v[j] = g.relu ? fmaxf(x, 0.f) : x;
            }
            float* c = g.C + (size_t)grow * g.N + n0 + tx * 8;
            *(float4*)c       = *(float4*)&v[0];
            *(float4*)(c + 4) = *(float4*)&v[4];
        }
    }
}

// ---------------------------------------------------------------------------
// Head matvec: out[row] = dot(h1c[row], Wc2) + bc2 ; out[NTX+row] = revenue
// one warp per row
// ---------------------------------------------------------------------------
__global__ void head_out(const float* __restrict__ h1c, const float* __restrict__ h1v,
                         const float* __restrict__ Wc2, const float* __restrict__ bc2,
                         const float* __restrict__ Wv2, const float* __restrict__ bv2,
                         float* __restrict__ out) {
    int row = blockIdx.x * (blockDim.x >> 5) + (threadIdx.x >> 5);
    int lane = threadIdx.x & 31;
    if (row >= NTX) return;

    float4 wc = ((const float4*)Wc2)[lane];
    float4 hc = ((const float4*)(h1c + (size_t)row * HHALF))[lane];
    float sc = hc.x * wc.x + hc.y * wc.y + hc.z * wc.z + hc.w * wc.w;

    float4 wv = ((const float4*)Wv2)[lane];
    float4 hv = ((const float4*)(h1v + (size_t)row * HHALF))[lane];
    float sv = hv.x * wv.x + hv.y * wv.y + hv.z * wv.z + hv.w * wv.w;

    #pragma unroll
    for (int off = 16; off > 0; off >>= 1) {
        sc += __shfl_xor_sync(0xffffffffu, sc, off);
        sv += __shfl_xor_sync(0xffffffffu, sv, off);
    }
    if (lane == 0) {
        out[row]       = sc + bc2[0];
        out[NTX + row] = sv + bv2[0];
    }
}

// ---------------------------------------------------------------------------
// Host orchestration
// ---------------------------------------------------------------------------
static inline int ceil_div(int a, int b) { return (a + b - 1) / b; }

extern "C" void kernel_launch(void* const* d_in, const int* in_sizes, int n_in,
                              void* d_out, int out_size) {
    const float* x_tx   = (const float*)d_in[0];
    const float* x_user = (const float*)d_in[1];
    const float* x_merch= (const float*)d_in[2];
    const float* Wp     = (const float*)d_in[3];
    const float* bp     = (const float*)d_in[4];
    const float* Wl     = (const float*)d_in[5];
    const float* bl     = (const float*)d_in[6];
    const float* Wr     = (const float*)d_in[7];
    const float* Wc1    = (const float*)d_in[8];
    const float* bc1    = (const float*)d_in[9];
    const float* Wc2    = (const float*)d_in[10];
    const float* bc2    = (const float*)d_in[11];
    const float* Wv1    = (const float*)d_in[12];
    const float* bv1    = (const float*)d_in[13];
    const float* Wv2    = (const float*)d_in[14];
    const float* bv2    = (const float*)d_in[15];
    const int* e_ut_src = (const int*)d_in[16];
    const int* e_ut_dst = (const int*)d_in[17];
    const int* e_tm_src = (const int*)d_in[18];
    const int* e_tm_dst = (const int*)d_in[19];
    const int* e_mt_src = (const int*)d_in[20];
    const int* e_mt_dst = (const int*)d_in[21];
    const int* e_tu_src = (const int*)d_in[22];
    const int* e_tu_dst = (const int*)d_in[23];
    float* out = (float*)d_out;

    WS* ws = nullptr;
    cudaGetSymbolAddress((void**)&ws, g_ws);

    // ---- init node features ----
    // xt[0] = x_tx @ Wp + bp
    {
        GemmArgs a = {};
        a.A[0] = x_tx; a.W[0] = Wp; a.b0 = bp; a.b1 = nullptr;
        a.C = ws->xt[0]; a.M = NTX; a.N = HDIM; a.nseg = 1; a.segK = FIN;
        a.outscale = 1.0f; a.relu = 0;
        gemm_fused<<<dim3(ceil_div(NTX, BM), HDIM / BN), 256>>>(a);
    }
    cudaMemcpyAsync(ws->xu[0], x_user,  (size_t)NUSER  * HDIM * sizeof(float), cudaMemcpyDeviceToDevice, 0);
    cudaMemcpyAsync(ws->xm[0], x_merch, (size_t)NMERCH * HDIM * sizeof(float), cudaMemcpyDeviceToDevice, 0);

    // ---- build CSRs (once per launch; edges constant across layers) ----
    cudaMemsetAsync(ws->deg,    0, sizeof(ws->deg),    0);
    cudaMemsetAsync(ws->cursor, 0, sizeof(ws->cursor), 0);
    build_count<<<dim3(ceil_div(NEDGE, 256), 4), 256>>>(e_ut_dst, e_tm_dst, e_mt_dst, e_tu_dst);
    scan4<<<4, 1024>>>(NTX, NMERCH, NTX, NUSER);
    build_fill<<<dim3(ceil_div(NEDGE, 256), 4), 256>>>(e_ut_src, e_ut_dst, e_tm_src, e_tm_dst,
                                                       e_mt_src, e_mt_dst, e_tu_src, e_tu_dst);

    int cur = 0;
    for (int l = 0; l < NLAYER; l++) {
        float* xt  = ws->xt[cur];
        float* xu  = ws->xu[cur];
        float* xm  = ws->xm[cur];
        float* xtn = ws->xt[1 - cur];
        float* xun = ws->xu[1 - cur];
        float* xmn = ws->xm[1 - cur];

        // segment means (warp per destination row)
        seg_mean<<<ceil_div(NTX * 32, 256), 256>>>(xu, 0, ws->mtu, NTX);
        seg_mean<<<ceil_div(NMERCH * 32, 256), 256>>>(xt, 1, ws->mm, NMERCH);
        seg_mean<<<ceil_div(NTX * 32, 256), 256>>>(xm, 2, ws->mtm, NTX);
        seg_mean<<<ceil_div(NUSER * 32, 256), 256>>>(xt, 3, ws->mu, NUSER);

        const float* Wl0 = Wl + ((size_t)(l * 4 + 0)) * HDIM * HDIM;
        const float* Wl1 = Wl + ((size_t)(l * 4 + 1)) * HDIM * HDIM;
        const float* Wl2 = Wl + ((size_t)(l * 4 + 2)) * HDIM * HDIM;
        const float* Wl3 = Wl + ((size_t)(l * 4 + 3)) * HDIM * HDIM;
        const float* Wr0 = Wr + ((size_t)(l * 4 + 0)) * HDIM * HDIM;
        const float* Wr1 = Wr + ((size_t)(l * 4 + 1)) * HDIM * HDIM;
        const float* Wr2 = Wr + ((size_t)(l * 4 + 2)) * HDIM * HDIM;
        const float* Wr3 = Wr + ((size_t)(l * 4 + 3)) * HDIM * HDIM;
        const float* bl0 = bl + (size_t)(l * 4 + 0) * HDIM;
        const float* bl1 = bl + (size_t)(l * 4 + 1) * HDIM;
        const float* bl2 = bl + (size_t)(l * 4 + 2) * HDIM;
        const float* bl3 = bl + (size_t)(l * 4 + 3) * HDIM;

        // xt_new = relu(0.5*(mtu@Wl0 + bl0 + xt@Wr0 + mtm@Wl2 + bl2 + xt@Wr2))
        {
            GemmArgs a = {};
            a.A[0] = ws->mtu; a.W[0] = Wl0;
            a.A[1] = xt;      a.W[1] = Wr0;
            a.A[2] = ws->mtm; a.W[2] = Wl2;
            a.A[3] = xt;      a.W[3] = Wr2;
            a.b0 = bl0; a.b1 = bl2;
            a.C = xtn; a.M = NTX; a.N = HDIM; a.nseg = 4; a.segK = HDIM;
            a.outscale = 0.5f; a.relu = 1;
            gemm_fused<<<dim3(ceil_div(NTX, BM), HDIM / BN), 256>>>(a);
        }
        // xm_new = relu(mm@Wl1 + bl1 + xm@Wr1)
        {
            GemmArgs a = {};
            a.A[0] = ws->mm; a.W[0] = Wl1;
            a.A[1] = xm;     a.W[1] = Wr1;
            a.b0 = bl1; a.b1 = nullptr;
            a.C = xmn; a.M = NMERCH; a.N = HDIM; a.nseg = 2; a.segK = HDIM;
            a.outscale = 1.0f; a.relu = 1;
            gemm_fused<<<dim3(ceil_div(NMERCH, BM), HDIM / BN), 256>>>(a);
        }
        // xu_new = relu(mu@Wl3 + bl3 + xu@Wr3)
        {
            GemmArgs a = {};
            a.A[0] = ws->mu; a.W[0] = Wl3;
            a.A[1] = xu;     a.W[1] = Wr3;
            a.b0 = bl3; a.b1 = nullptr;
            a.C = xun; a.M = NUSER; a.N = HDIM; a.nseg = 2; a.segK = HDIM;
            a.outscale = 1.0f; a.relu = 1;
            gemm_fused<<<dim3(ceil_div(NUSER, BM), HDIM / BN), 256>>>(a);
        }
        cur ^= 1;
    }

    // ---- heads ----
    float* xtf = ws->xt[cur];
    {
        GemmArgs a = {};
        a.A[0] = xtf; a.W[0] = Wc1; a.b0 = bc1; a.b1 = nullptr;
        a.C = ws->h1c; a.M = NTX; a.N = HHALF; a.nseg = 1; a.segK = HDIM;
        a.outscale = 1.0f; a.relu = 1;
        gemm_fused<<<dim3(ceil_div(NTX, BM), HHALF / BN), 256>>>(a);
    }
    {
        GemmArgs a = {};
        a.A[0] = xtf; a.W[0] = Wv1; a.b0 = bv1; a.b1 = nullptr;
        a.C = ws->h1v; a.M = NTX; a.N = HHALF; a.nseg = 1; a.segK = HDIM;
        a.outscale = 1.0f; a.relu = 1;
        gemm_fused<<<dim3(ceil_div(NTX, BM), HHALF / BN), 256>>>(a);
    }
    head_out<<<ceil_div(NTX * 32, 256), 256>>>(ws->h1c, ws->h1v, Wc2, bc2, Wv2, bv2, out);
}

// round 3
// speedup vs baseline: 1.5729x; 1.5729x over previous
#include <cuda_runtime.h>
#include <cstdint>

#define NTX    100000
#define NUSER  20000
#define NMERCH 5000
#define NEDGE  400000
#define HDIM   256
#define HHALF  128
#define FIN    32
#define NLAYER 2

// ---------------------------------------------------------------------------
// Workspace (single __device__ global; no allocations allowed)
// ---------------------------------------------------------------------------
struct WS {
    float xt[2][NTX * HDIM];
    float xu[2][NUSER * HDIM];
    float xm[2][NMERCH * HDIM];
    float mtu[NTX * HDIM];
    float mtm[NTX * HDIM];
    float mm [NMERCH * HDIM];
    float mu [NUSER * HDIM];
    float h1c[NTX * HHALF];
    float h1v[NTX * HHALF];
    int deg   [4][NTX];
    int cursor[4][NTX];
    int rowptr[4][NTX + 1];
    int perm  [4][NEDGE];
};
__device__ WS g_ws;

// relations: 0 = user->tx, 1 = tx->merch, 2 = merch->tx, 3 = tx->user
// ---------------------------------------------------------------------------
// CSR build
// ---------------------------------------------------------------------------
__global__ void build_count(const int* __restrict__ d0, const int* __restrict__ d1,
                            const int* __restrict__ d2, const int* __restrict__ d3) {
    int i = blockIdx.x * blockDim.x + threadIdx.x;
    if (i >= NEDGE) return;
    int rel = blockIdx.y;
    const int* d = (rel == 0) ? d0 : (rel == 1) ? d1 : (rel == 2) ? d2 : d3;
    atomicAdd(&g_ws.deg[rel][d[i]], 1);
}

__global__ void scan4(int n0, int n1, int n2, int n3) {
    int rel = blockIdx.x;
    int n = (rel == 0) ? n0 : (rel == 1) ? n1 : (rel == 2) ? n2 : n3;
    const int* deg = g_ws.deg[rel];
    int* rp = g_ws.rowptr[rel];
    __shared__ int wsum[32];
    __shared__ int s_carry;
    int tid = threadIdx.x, lane = tid & 31, wid = tid >> 5;
    if (tid == 0) s_carry = 0;
    __syncthreads();
    for (int base = 0; base < n; base += 1024) {
        int i = base + tid;
        int v = (i < n) ? deg[i] : 0;
        int x = v;
        #pragma unroll
        for (int off = 1; off < 32; off <<= 1) {
            int u = __shfl_up_sync(0xffffffffu, x, off);
            if (lane >= off) x += u;
        }
        if (lane == 31) wsum[wid] = x;
        __syncthreads();
        if (wid == 0) {
            int w = wsum[lane];
            int y = w;
            #pragma unroll
            for (int off = 1; off < 32; off <<= 1) {
                int u = __shfl_up_sync(0xffffffffu, y, off);
                if (lane >= off) y += u;
            }
            wsum[lane] = y - w;
        }
        __syncthreads();
        int incl = x + wsum[wid];
        int c = s_carry;
        __syncthreads();
        if (i < n) rp[i] = c + incl - v;
        if (tid == 1023) s_carry = c + incl;
        __syncthreads();
    }
    if (tid == 0) rp[n] = s_carry;
}

__global__ void build_fill(const int* __restrict__ s0, const int* __restrict__ d0,
                           const int* __restrict__ s1, const int* __restrict__ d1,
                           const int* __restrict__ s2, const int* __restrict__ d2,
                           const int* __restrict__ s3, const int* __restrict__ d3) {
    int i = blockIdx.x * blockDim.x + threadIdx.x;
    if (i >= NEDGE) return;
    int rel = blockIdx.y;
    const int* s = (rel == 0) ? s0 : (rel == 1) ? s1 : (rel == 2) ? s2 : s3;
    const int* d = (rel == 0) ? d0 : (rel == 1) ? d1 : (rel == 2) ? d2 : d3;
    int dst = d[i];
    int pos = g_ws.rowptr[rel][dst] + atomicAdd(&g_ws.cursor[rel][dst], 1);
    g_ws.perm[rel][pos] = s[i];
}

// ---------------------------------------------------------------------------
// Segment-mean: warp per destination row, register accumulation
// ---------------------------------------------------------------------------
__global__ void seg_mean(const float* __restrict__ xsrc, int rel,
                         float* __restrict__ outm, int n_dst) {
    int w = (blockIdx.x * blockDim.x + threadIdx.x) >> 5;
    int lane = threadIdx.x & 31;
    if (w >= n_dst) return;
    const int* __restrict__ rp = g_ws.rowptr[rel];
    const int* __restrict__ pm = g_ws.perm[rel];
    int beg = rp[w], end = rp[w + 1];
    float4 a0 = make_float4(0.f, 0.f, 0.f, 0.f);
    float4 a1 = make_float4(0.f, 0.f, 0.f, 0.f);
    for (int e = beg; e < end; e++) {
        int s = pm[e];
        const float4* p = (const float4*)(xsrc + (size_t)s * HDIM);
        float4 v0 = p[lane];
        float4 v1 = p[lane + 32];
        a0.x += v0.x; a0.y += v0.y; a0.z += v0.z; a0.w += v0.w;
        a1.x += v1.x; a1.y += v1.y; a1.z += v1.z; a1.w += v1.w;
    }
    float inv = 1.0f / (float)max(end - beg, 1);
    a0.x *= inv; a0.y *= inv; a0.z *= inv; a0.w *= inv;
    a1.x *= inv; a1.y *= inv; a1.z *= inv; a1.w *= inv;
    float4* o = (float4*)(outm + (size_t)w * HDIM);
    o[lane] = a0;
    o[lane + 32] = a1;
}

// ---------------------------------------------------------------------------
// Fused multi-segment GEMM on tf32 tensor cores (mma.sync.m16n8k8)
// C = epi( sum_seg A[seg] @ W[seg] + b0 + b1 )
// Block tile 128x128x32, 256 threads = 8 warps in 4(m) x 2(n) grid,
// warp tile 32x64 = 2 m16 x 8 n8 MMA tiles, fp32 accumulate.
// ---------------------------------------------------------------------------
#define BM 128
#define BN 128
#define BK 32
#define SPAD 4

struct GemmArgs {
    const float* A[4];
    const float* W[4];
    const float* b0;
    const float* b1;
    float* C;
    int M, N, nseg, segK;
    float outscale;
    int relu;
};

__device__ __forceinline__ uint32_t f2tf32(float f) {
    uint32_t u;
    asm("cvt.rna.tf32.f32 %0, %1;" : "=r"(u) : "f"(f));
    return u;
}

__global__ void __launch_bounds__(256, 2) gemm_tf32(GemmArgs g) {
    __shared__ uint32_t As[BK][BM + SPAD];
    __shared__ uint32_t Ws[BK][BN + SPAD];

    int tid = threadIdx.x;
    int lane = tid & 31;
    int warp = tid >> 5;
    int wm = (warp & 3) * 32;       // warp m offset in block tile
    int wn = (warp >> 2) * 64;      // warp n offset in block tile
    int grp = lane >> 2;            // 0..7
    int tg  = lane & 3;             // 0..3

    int m0 = blockIdx.x * BM, n0 = blockIdx.y * BN;

    float acc[2][8][4];
    #pragma unroll
    for (int i = 0; i < 2; i++)
        #pragma unroll
        for (int j = 0; j < 8; j++)
            #pragma unroll
            for (int c = 0; c < 4; c++) acc[i][j][c] = 0.f;

    // load thread mapping
    int arow = tid & 127;           // A row within tile
    int ahalf = (tid >> 7) * 16;    // k offset 0 or 16
    int wk = tid >> 3;              // 0..31 W k-row
    int wnc = (tid & 7) * 16;       // W col offset

    int ktiles = g.nseg * g.segK / BK;

    for (int kt = 0; kt < ktiles; kt++) {
        int k0 = kt * BK;
        int seg = k0 / g.segK;
        int koff = k0 - seg * g.segK;
        const float* __restrict__ A = g.A[seg];
        const float* __restrict__ W = g.W[seg];

        // ---- load A tile (transpose to [k][m]) ----
        {
            int grow = m0 + arow;
            if (grow < g.M) {
                const float* p = A + (size_t)grow * g.segK + koff + ahalf;
                float4 v0 = *(const float4*)(p + 0);
                float4 v1 = *(const float4*)(p + 4);
                float4 v2 = *(const float4*)(p + 8);
                float4 v3 = *(const float4*)(p + 12);
                As[ahalf + 0][arow]  = f2tf32(v0.x);
                As[ahalf + 1][arow]  = f2tf32(v0.y);
                As[ahalf + 2][arow]  = f2tf32(v0.z);
                As[ahalf + 3][arow]  = f2tf32(v0.w);
                As[ahalf + 4][arow]  = f2tf32(v1.x);
                As[ahalf + 5][arow]  = f2tf32(v1.y);
                As[ahalf + 6][arow]  = f2tf32(v1.z);
                As[ahalf + 7][arow]  = f2tf32(v1.w);
                As[ahalf + 8][arow]  = f2tf32(v2.x);
                As[ahalf + 9][arow]  = f2tf32(v2.y);
                As[ahalf + 10][arow] = f2tf32(v2.z);
                As[ahalf + 11][arow] = f2tf32(v2.w);
                As[ahalf + 12][arow] = f2tf32(v3.x);
                As[ahalf + 13][arow] = f2tf32(v3.y);
                As[ahalf + 14][arow] = f2tf32(v3.z);
                As[ahalf + 15][arow] = f2tf32(v3.w);
            } else {
                #pragma unroll
                for (int j = 0; j < 16; j++) As[ahalf + j][arow] = 0u;
            }
        }
        // ---- load W tile [k][n] ----
        {
            const float* q = W + (size_t)(koff + wk) * g.N + n0 + wnc;
            float4 v0 = *(const float4*)(q + 0);
            float4 v1 = *(const float4*)(q + 4);
            float4 v2 = *(const float4*)(q + 8);
            float4 v3 = *(const float4*)(q + 12);
            Ws[wk][wnc + 0]  = f2tf32(v0.x);
            Ws[wk][wnc + 1]  = f2tf32(v0.y);
            Ws[wk][wnc + 2]  = f2tf32(v0.z);
            Ws[wk][wnc + 3]  = f2tf32(v0.w);
            Ws[wk][wnc + 4]  = f2tf32(v1.x);
            Ws[wk][wnc + 5]  = f2tf32(v1.y);
            Ws[wk][wnc + 6]  = f2tf32(v1.z);
            Ws[wk][wnc + 7]  = f2tf32(v1.w);
            Ws[wk][wnc + 8]  = f2tf32(v2.x);
            Ws[wk][wnc + 9]  = f2tf32(v2.y);
            Ws[wk][wnc + 10] = f2tf32(v2.z);
            Ws[wk][wnc + 11] = f2tf32(v2.w);
            Ws[wk][wnc + 12] = f2tf32(v3.x);
            Ws[wk][wnc + 13] = f2tf32(v3.y);
            Ws[wk][wnc + 14] = f2tf32(v3.z);
            Ws[wk][wnc + 15] = f2tf32(v3.w);
        }
        __syncthreads();

        #pragma unroll
        for (int ks = 0; ks < BK / 8; ks++) {
            int k8 = ks * 8;
            uint32_t afr[2][4];
            #pragma unroll
            for (int mi = 0; mi < 2; mi++) {
                int mb = wm + mi * 16;
                afr[mi][0] = As[k8 + tg][mb + grp];
                afr[mi][1] = As[k8 + tg][mb + grp + 8];
                afr[mi][2] = As[k8 + tg + 4][mb + grp];
                afr[mi][3] = As[k8 + tg + 4][mb + grp + 8];
            }
            uint32_t bfr[8][2];
            #pragma unroll
            for (int nt = 0; nt < 8; nt++) {
                int nb = wn + nt * 8 + grp;
                bfr[nt][0] = Ws[k8 + tg][nb];
                bfr[nt][1] = Ws[k8 + tg + 4][nb];
            }
            #pragma unroll
            for (int mi = 0; mi < 2; mi++) {
                #pragma unroll
                for (int nt = 0; nt < 8; nt++) {
                    asm volatile(
                        "mma.sync.aligned.m16n8k8.row.col.f32.tf32.tf32.f32 "
                        "{%0,%1,%2,%3}, {%4,%5,%6,%7}, {%8,%9}, {%0,%1,%2,%3};"
                        : "+f"(acc[mi][nt][0]), "+f"(acc[mi][nt][1]),
                          "+f"(acc[mi][nt][2]), "+f"(acc[mi][nt][3])
                        : "r"(afr[mi][0]), "r"(afr[mi][1]),
                          "r"(afr[mi][2]), "r"(afr[mi][3]),
                          "r"(bfr[nt][0]), "r"(bfr[nt][1]));
                }
            }
        }
        __syncthreads();
    }

    // ---- epilogue ----
    float bias[8][2];
    #pragma unroll
    for (int nt = 0; nt < 8; nt++) {
        int c = n0 + wn + nt * 8 + tg * 2;
        float b0v = 0.f, b1v = 0.f;
        if (g.b0) b0v = g.b0[c] + (g.b1 ? g.b1[c] : 0.f);
        if (g.b0) b1v = g.b0[c + 1] + (g.b1 ? g.b1[c + 1] : 0.f);
        bias[nt][0] = b0v;
        bias[nt][1] = b1v;
    }

    #pragma unroll
    for (int mi = 0; mi < 2; mi++) {
        int r0 = m0 + wm + mi * 16 + grp;
        int r1 = r0 + 8;
        #pragma unroll
        for (int nt = 0; nt < 8; nt++) {
            int c = n0 + wn + nt * 8 + tg * 2;
            if (r0 < g.M) {
                float v0 = (acc[mi][nt][0] + bias[nt][0]) * g.outscale;
                float v1 = (acc[mi][nt][1] + bias[nt][1]) * g.outscale;
                if (g.relu) { v0 = fmaxf(v0, 0.f); v1 = fmaxf(v1, 0.f); }
                *(float2*)(g.C + (size_t)r0 * g.N + c) = make_float2(v0, v1);
            }
            if (r1 < g.M) {
                float v0 = (acc[mi][nt][2] + bias[nt][0]) * g.outscale;
                float v1 = (acc[mi][nt][3] + bias[nt][1]) * g.outscale;
                if (g.relu) { v0 = fmaxf(v0, 0.f); v1 = fmaxf(v1, 0.f); }
                *(float2*)(g.C + (size_t)r1 * g.N + c) = make_float2(v0, v1);
            }
        }
    }
}

// ---------------------------------------------------------------------------
// Head matvec
// ---------------------------------------------------------------------------
__global__ void head_out(const float* __restrict__ h1c, const float* __restrict__ h1v,
                         const float* __restrict__ Wc2, const float* __restrict__ bc2,
                         const float* __restrict__ Wv2, const float* __restrict__ bv2,
                         float* __restrict__ out) {
    int row = blockIdx.x * (blockDim.x >> 5) + (threadIdx.x >> 5);
    int lane = threadIdx.x & 31;
    if (row >= NTX) return;

    float4 wc = ((const float4*)Wc2)[lane];
    float4 hc = ((const float4*)(h1c + (size_t)row * HHALF))[lane];
    float sc = hc.x * wc.x + hc.y * wc.y + hc.z * wc.z + hc.w * wc.w;

    float4 wv = ((const float4*)Wv2)[lane];
    float4 hv = ((const float4*)(h1v + (size_t)row * HHALF))[lane];
    float sv = hv.x * wv.x + hv.y * wv.y + hv.z * wv.z + hv.w * wv.w;

    #pragma unroll
    for (int off = 16; off > 0; off >>= 1) {
        sc += __shfl_xor_sync(0xffffffffu, sc, off);
        sv += __shfl_xor_sync(0xffffffffu, sv, off);
    }
    if (lane == 0) {
        out[row]       = sc + bc2[0];
        out[NTX + row] = sv + bv2[0];
    }
}

// ---------------------------------------------------------------------------
// Host orchestration
// ---------------------------------------------------------------------------
static inline int ceil_div(int a, int b) { return (a + b - 1) / b; }

extern "C" void kernel_launch(void* const* d_in, const int* in_sizes, int n_in,
                              void* d_out, int out_size) {
    const float* x_tx   = (const float*)d_in[0];
    const float* x_user = (const float*)d_in[1];
    const float* x_merch= (const float*)d_in[2];
    const float* Wp     = (const float*)d_in[3];
    const float* bp     = (const float*)d_in[4];
    const float* Wl     = (const float*)d_in[5];
    const float* bl     = (const float*)d_in[6];
    const float* Wr     = (const float*)d_in[7];
    const float* Wc1    = (const float*)d_in[8];
    const float* bc1    = (const float*)d_in[9];
    const float* Wc2    = (const float*)d_in[10];
    const float* bc2    = (const float*)d_in[11];
    const float* Wv1    = (const float*)d_in[12];
    const float* bv1    = (const float*)d_in[13];
    const float* Wv2    = (const float*)d_in[14];
    const float* bv2    = (const float*)d_in[15];
    const int* e_ut_src = (const int*)d_in[16];
    const int* e_ut_dst = (const int*)d_in[17];
    const int* e_tm_src = (const int*)d_in[18];
    const int* e_tm_dst = (const int*)d_in[19];
    const int* e_mt_src = (const int*)d_in[20];
    const int* e_mt_dst = (const int*)d_in[21];
    const int* e_tu_src = (const int*)d_in[22];
    const int* e_tu_dst = (const int*)d_in[23];
    float* out = (float*)d_out;

    WS* ws = nullptr;
    cudaGetSymbolAddress((void**)&ws, g_ws);

    // xt[0] = x_tx @ Wp + bp
    {
        GemmArgs a = {};
        a.A[0] = x_tx; a.W[0] = Wp; a.b0 = bp; a.b1 = nullptr;
        a.C = ws->xt[0]; a.M = NTX; a.N = HDIM; a.nseg = 1; a.segK = FIN;
        a.outscale = 1.0f; a.relu = 0;
        gemm_tf32<<<dim3(ceil_div(NTX, BM), HDIM / BN), 256>>>(a);
    }
    cudaMemcpyAsync(ws->xu[0], x_user,  (size_t)NUSER  * HDIM * sizeof(float), cudaMemcpyDeviceToDevice, 0);
    cudaMemcpyAsync(ws->xm[0], x_merch, (size_t)NMERCH * HDIM * sizeof(float), cudaMemcpyDeviceToDevice, 0);

    cudaMemsetAsync(ws->deg,    0, sizeof(ws->deg),    0);
    cudaMemsetAsync(ws->cursor, 0, sizeof(ws->cursor), 0);
    build_count<<<dim3(ceil_div(NEDGE, 256), 4), 256>>>(e_ut_dst, e_tm_dst, e_mt_dst, e_tu_dst);
    scan4<<<4, 1024>>>(NTX, NMERCH, NTX, NUSER);
    build_fill<<<dim3(ceil_div(NEDGE, 256), 4), 256>>>(e_ut_src, e_ut_dst, e_tm_src, e_tm_dst,
                                                       e_mt_src, e_mt_dst, e_tu_src, e_tu_dst);

    int cur = 0;
    for (int l = 0; l < NLAYER; l++) {
        float* xt  = ws->xt[cur];
        float* xu  = ws->xu[cur];
        float* xm  = ws->xm[cur];
        float* xtn = ws->xt[1 - cur];
        float* xun = ws->xu[1 - cur];
        float* xmn = ws->xm[1 - cur];

        seg_mean<<<ceil_div(NTX * 32, 256), 256>>>(xu, 0, ws->mtu, NTX);
        seg_mean<<<ceil_div(NMERCH * 32, 256), 256>>>(xt, 1, ws->mm, NMERCH);
        seg_mean<<<ceil_div(NTX * 32, 256), 256>>>(xm, 2, ws->mtm, NTX);
        seg_mean<<<ceil_div(NUSER * 32, 256), 256>>>(xt, 3, ws->mu, NUSER);

        const float* Wl0 = Wl + ((size_t)(l * 4 + 0)) * HDIM * HDIM;
        const float* Wl1 = Wl + ((size_t)(l * 4 + 1)) * HDIM * HDIM;
        const float* Wl2 = Wl + ((size_t)(l * 4 + 2)) * HDIM * HDIM;
        const float* Wl3 = Wl + ((size_t)(l * 4 + 3)) * HDIM * HDIM;
        const float* Wr0 = Wr + ((size_t)(l * 4 + 0)) * HDIM * HDIM;
        const float* Wr1 = Wr + ((size_t)(l * 4 + 1)) * HDIM * HDIM;
        const float* Wr2 = Wr + ((size_t)(l * 4 + 2)) * HDIM * HDIM;
        const float* Wr3 = Wr + ((size_t)(l * 4 + 3)) * HDIM * HDIM;
        const float* bl0 = bl + (size_t)(l * 4 + 0) * HDIM;
        const float* bl1 = bl + (size_t)(l * 4 + 1) * HDIM;
        const float* bl2 = bl + (size_t)(l * 4 + 2) * HDIM;
        const float* bl3 = bl + (size_t)(l * 4 + 3) * HDIM;

        {
            GemmArgs a = {};
            a.A[0] = ws->mtu; a.W[0] = Wl0;
            a.A[1] = xt;      a.W[1] = Wr0;
            a.A[2] = ws->mtm; a.W[2] = Wl2;
            a.A[3] = xt;      a.W[3] = Wr2;
            a.b0 = bl0; a.b1 = bl2;
            a.C = xtn; a.M = NTX; a.N = HDIM; a.nseg = 4; a.segK = HDIM;
            a.outscale = 0.5f; a.relu = 1;
            gemm_tf32<<<dim3(ceil_div(NTX, BM), HDIM / BN), 256>>>(a);
        }
        {
            GemmArgs a = {};
            a.A[0] = ws->mm; a.W[0] = Wl1;
            a.A[1] = xm;     a.W[1] = Wr1;
            a.b0 = bl1; a.b1 = nullptr;
            a.C = xmn; a.M = NMERCH; a.N = HDIM; a.nseg = 2; a.segK = HDIM;
            a.outscale = 1.0f; a.relu = 1;
            gemm_tf32<<<dim3(ceil_div(NMERCH, BM), HDIM / BN), 256>>>(a);
        }
        {
            GemmArgs a = {};
            a.A[0] = ws->mu; a.W[0] = Wl3;
            a.A[1] = xu;     a.W[1] = Wr3;
            a.b0 = bl3; a.b1 = nullptr;
            a.C = xun; a.M = NUSER; a.N = HDIM; a.nseg = 2; a.segK = HDIM;
            a.outscale = 1.0f; a.relu = 1;
            gemm_tf32<<<dim3(ceil_div(NUSER, BM), HDIM / BN), 256>>>(a);
        }
        cur ^= 1;
    }

    float* xtf = ws->xt[cur];
    {
        GemmArgs a = {};
        a.A[0] = xtf; a.W[0] = Wc1; a.b0 = bc1; a.b1 = nullptr;
        a.C = ws->h1c; a.M = NTX; a.N = HHALF; a.nseg = 1; a.segK = HDIM;
        a.outscale = 1.0f; a.relu = 1;
        gemm_tf32<<<dim3(ceil_div(NTX, BM), HHALF / BN), 256>>>(a);
    }
    {
        GemmArgs a = {};
        a.A[0] = xtf; a.W[0] = Wv1; a.b0 = bv1; a.b1 = nullptr;
        a.C = ws->h1v; a.M = NTX; a.N = HHALF; a.nseg = 1; a.segK = HDIM;
        a.outscale = 1.0f; a.relu = 1;
        gemm_tf32<<<dim3(ceil_div(NTX, BM), HHALF / BN), 256>>>(a);
    }
    head_out<<<ceil_div(NTX * 32, 256), 256>>>(ws->h1c, ws->h1v, Wc2, bc2, Wv2, bv2, out);
}

// round 4
// speedup vs baseline: 1.9087x; 1.2135x over previous
#include <cuda_runtime.h>
#include <cstdint>

#define NTX    100000
#define NUSER  20000
#define NMERCH 5000
#define NEDGE  400000
#define HDIM   256
#define HHALF  128
#define FIN    32
#define NLAYER 2

// ---------------------------------------------------------------------------
// Workspace (single __device__ global; no allocations allowed)
// ---------------------------------------------------------------------------
struct WS {
    float xt[2][NTX * HDIM];
    float xu[2][NUSER * HDIM];
    float xm[2][NMERCH * HDIM];
    float gtu[NTX * HDIM];       // seg-mean of (xu @ Wl0) into tx
    float gtm[NTX * HDIM];       // seg-mean of (xm @ Wl2) into tx
    float mm [NMERCH * HDIM];    // seg-mean of xt into merch
    float mu [NUSER * HDIM];     // seg-mean of xt into user
    float yu [NUSER * HDIM];     // xu @ Wl0
    float ym [NMERCH * HDIM];    // xm @ Wl2
    float h1c[NTX * HHALF];
    float h1v[NTX * HHALF];
    int deg   [4][NTX];
    int cursor[4][NTX];
    int rowptr[4][NTX + 1];
    int perm  [4][NEDGE];
};
__device__ WS g_ws;

// relations: 0 = user->tx, 1 = tx->merch, 2 = merch->tx, 3 = tx->user
// ---------------------------------------------------------------------------
// CSR build
// ---------------------------------------------------------------------------
__global__ void build_count(const int* __restrict__ d0, const int* __restrict__ d1,
                            const int* __restrict__ d2, const int* __restrict__ d3) {
    int i = blockIdx.x * blockDim.x + threadIdx.x;
    if (i >= NEDGE) return;
    int rel = blockIdx.y;
    const int* d = (rel == 0) ? d0 : (rel == 1) ? d1 : (rel == 2) ? d2 : d3;
    atomicAdd(&g_ws.deg[rel][d[i]], 1);
}

__global__ void scan4(int n0, int n1, int n2, int n3) {
    int rel = blockIdx.x;
    int n = (rel == 0) ? n0 : (rel == 1) ? n1 : (rel == 2) ? n2 : n3;
    const int* deg = g_ws.deg[rel];
    int* rp = g_ws.rowptr[rel];
    __shared__ int wsum[32];
    __shared__ int s_carry;
    int tid = threadIdx.x, lane = tid & 31, wid = tid >> 5;
    if (tid == 0) s_carry = 0;
    __syncthreads();
    for (int base = 0; base < n; base += 1024) {
        int i = base + tid;
        int v = (i < n) ? deg[i] : 0;
        int x = v;
        #pragma unroll
        for (int off = 1; off < 32; off <<= 1) {
            int u = __shfl_up_sync(0xffffffffu, x, off);
            if (lane >= off) x += u;
        }
        if (lane == 31) wsum[wid] = x;
        __syncthreads();
        if (wid == 0) {
            int w = wsum[lane];
            int y = w;
            #pragma unroll
            for (int off = 1; off < 32; off <<= 1) {
                int u = __shfl_up_sync(0xffffffffu, y, off);
                if (lane >= off) y += u;
            }
            wsum[lane] = y - w;
        }
        __syncthreads();
        int incl = x + wsum[wid];
        int c = s_carry;
        __syncthreads();
        if (i < n) rp[i] = c + incl - v;
        if (tid == 1023) s_carry = c + incl;
        __syncthreads();
    }
    if (tid == 0) rp[n] = s_carry;
}

__global__ void build_fill(const int* __restrict__ s0, const int* __restrict__ d0,
                           const int* __restrict__ s1, const int* __restrict__ d1,
                           const int* __restrict__ s2, const int* __restrict__ d2,
                           const int* __restrict__ s3, const int* __restrict__ d3) {
    int i = blockIdx.x * blockDim.x + threadIdx.x;
    if (i >= NEDGE) return;
    int rel = blockIdx.y;
    const int* s = (rel == 0) ? s0 : (rel == 1) ? s1 : (rel == 2) ? s2 : s3;
    const int* d = (rel == 0) ? d0 : (rel == 1) ? d1 : (rel == 2) ? d2 : d3;
    int dst = d[i];
    int pos = g_ws.rowptr[rel][dst] + atomicAdd(&g_ws.cursor[rel][dst], 1);
    g_ws.perm[rel][pos] = s[i];
}

// ---------------------------------------------------------------------------
// Segment-mean: warp per destination row, register accumulation
// ---------------------------------------------------------------------------
__global__ void seg_mean(const float* __restrict__ xsrc, int rel,
                         float* __restrict__ outm, int n_dst) {
    int w = (blockIdx.x * blockDim.x + threadIdx.x) >> 5;
    int lane = threadIdx.x & 31;
    if (w >= n_dst) return;
    const int* __restrict__ rp = g_ws.rowptr[rel];
    const int* __restrict__ pm = g_ws.perm[rel];
    int beg = rp[w], end = rp[w + 1];
    float4 a0 = make_float4(0.f, 0.f, 0.f, 0.f);
    float4 a1 = make_float4(0.f, 0.f, 0.f, 0.f);
    for (int e = beg; e < end; e++) {
        int s = pm[e];
        const float4* p = (const float4*)(xsrc + (size_t)s * HDIM);
        float4 v0 = p[lane];
        float4 v1 = p[lane + 32];
        a0.x += v0.x; a0.y += v0.y; a0.z += v0.z; a0.w += v0.w;
        a1.x += v1.x; a1.y += v1.y; a1.z += v1.z; a1.w += v1.w;
    }
    float inv = 1.0f / (float)max(end - beg, 1);
    a0.x *= inv; a0.y *= inv; a0.z *= inv; a0.w *= inv;
    a1.x *= inv; a1.y *= inv; a1.z *= inv; a1.w *= inv;
    float4* o = (float4*)(outm + (size_t)w * HDIM);
    o[lane] = a0;
    o[lane + 32] = a1;
}

// ---------------------------------------------------------------------------
// Fused multi-segment GEMM on tf32 tensor cores (mma.sync.m16n8k8)
// C = epi( sum_seg A[seg]@W[seg] + E0 + E1 + b0 + b1 )
// Block tile 128x128x32, 256 threads = 8 warps (4m x 2n), warp tile 32x64.
// ---------------------------------------------------------------------------
#define BM 128
#define BN 128
#define BK 32
#define SPAD 4

struct GemmArgs {
    const float* A[4];
    const float* W[4];
    const float* b0;
    const float* b1;
    const float* E0;   // optional elementwise addend [M,N]
    const float* E1;   // optional elementwise addend [M,N]
    float* C;
    int M, N, nseg, segK;
    float outscale;
    int relu;
};

__device__ __forceinline__ uint32_t f2tf32(float f) {
    uint32_t u;
    asm("cvt.rna.tf32.f32 %0, %1;" : "=r"(u) : "f"(f));
    return u;
}

__global__ void __launch_bounds__(256, 2) gemm_tf32(GemmArgs g) {
    __shared__ uint32_t As[BK][BM + SPAD];
    __shared__ uint32_t Ws[BK][BN + SPAD];

    int tid = threadIdx.x;
    int lane = tid & 31;
    int warp = tid >> 5;
    int wm = (warp & 3) * 32;
    int wn = (warp >> 2) * 64;
    int grp = lane >> 2;
    int tg  = lane & 3;

    int m0 = blockIdx.x * BM, n0 = blockIdx.y * BN;

    float acc[2][8][4];
    #pragma unroll
    for (int i = 0; i < 2; i++)
        #pragma unroll
        for (int j = 0; j < 8; j++)
            #pragma unroll
            for (int c = 0; c < 4; c++) acc[i][j][c] = 0.f;

    int arow = tid & 127;
    int ahalf = (tid >> 7) * 16;
    int wk = tid >> 3;
    int wnc = (tid & 7) * 16;

    int ktiles = g.nseg * g.segK / BK;

    for (int kt = 0; kt < ktiles; kt++) {
        int k0 = kt * BK;
        int seg = k0 / g.segK;
        int koff = k0 - seg * g.segK;
        const float* __restrict__ A = g.A[seg];
        const float* __restrict__ W = g.W[seg];

        {
            int grow = m0 + arow;
            if (grow < g.M) {
                const float* p = A + (size_t)grow * g.segK + koff + ahalf;
                float4 v0 = *(const float4*)(p + 0);
                float4 v1 = *(const float4*)(p + 4);
                float4 v2 = *(const float4*)(p + 8);
                float4 v3 = *(const float4*)(p + 12);
                As[ahalf + 0][arow]  = f2tf32(v0.x);
                As[ahalf + 1][arow]  = f2tf32(v0.y);
                As[ahalf + 2][arow]  = f2tf32(v0.z);
                As[ahalf + 3][arow]  = f2tf32(v0.w);
                As[ahalf + 4][arow]  = f2tf32(v1.x);
                As[ahalf + 5][arow]  = f2tf32(v1.y);
                As[ahalf + 6][arow]  = f2tf32(v1.z);
                As[ahalf + 7][arow]  = f2tf32(v1.w);
                As[ahalf + 8][arow]  = f2tf32(v2.x);
                As[ahalf + 9][arow]  = f2tf32(v2.y);
                As[ahalf + 10][arow] = f2tf32(v2.z);
                As[ahalf + 11][arow] = f2tf32(v2.w);
                As[ahalf + 12][arow] = f2tf32(v3.x);
                As[ahalf + 13][arow] = f2tf32(v3.y);
                As[ahalf + 14][arow] = f2tf32(v3.z);
                As[ahalf + 15][arow] = f2tf32(v3.w);
            } else {
                #pragma unroll
                for (int j = 0; j < 16; j++) As[ahalf + j][arow] = 0u;
            }
        }
        {
            const float* q = W + (size_t)(koff + wk) * g.N + n0 + wnc;
            float4 v0 = *(const float4*)(q + 0);
            float4 v1 = *(const float4*)(q + 4);
            float4 v2 = *(const float4*)(q + 8);
            float4 v3 = *(const float4*)(q + 12);
            Ws[wk][wnc + 0]  = f2tf32(v0.x);
            Ws[wk][wnc + 1]  = f2tf32(v0.y);
            Ws[wk][wnc + 2]  = f2tf32(v0.z);
            Ws[wk][wnc + 3]  = f2tf32(v0.w);
            Ws[wk][wnc + 4]  = f2tf32(v1.x);
            Ws[wk][wnc + 5]  = f2tf32(v1.y);
            Ws[wk][wnc + 6]  = f2tf32(v1.z);
            Ws[wk][wnc + 7]  = f2tf32(v1.w);
            Ws[wk][wnc + 8]  = f2tf32(v2.x);
            Ws[wk][wnc + 9]  = f2tf32(v2.y);
            Ws[wk][wnc + 10] = f2tf32(v2.z);
            Ws[wk][wnc + 11] = f2tf32(v2.w);
            Ws[wk][wnc + 12] = f2tf32(v3.x);
            Ws[wk][wnc + 13] = f2tf32(v3.y);
            Ws[wk][wnc + 14] = f2tf32(v3.z);
            Ws[wk][wnc + 15] = f2tf32(v3.w);
        }
        __syncthreads();

        #pragma unroll
        for (int ks = 0; ks < BK / 8; ks++) {
            int k8 = ks * 8;
            uint32_t afr[2][4];
            #pragma unroll
            for (int mi = 0; mi < 2; mi++) {
                int mb = wm + mi * 16;
                afr[mi][0] = As[k8 + tg][mb + grp];
                afr[mi][1] = As[k8 + tg][mb + grp + 8];
                afr[mi][2] = As[k8 + tg + 4][mb + grp];
                afr[mi][3] = As[k8 + tg + 4][mb + grp + 8];
            }
            uint32_t bfr[8][2];
            #pragma unroll
            for (int nt = 0; nt < 8; nt++) {
                int nb = wn + nt * 8 + grp;
                bfr[nt][0] = Ws[k8 + tg][nb];
                bfr[nt][1] = Ws[k8 + tg + 4][nb];
            }
            #pragma unroll
            for (int mi = 0; mi < 2; mi++) {
                #pragma unroll
                for (int nt = 0; nt < 8; nt++) {
                    asm volatile(
                        "mma.sync.aligned.m16n8k8.row.col.f32.tf32.tf32.f32 "
                        "{%0,%1,%2,%3}, {%4,%5,%6,%7}, {%8,%9}, {%0,%1,%2,%3};"
                        : "+f"(acc[mi][nt][0]), "+f"(acc[mi][nt][1]),
                          "+f"(acc[mi][nt][2]), "+f"(acc[mi][nt][3])
                        : "r"(afr[mi][0]), "r"(afr[mi][1]),
                          "r"(afr[mi][2]), "r"(afr[mi][3]),
                          "r"(bfr[nt][0]), "r"(bfr[nt][1]));
                }
            }
        }
        __syncthreads();
    }

    // ---- epilogue ----
    float bias[8][2];
    #pragma unroll
    for (int nt = 0; nt < 8; nt++) {
        int c = n0 + wn + nt * 8 + tg * 2;
        float b0v = 0.f, b1v = 0.f;
        if (g.b0) { b0v = g.b0[c] + (g.b1 ? g.b1[c] : 0.f); }
        if (g.b0) { b1v = g.b0[c + 1] + (g.b1 ? g.b1[c + 1] : 0.f); }
        bias[nt][0] = b0v;
        bias[nt][1] = b1v;
    }

    #pragma unroll
    for (int mi = 0; mi < 2; mi++) {
        int r0 = m0 + wm + mi * 16 + grp;
        int r1 = r0 + 8;
        #pragma unroll
        for (int nt = 0; nt < 8; nt++) {
            int c = n0 + wn + nt * 8 + tg * 2;
            if (r0 < g.M) {
                float e0 = 0.f, e1 = 0.f;
                if (g.E0) {
                    float2 t = *(const float2*)(g.E0 + (size_t)r0 * g.N + c);
                    e0 += t.x; e1 += t.y;
                }
                if (g.E1) {
                    float2 t = *(const float2*)(g.E1 + (size_t)r0 * g.N + c);
                    e0 += t.x; e1 += t.y;
                }
                float v0 = (acc[mi][nt][0] + bias[nt][0] + e0) * g.outscale;
                float v1 = (acc[mi][nt][1] + bias[nt][1] + e1) * g.outscale;
                if (g.relu) { v0 = fmaxf(v0, 0.f); v1 = fmaxf(v1, 0.f); }
                *(float2*)(g.C + (size_t)r0 * g.N + c) = make_float2(v0, v1);
            }
            if (r1 < g.M) {
                float e0 = 0.f, e1 = 0.f;
                if (g.E0) {
                    float2 t = *(const float2*)(g.E0 + (size_t)r1 * g.N + c);
                    e0 += t.x; e1 += t.y;
                }
                if (g.E1) {
                    float2 t = *(const float2*)(g.E1 + (size_t)r1 * g.N + c);
                    e0 += t.x; e1 += t.y;
                }
                float v0 = (acc[mi][nt][2] + bias[nt][0] + e0) * g.outscale;
                float v1 = (acc[mi][nt][3] + bias[nt][1] + e1) * g.outscale;
                if (g.relu) { v0 = fmaxf(v0, 0.f); v1 = fmaxf(v1, 0.f); }
                *(float2*)(g.C + (size_t)r1 * g.N + c) = make_float2(v0, v1);
            }
        }
    }
}

// ---------------------------------------------------------------------------
// Head matvec
// ---------------------------------------------------------------------------
__global__ void head_out(const float* __restrict__ h1c, const float* __restrict__ h1v,
                         const float* __restrict__ Wc2, const float* __restrict__ bc2,
                         const float* __restrict__ Wv2, const float* __restrict__ bv2,
                         float* __restrict__ out) {
    int row = blockIdx.x * (blockDim.x >> 5) + (threadIdx.x >> 5);
    int lane = threadIdx.x & 31;
    if (row >= NTX) return;

    float4 wc = ((const float4*)Wc2)[lane];
    float4 hc = ((const float4*)(h1c + (size_t)row * HHALF))[lane];
    float sc = hc.x * wc.x + hc.y * wc.y + hc.z * wc.z + hc.w * wc.w;

    float4 wv = ((const float4*)Wv2)[lane];
    float4 hv = ((const float4*)(h1v + (size_t)row * HHALF))[lane];
    float sv = hv.x * wv.x + hv.y * wv.y + hv.z * wv.z + hv.w * wv.w;

    #pragma unroll
    for (int off = 16; off > 0; off >>= 1) {
        sc += __shfl_xor_sync(0xffffffffu, sc, off);
        sv += __shfl_xor_sync(0xffffffffu, sv, off);
    }
    if (lane == 0) {
        out[row]       = sc + bc2[0];
        out[NTX + row] = sv + bv2[0];
    }
}

// ---------------------------------------------------------------------------
// Host orchestration
// ---------------------------------------------------------------------------
static inline int ceil_div(int a, int b) { return (a + b - 1) / b; }

extern "C" void kernel_launch(void* const* d_in, const int* in_sizes, int n_in,
                              void* d_out, int out_size) {
    const float* x_tx   = (const float*)d_in[0];
    const float* x_user = (const float*)d_in[1];
    const float* x_merch= (const float*)d_in[2];
    const float* Wp     = (const float*)d_in[3];
    const float* bp     = (const float*)d_in[4];
    const float* Wl     = (const float*)d_in[5];
    const float* bl     = (const float*)d_in[6];
    const float* Wr     = (const float*)d_in[7];
    const float* Wc1    = (const float*)d_in[8];
    const float* bc1    = (const float*)d_in[9];
    const float* Wc2    = (const float*)d_in[10];
    const float* bc2    = (const float*)d_in[11];
    const float* Wv1    = (const float*)d_in[12];
    const float* bv1    = (const float*)d_in[13];
    const float* Wv2    = (const float*)d_in[14];
    const float* bv2    = (const float*)d_in[15];
    const int* e_ut_src = (const int*)d_in[16];
    const int* e_ut_dst = (const int*)d_in[17];
    const int* e_tm_src = (const int*)d_in[18];
    const int* e_tm_dst = (const int*)d_in[19];
    const int* e_mt_src = (const int*)d_in[20];
    const int* e_mt_dst = (const int*)d_in[21];
    const int* e_tu_src = (const int*)d_in[22];
    const int* e_tu_dst = (const int*)d_in[23];
    float* out = (float*)d_out;

    WS* ws = nullptr;
    cudaGetSymbolAddress((void**)&ws, g_ws);

    // xt[0] = x_tx @ Wp + bp
    {
        GemmArgs a = {};
        a.A[0] = x_tx; a.W[0] = Wp; a.b0 = bp;
        a.C = ws->xt[0]; a.M = NTX; a.N = HDIM; a.nseg = 1; a.segK = FIN;
        a.outscale = 1.0f; a.relu = 0;
        gemm_tf32<<<dim3(ceil_div(NTX, BM), HDIM / BN), 256>>>(a);
    }
    cudaMemcpyAsync(ws->xu[0], x_user,  (size_t)NUSER  * HDIM * sizeof(float), cudaMemcpyDeviceToDevice, 0);
    cudaMemcpyAsync(ws->xm[0], x_merch, (size_t)NMERCH * HDIM * sizeof(float), cudaMemcpyDeviceToDevice, 0);

    cudaMemsetAsync(ws->deg,    0, sizeof(ws->deg),    0);
    cudaMemsetAsync(ws->cursor, 0, sizeof(ws->cursor), 0);
    build_count<<<dim3(ceil_div(NEDGE, 256), 4), 256>>>(e_ut_dst, e_tm_dst, e_mt_dst, e_tu_dst);
    scan4<<<4, 1024>>>(NTX, NMERCH, NTX, NUSER);
    build_fill<<<dim3(ceil_div(NEDGE, 256), 4), 256>>>(e_ut_src, e_ut_dst, e_tm_src, e_tm_dst,
                                                       e_mt_src, e_mt_dst, e_tu_src, e_tu_dst);

    int cur = 0;
    for (int l = 0; l < NLAYER; l++) {
        float* xt  = ws->xt[cur];
        float* xu  = ws->xu[cur];
        float* xm  = ws->xm[cur];
        float* xtn = ws->xt[1 - cur];
        float* xun = ws->xu[1 - cur];
        float* xmn = ws->xm[1 - cur];

        const float* Wl0 = Wl + ((size_t)(l * 4 + 0)) * HDIM * HDIM;
        const float* Wl1 = Wl + ((size_t)(l * 4 + 1)) * HDIM * HDIM;
        const float* Wl2 = Wl + ((size_t)(l * 4 + 2)) * HDIM * HDIM;
        const float* Wl3 = Wl + ((size_t)(l * 4 + 3)) * HDIM * HDIM;
        const float* Wr0 = Wr + ((size_t)(l * 4 + 0)) * HDIM * HDIM;
        const float* Wr1 = Wr + ((size_t)(l * 4 + 1)) * HDIM * HDIM;
        const float* Wr2 = Wr + ((size_t)(l * 4 + 2)) * HDIM * HDIM;
        const float* Wr3 = Wr + ((size_t)(l * 4 + 3)) * HDIM * HDIM;
        const float* bl0 = bl + (size_t)(l * 4 + 0) * HDIM;
        const float* bl1 = bl + (size_t)(l * 4 + 1) * HDIM;
        const float* bl2 = bl + (size_t)(l * 4 + 2) * HDIM;
        const float* bl3 = bl + (size_t)(l * 4 + 3) * HDIM;

        // Transform small-side sources first: yu = xu@Wl0, ym = xm@Wl2
        {
            GemmArgs a = {};
            a.A[0] = xu; a.W[0] = Wl0;
            a.C = ws->yu; a.M = NUSER; a.N = HDIM; a.nseg = 1; a.segK = HDIM;
            a.outscale = 1.0f; a.relu = 0;
            gemm_tf32<<<dim3(ceil_div(NUSER, BM), HDIM / BN), 256>>>(a);
        }
        {
            GemmArgs a = {};
            a.A[0] = xm; a.W[0] = Wl2;
            a.C = ws->ym; a.M = NMERCH; a.N = HDIM; a.nseg = 1; a.segK = HDIM;
            a.outscale = 1.0f; a.relu = 0;
            gemm_tf32<<<dim3(ceil_div(NMERCH, BM), HDIM / BN), 256>>>(a);
        }

        // Segment means
        seg_mean<<<ceil_div(NTX * 32, 256), 256>>>(ws->yu, 0, ws->gtu, NTX);     // mean(xu@Wl0) -> tx
        seg_mean<<<ceil_div(NTX * 32, 256), 256>>>(ws->ym, 2, ws->gtm, NTX);     // mean(xm@Wl2) -> tx
        seg_mean<<<ceil_div(NMERCH * 32, 256), 256>>>(xt, 1, ws->mm, NMERCH);    // mean(xt) -> merch
        seg_mean<<<ceil_div(NUSER * 32, 256), 256>>>(xt, 3, ws->mu, NUSER);      // mean(xt) -> user

        // xt_new = relu(0.5*(gtu + gtm + bl0 + bl2 + xt@Wr0 + xt@Wr2))
        {
            GemmArgs a = {};
            a.A[0] = xt; a.W[0] = Wr0;
            a.A[1] = xt; a.W[1] = Wr2;
            a.b0 = bl0; a.b1 = bl2;
            a.E0 = ws->gtu; a.E1 = ws->gtm;
            a.C = xtn; a.M = NTX; a.N = HDIM; a.nseg = 2; a.segK = HDIM;
            a.outscale = 0.5f; a.relu = 1;
            gemm_tf32<<<dim3(ceil_div(NTX, BM), HDIM / BN), 256>>>(a);
        }
        // xm_new = relu(mm@Wl1 + bl1 + xm@Wr1)
        {
            GemmArgs a = {};
            a.A[0] = ws->mm; a.W[0] = Wl1;
            a.A[1] = xm;     a.W[1] = Wr1;
            a.b0 = bl1;
            a.C = xmn; a.M = NMERCH; a.N = HDIM; a.nseg = 2; a.segK = HDIM;
            a.outscale = 1.0f; a.relu = 1;
            gemm_tf32<<<dim3(ceil_div(NMERCH, BM), HDIM / BN), 256>>>(a);
        }
        // xu_new = relu(mu@Wl3 + bl3 + xu@Wr3)
        {
            GemmArgs a = {};
            a.A[0] = ws->mu; a.W[0] = Wl3;
            a.A[1] = xu;     a.W[1] = Wr3;
            a.b0 = bl3;
            a.C = xun; a.M = NUSER; a.N = HDIM; a.nseg = 2; a.segK = HDIM;
            a.outscale = 1.0f; a.relu = 1;
            gemm_tf32<<<dim3(ceil_div(NUSER, BM), HDIM / BN), 256>>>(a);
        }
        cur ^= 1;
    }

    float* xtf = ws->xt[cur];
    {
        GemmArgs a = {};
        a.A[0] = xtf; a.W[0] = Wc1; a.b0 = bc1;
        a.C = ws->h1c; a.M = NTX; a.N = HHALF; a.nseg = 1; a.segK = HDIM;
        a.outscale = 1.0f; a.relu = 1;
        gemm_tf32<<<dim3(ceil_div(NTX, BM), HHALF / BN), 256>>>(a);
    }
    {
        GemmArgs a = {};
        a.A[0] = xtf; a.W[0] = Wv1; a.b0 = bv1;
        a.C = ws->h1v; a.M = NTX; a.N = HHALF; a.nseg = 1; a.segK = HDIM;
        a.outscale = 1.0f; a.relu = 1;
        gemm_tf32<<<dim3(ceil_div(NTX, BM), HHALF / BN), 256>>>(a);
    }
    head_out<<<ceil_div(NTX * 32, 256), 256>>>(ws->h1c, ws->h1v, Wc2, bc2, Wv2, bv2, out);
}

// round 5
// speedup vs baseline: 2.2187x; 1.1624x over previous
#include <cuda_runtime.h>
#include <cstdint>

#define NTX    100000
#define NUSER  20000
#define NMERCH 5000
#define NEDGE  400000
#define HDIM   256
#define HHALF  128
#define FIN    32
#define NLAYER 2

// ---------------------------------------------------------------------------
// Workspace (single __device__ global; no allocations allowed)
// ---------------------------------------------------------------------------
struct WS {
    float xt[2][NTX * HDIM];
    float xu[2][NUSER * HDIM];
    float xm[2][NMERCH * HDIM];
    float gts[NTX * HDIM];       // mean(xu@Wl0)->tx + mean(xm@Wl2)->tx (summed)
    float mm [NMERCH * HDIM];    // seg-mean of xt into merch
    float mu [NUSER * HDIM];     // seg-mean of xt into user
    float yu [NUSER * HDIM];     // xu @ Wl0
    float ym [NMERCH * HDIM];    // xm @ Wl2
    float h1c[NTX * HHALF];
    float h1v[NTX * HHALF];
    int deg   [4][NTX];
    int cursor[4][NTX];
    int rowptr[4][NTX + 1];
    int perm  [4][NEDGE];
};
__device__ WS g_ws;

// relations: 0 = user->tx, 1 = tx->merch, 2 = merch->tx, 3 = tx->user
// ---------------------------------------------------------------------------
// CSR build
// ---------------------------------------------------------------------------
__global__ void build_count(const int* __restrict__ d0, const int* __restrict__ d1,
                            const int* __restrict__ d2, const int* __restrict__ d3) {
    int i = blockIdx.x * blockDim.x + threadIdx.x;
    if (i >= NEDGE) return;
    int rel = blockIdx.y;
    const int* d = (rel == 0) ? d0 : (rel == 1) ? d1 : (rel == 2) ? d2 : d3;
    atomicAdd(&g_ws.deg[rel][d[i]], 1);
}

__global__ void scan4(int n0, int n1, int n2, int n3) {
    int rel = blockIdx.x;
    int n = (rel == 0) ? n0 : (rel == 1) ? n1 : (rel == 2) ? n2 : n3;
    const int* deg = g_ws.deg[rel];
    int* rp = g_ws.rowptr[rel];
    __shared__ int wsum[32];
    __shared__ int s_carry;
    int tid = threadIdx.x, lane = tid & 31, wid = tid >> 5;
    if (tid == 0) s_carry = 0;
    __syncthreads();
    for (int base = 0; base < n; base += 1024) {
        int i = base + tid;
        int v = (i < n) ? deg[i] : 0;
        int x = v;
        #pragma unroll
        for (int off = 1; off < 32; off <<= 1) {
            int u = __shfl_up_sync(0xffffffffu, x, off);
            if (lane >= off) x += u;
        }
        if (lane == 31) wsum[wid] = x;
        __syncthreads();
        if (wid == 0) {
            int w = wsum[lane];
            int y = w;
            #pragma unroll
            for (int off = 1; off < 32; off <<= 1) {
                int u = __shfl_up_sync(0xffffffffu, y, off);
                if (lane >= off) y += u;
            }
            wsum[lane] = y - w;
        }
        __syncthreads();
        int incl = x + wsum[wid];
        int c = s_carry;
        __syncthreads();
        if (i < n) rp[i] = c + incl - v;
        if (tid == 1023) s_carry = c + incl;
        __syncthreads();
    }
    if (tid == 0) rp[n] = s_carry;
}

__global__ void build_fill(const int* __restrict__ s0, const int* __restrict__ d0,
                           const int* __restrict__ s1, const int* __restrict__ d1,
                           const int* __restrict__ s2, const int* __restrict__ d2,
                           const int* __restrict__ s3, const int* __restrict__ d3) {
    int i = blockIdx.x * blockDim.x + threadIdx.x;
    if (i >= NEDGE) return;
    int rel = blockIdx.y;
    const int* s = (rel == 0) ? s0 : (rel == 1) ? s1 : (rel == 2) ? s2 : s3;
    const int* d = (rel == 0) ? d0 : (rel == 1) ? d1 : (rel == 2) ? d2 : d3;
    int dst = d[i];
    int pos = g_ws.rowptr[rel][dst] + atomicAdd(&g_ws.cursor[rel][dst], 1);
    g_ws.perm[rel][pos] = s[i];
}

// ---------------------------------------------------------------------------
// Segment-mean: warp per destination row, register accumulation
// ---------------------------------------------------------------------------
__global__ void seg_mean(const float* __restrict__ xsrc, int rel,
                         float* __restrict__ outm, int n_dst) {
    int w = (blockIdx.x * blockDim.x + threadIdx.x) >> 5;
    int lane = threadIdx.x & 31;
    if (w >= n_dst) return;
    const int* __restrict__ rp = g_ws.rowptr[rel];
    const int* __restrict__ pm = g_ws.perm[rel];
    int beg = rp[w], end = rp[w + 1];
    float4 a0 = make_float4(0.f, 0.f, 0.f, 0.f);
    float4 a1 = make_float4(0.f, 0.f, 0.f, 0.f);
    for (int e = beg; e < end; e++) {
        int s = pm[e];
        const float4* p = (const float4*)(xsrc + (size_t)s * HDIM);
        float4 v0 = p[lane];
        float4 v1 = p[lane + 32];
        a0.x += v0.x; a0.y += v0.y; a0.z += v0.z; a0.w += v0.w;
        a1.x += v1.x; a1.y += v1.y; a1.z += v1.z; a1.w += v1.w;
    }
    float inv = 1.0f / (float)max(end - beg, 1);
    a0.x *= inv; a0.y *= inv; a0.z *= inv; a0.w *= inv;
    a1.x *= inv; a1.y *= inv; a1.z *= inv; a1.w *= inv;
    float4* o = (float4*)(outm + (size_t)w * HDIM);
    o[lane] = a0;
    o[lane + 32] = a1;
}

// Dual segment-mean into tx: out = mean_rel0(ya) + mean_rel2(yb)
__global__ void seg_mean_dual(const float* __restrict__ ya, const float* __restrict__ yb,
                              float* __restrict__ outm) {
    int w = (blockIdx.x * blockDim.x + threadIdx.x) >> 5;
    int lane = threadIdx.x & 31;
    if (w >= NTX) return;

    float4 r0 = make_float4(0.f, 0.f, 0.f, 0.f);
    float4 r1 = make_float4(0.f, 0.f, 0.f, 0.f);

    {
        const int* __restrict__ rp = g_ws.rowptr[0];
        const int* __restrict__ pm = g_ws.perm[0];
        int beg = rp[w], end = rp[w + 1];
        float4 a0 = make_float4(0.f, 0.f, 0.f, 0.f);
        float4 a1 = make_float4(0.f, 0.f, 0.f, 0.f);
        for (int e = beg; e < end; e++) {
            int s = pm[e];
            const float4* p = (const float4*)(ya + (size_t)s * HDIM);
            float4 v0 = p[lane];
            float4 v1 = p[lane + 32];
            a0.x += v0.x; a0.y += v0.y; a0.z += v0.z; a0.w += v0.w;
            a1.x += v1.x; a1.y += v1.y; a1.z += v1.z; a1.w += v1.w;
        }
        float inv = 1.0f / (float)max(end - beg, 1);
        r0.x += a0.x * inv; r0.y += a0.y * inv; r0.z += a0.z * inv; r0.w += a0.w * inv;
        r1.x += a1.x * inv; r1.y += a1.y * inv; r1.z += a1.z * inv; r1.w += a1.w * inv;
    }
    {
        const int* __restrict__ rp = g_ws.rowptr[2];
        const int* __restrict__ pm = g_ws.perm[2];
        int beg = rp[w], end = rp[w + 1];
        float4 a0 = make_float4(0.f, 0.f, 0.f, 0.f);
        float4 a1 = make_float4(0.f, 0.f, 0.f, 0.f);
        for (int e = beg; e < end; e++) {
            int s = pm[e];
            const float4* p = (const float4*)(yb + (size_t)s * HDIM);
            float4 v0 = p[lane];
            float4 v1 = p[lane + 32];
            a0.x += v0.x; a0.y += v0.y; a0.z += v0.z; a0.w += v0.w;
            a1.x += v1.x; a1.y += v1.y; a1.z += v1.z; a1.w += v1.w;
        }
        float inv = 1.0f / (float)max(end - beg, 1);
        r0.x += a0.x * inv; r0.y += a0.y * inv; r0.z += a0.z * inv; r0.w += a0.w * inv;
        r1.x += a1.x * inv; r1.y += a1.y * inv; r1.z += a1.z * inv; r1.w += a1.w * inv;
    }

    float4* o = (float4*)(outm + (size_t)w * HDIM);
    o[lane] = r0;
    o[lane + 32] = r1;
}

// ---------------------------------------------------------------------------
// Fused multi-segment GEMM on tf32 tensor cores (mma.sync.m16n8k8)
// ---------------------------------------------------------------------------
#define BM 128
#define BN 128
#define BK 32
#define SPAD 4

struct GemmArgs {
    const float* A[4];
    const float* W[4];
    const float* b0;
    const float* b1;
    const float* E0;
    const float* E1;
    float* C;
    int M, N, nseg, segK;
    float outscale;
    int relu;
};

__device__ __forceinline__ uint32_t f2tf32(float f) {
    uint32_t u;
    asm("cvt.rna.tf32.f32 %0, %1;" : "=r"(u) : "f"(f));
    return u;
}

__global__ void __launch_bounds__(256, 2) gemm_tf32(GemmArgs g) {
    __shared__ uint32_t As[BK][BM + SPAD];
    __shared__ uint32_t Ws[BK][BN + SPAD];

    int tid = threadIdx.x;
    int lane = tid & 31;
    int warp = tid >> 5;
    int wm = (warp & 3) * 32;
    int wn = (warp >> 2) * 64;
    int grp = lane >> 2;
    int tg  = lane & 3;

    int m0 = blockIdx.x * BM, n0 = blockIdx.y * BN;

    float acc[2][8][4];
    #pragma unroll
    for (int i = 0; i < 2; i++)
        #pragma unroll
        for (int j = 0; j < 8; j++)
            #pragma unroll
            for (int c = 0; c < 4; c++) acc[i][j][c] = 0.f;

    int arow = tid & 127;
    int ahalf = (tid >> 7) * 16;
    int wk = tid >> 3;
    int wnc = (tid & 7) * 16;

    int ktiles = g.nseg * g.segK / BK;

    for (int kt = 0; kt < ktiles; kt++) {
        int k0 = kt * BK;
        int seg = k0 / g.segK;
        int koff = k0 - seg * g.segK;
        const float* __restrict__ A = g.A[seg];
        const float* __restrict__ W = g.W[seg];

        {
            int grow = m0 + arow;
            if (grow < g.M) {
                const float* p = A + (size_t)grow * g.segK + koff + ahalf;
                float4 v0 = *(const float4*)(p + 0);
                float4 v1 = *(const float4*)(p + 4);
                float4 v2 = *(const float4*)(p + 8);
                float4 v3 = *(const float4*)(p + 12);
                As[ahalf + 0][arow]  = f2tf32(v0.x);
                As[ahalf + 1][arow]  = f2tf32(v0.y);
                As[ahalf + 2][arow]  = f2tf32(v0.z);
                As[ahalf + 3][arow]  = f2tf32(v0.w);
                As[ahalf + 4][arow]  = f2tf32(v1.x);
                As[ahalf + 5][arow]  = f2tf32(v1.y);
                As[ahalf + 6][arow]  = f2tf32(v1.z);
                As[ahalf + 7][arow]  = f2tf32(v1.w);
                As[ahalf + 8][arow]  = f2tf32(v2.x);
                As[ahalf + 9][arow]  = f2tf32(v2.y);
                As[ahalf + 10][arow] = f2tf32(v2.z);
                As[ahalf + 11][arow] = f2tf32(v2.w);
                As[ahalf + 12][arow] = f2tf32(v3.x);
                As[ahalf + 13][arow] = f2tf32(v3.y);
                As[ahalf + 14][arow] = f2tf32(v3.z);
                As[ahalf + 15][arow] = f2tf32(v3.w);
            } else {
                #pragma unroll
                for (int j = 0; j < 16; j++) As[ahalf + j][arow] = 0u;
            }
        }
        {
            const float* q = W + (size_t)(koff + wk) * g.N + n0 + wnc;
            float4 v0 = *(const float4*)(q + 0);
            float4 v1 = *(const float4*)(q + 4);
            float4 v2 = *(const float4*)(q + 8);
            float4 v3 = *(const float4*)(q + 12);
            Ws[wk][wnc + 0]  = f2tf32(v0.x);
            Ws[wk][wnc + 1]  = f2tf32(v0.y);
            Ws[wk][wnc + 2]  = f2tf32(v0.z);
            Ws[wk][wnc + 3]  = f2tf32(v0.w);
            Ws[wk][wnc + 4]  = f2tf32(v1.x);
            Ws[wk][wnc + 5]  = f2tf32(v1.y);
            Ws[wk][wnc + 6]  = f2tf32(v1.z);
            Ws[wk][wnc + 7]  = f2tf32(v1.w);
            Ws[wk][wnc + 8]  = f2tf32(v2.x);
            Ws[wk][wnc + 9]  = f2tf32(v2.y);
            Ws[wk][wnc + 10] = f2tf32(v2.z);
            Ws[wk][wnc + 11] = f2tf32(v2.w);
            Ws[wk][wnc + 12] = f2tf32(v3.x);
            Ws[wk][wnc + 13] = f2tf32(v3.y);
            Ws[wk][wnc + 14] = f2tf32(v3.z);
            Ws[wk][wnc + 15] = f2tf32(v3.w);
        }
        __syncthreads();

        #pragma unroll
        for (int ks = 0; ks < BK / 8; ks++) {
            int k8 = ks * 8;
            uint32_t afr[2][4];
            #pragma unroll
            for (int mi = 0; mi < 2; mi++) {
                int mb = wm + mi * 16;
                afr[mi][0] = As[k8 + tg][mb + grp];
                afr[mi][1] = As[k8 + tg][mb + grp + 8];
                afr[mi][2] = As[k8 + tg + 4][mb + grp];
                afr[mi][3] = As[k8 + tg + 4][mb + grp + 8];
            }
            uint32_t bfr[8][2];
            #pragma unroll
            for (int nt = 0; nt < 8; nt++) {
                int nb = wn + nt * 8 + grp;
                bfr[nt][0] = Ws[k8 + tg][nb];
                bfr[nt][1] = Ws[k8 + tg + 4][nb];
            }
            #pragma unroll
            for (int mi = 0; mi < 2; mi++) {
                #pragma unroll
                for (int nt = 0; nt < 8; nt++) {
                    asm volatile(
                        "mma.sync.aligned.m16n8k8.row.col.f32.tf32.tf32.f32 "
                        "{%0,%1,%2,%3}, {%4,%5,%6,%7}, {%8,%9}, {%0,%1,%2,%3};"
                        : "+f"(acc[mi][nt][0]), "+f"(acc[mi][nt][1]),
                          "+f"(acc[mi][nt][2]), "+f"(acc[mi][nt][3])
                        : "r"(afr[mi][0]), "r"(afr[mi][1]),
                          "r"(afr[mi][2]), "r"(afr[mi][3]),
                          "r"(bfr[nt][0]), "r"(bfr[nt][1]));
                }
            }
        }
        __syncthreads();
    }

    float bias[8][2];
    #pragma unroll
    for (int nt = 0; nt < 8; nt++) {
        int c = n0 + wn + nt * 8 + tg * 2;
        float b0v = 0.f, b1v = 0.f;
        if (g.b0) { b0v = g.b0[c] + (g.b1 ? g.b1[c] : 0.f); }
        if (g.b0) { b1v = g.b0[c + 1] + (g.b1 ? g.b1[c + 1] : 0.f); }
        bias[nt][0] = b0v;
        bias[nt][1] = b1v;
    }

    #pragma unroll
    for (int mi = 0; mi < 2; mi++) {
        int r0 = m0 + wm + mi * 16 + grp;
        int r1 = r0 + 8;
        #pragma unroll
        for (int nt = 0; nt < 8; nt++) {
            int c = n0 + wn + nt * 8 + tg * 2;
            if (r0 < g.M) {
                float e0 = 0.f, e1 = 0.f;
                if (g.E0) {
                    float2 t = *(const float2*)(g.E0 + (size_t)r0 * g.N + c);
                    e0 += t.x; e1 += t.y;
                }
                if (g.E1) {
                    float2 t = *(const float2*)(g.E1 + (size_t)r0 * g.N + c);
                    e0 += t.x; e1 += t.y;
                }
                float v0 = (acc[mi][nt][0] + bias[nt][0] + e0) * g.outscale;
                float v1 = (acc[mi][nt][1] + bias[nt][1] + e1) * g.outscale;
                if (g.relu) { v0 = fmaxf(v0, 0.f); v1 = fmaxf(v1, 0.f); }
                *(float2*)(g.C + (size_t)r0 * g.N + c) = make_float2(v0, v1);
            }
            if (r1 < g.M) {
                float e0 = 0.f, e1 = 0.f;
                if (g.E0) {
                    float2 t = *(const float2*)(g.E0 + (size_t)r1 * g.N + c);
                    e0 += t.x; e1 += t.y;
                }
                if (g.E1) {
                    float2 t = *(const float2*)(g.E1 + (size_t)r1 * g.N + c);
                    e0 += t.x; e1 += t.y;
                }
                float v0 = (acc[mi][nt][2] + bias[nt][0] + e0) * g.outscale;
                float v1 = (acc[mi][nt][3] + bias[nt][1] + e1) * g.outscale;
                if (g.relu) { v0 = fmaxf(v0, 0.f); v1 = fmaxf(v1, 0.f); }
                *(float2*)(g.C + (size_t)r1 * g.N + c) = make_float2(v0, v1);
            }
        }
    }
}

// ---------------------------------------------------------------------------
// Head matvec
// ---------------------------------------------------------------------------
__global__ void head_out(const float* __restrict__ h1c, const float* __restrict__ h1v,
                         const float* __restrict__ Wc2, const float* __restrict__ bc2,
                         const float* __restrict__ Wv2, const float* __restrict__ bv2,
                         float* __restrict__ out) {
    int row = blockIdx.x * (blockDim.x >> 5) + (threadIdx.x >> 5);
    int lane = threadIdx.x & 31;
    if (row >= NTX) return;

    float4 wc = ((const float4*)Wc2)[lane];
    float4 hc = ((const float4*)(h1c + (size_t)row * HHALF))[lane];
    float sc = hc.x * wc.x + hc.y * wc.y + hc.z * wc.z + hc.w * wc.w;

    float4 wv = ((const float4*)Wv2)[lane];
    float4 hv = ((const float4*)(h1v + (size_t)row * HHALF))[lane];
    float sv = hv.x * wv.x + hv.y * wv.y + hv.z * wv.z + hv.w * wv.w;

    #pragma unroll
    for (int off = 16; off > 0; off >>= 1) {
        sc += __shfl_xor_sync(0xffffffffu, sc, off);
        sv += __shfl_xor_sync(0xffffffffu, sv, off);
    }
    if (lane == 0) {
        out[row]       = sc + bc2[0];
        out[NTX + row] = sv + bv2[0];
    }
}

// ---------------------------------------------------------------------------
// Host orchestration with fork/join stream concurrency (graph-capturable)
// ---------------------------------------------------------------------------
static inline int ceil_div(int a, int b) { return (a + b - 1) / b; }

extern "C" void kernel_launch(void* const* d_in, const int* in_sizes, int n_in,
                              void* d_out, int out_size) {
    const float* x_tx   = (const float*)d_in[0];
    const float* x_user = (const float*)d_in[1];
    const float* x_merch= (const float*)d_in[2];
    const float* Wp     = (const float*)d_in[3];
    const float* bp     = (const float*)d_in[4];
    const float* Wl     = (const float*)d_in[5];
    const float* bl     = (const float*)d_in[6];
    const float* Wr     = (const float*)d_in[7];
    const float* Wc1    = (const float*)d_in[8];
    const float* bc1    = (const float*)d_in[9];
    const float* Wc2    = (const float*)d_in[10];
    const float* bc2    = (const float*)d_in[11];
    const float* Wv1    = (const float*)d_in[12];
    const float* bv1    = (const float*)d_in[13];
    const float* Wv2    = (const float*)d_in[14];
    const float* bv2    = (const float*)d_in[15];
    const int* e_ut_src = (const int*)d_in[16];
    const int* e_ut_dst = (const int*)d_in[17];
    const int* e_tm_src = (const int*)d_in[18];
    const int* e_tm_dst = (const int*)d_in[19];
    const int* e_mt_src = (const int*)d_in[20];
    const int* e_mt_dst = (const int*)d_in[21];
    const int* e_tu_src = (const int*)d_in[22];
    const int* e_tu_dst = (const int*)d_in[23];
    float* out = (float*)d_out;

    WS* ws = nullptr;
    cudaGetSymbolAddress((void**)&ws, g_ws);

    // side streams + events, created once (host resources only)
    static cudaStream_t sB = nullptr, sC = nullptr;
    static cudaEvent_t ev[16];
    if (!sB) {
        cudaStreamCreateWithFlags(&sB, cudaStreamNonBlocking);
        cudaStreamCreateWithFlags(&sC, cudaStreamNonBlocking);
        for (int i = 0; i < 16; i++)
            cudaEventCreateWithFlags(&ev[i], cudaEventDisableTiming);
    }
    cudaStream_t s0 = 0;
    cudaEvent_t evFork0 = ev[0], evCsr = ev[1], evMcpy = ev[2];
    cudaEvent_t evForkL[2] = {ev[3], ev[4]};
    cudaEvent_t evYm[2]    = {ev[5], ev[6]};
    cudaEvent_t evB[2]     = {ev[7], ev[8]};
    cudaEvent_t evC[2]     = {ev[9], ev[10]};
    cudaEvent_t evForkH = ev[11], evHv = ev[12];

    // ---- prologue fork: proj GEMM (s0) || CSR build (sB) || memcpys (sC) ----
    cudaEventRecord(evFork0, s0);
    cudaStreamWaitEvent(sB, evFork0, 0);
    cudaStreamWaitEvent(sC, evFork0, 0);

    {   // s0: xt[0] = x_tx @ Wp + bp
        GemmArgs a = {};
        a.A[0] = x_tx; a.W[0] = Wp; a.b0 = bp;
        a.C = ws->xt[0]; a.M = NTX; a.N = HDIM; a.nseg = 1; a.segK = FIN;
        a.outscale = 1.0f; a.relu = 0;
        gemm_tf32<<<dim3(ceil_div(NTX, BM), HDIM / BN), 256, 0, s0>>>(a);
    }
    // sB: CSR build
    cudaMemsetAsync(ws->deg,    0, sizeof(ws->deg),    sB);
    cudaMemsetAsync(ws->cursor, 0, sizeof(ws->cursor), sB);
    build_count<<<dim3(ceil_div(NEDGE, 256), 4), 256, 0, sB>>>(e_ut_dst, e_tm_dst, e_mt_dst, e_tu_dst);
    scan4<<<4, 1024, 0, sB>>>(NTX, NMERCH, NTX, NUSER);
    build_fill<<<dim3(ceil_div(NEDGE, 256), 4), 256, 0, sB>>>(e_ut_src, e_ut_dst, e_tm_src, e_tm_dst,
                                                              e_mt_src, e_mt_dst, e_tu_src, e_tu_dst);
    cudaEventRecord(evCsr, sB);
    // sC: copy user/merch features
    cudaMemcpyAsync(ws->xu[0], x_user,  (size_t)NUSER  * HDIM * sizeof(float), cudaMemcpyDeviceToDevice, sC);
    cudaMemcpyAsync(ws->xm[0], x_merch, (size_t)NMERCH * HDIM * sizeof(float), cudaMemcpyDeviceToDevice, sC);
    cudaEventRecord(evMcpy, sC);

    cudaStreamWaitEvent(s0, evCsr, 0);
    cudaStreamWaitEvent(s0, evMcpy, 0);

    int cur = 0;
    for (int l = 0; l < NLAYER; l++) {
        float* xt  = ws->xt[cur];
        float* xu  = ws->xu[cur];
        float* xm  = ws->xm[cur];
        float* xtn = ws->xt[1 - cur];
        float* xun = ws->xu[1 - cur];
        float* xmn = ws->xm[1 - cur];

        const float* Wl0 = Wl + ((size_t)(l * 4 + 0)) * HDIM * HDIM;
        const float* Wl1 = Wl + ((size_t)(l * 4 + 1)) * HDIM * HDIM;
        const float* Wl2 = Wl + ((size_t)(l * 4 + 2)) * HDIM * HDIM;
        const float* Wl3 = Wl + ((size_t)(l * 4 + 3)) * HDIM * HDIM;
        const float* Wr0 = Wr + ((size_t)(l * 4 + 0)) * HDIM * HDIM;
        const float* Wr1 = Wr + ((size_t)(l * 4 + 1)) * HDIM * HDIM;
        const float* Wr2 = Wr + ((size_t)(l * 4 + 2)) * HDIM * HDIM;
        const float* Wr3 = Wr + ((size_t)(l * 4 + 3)) * HDIM * HDIM;
        const float* bl0 = bl + (size_t)(l * 4 + 0) * HDIM;
        const float* bl1 = bl + (size_t)(l * 4 + 1) * HDIM;
        const float* bl2 = bl + (size_t)(l * 4 + 2) * HDIM;
        const float* bl3 = bl + (size_t)(l * 4 + 3) * HDIM;

        // fork
        cudaEventRecord(evForkL[l], s0);
        cudaStreamWaitEvent(sB, evForkL[l], 0);
        cudaStreamWaitEvent(sC, evForkL[l], 0);

        // --- sB: ym = xm@Wl2 ; then seg_mean(xt->mm) ; xm_new GEMM ---
        {
            GemmArgs a = {};
            a.A[0] = xm; a.W[0] = Wl2;
            a.C = ws->ym; a.M = NMERCH; a.N = HDIM; a.nseg = 1; a.segK = HDIM;
            a.outscale = 1.0f; a.relu = 0;
            gemm_tf32<<<dim3(ceil_div(NMERCH, BM), HDIM / BN), 256, 0, sB>>>(a);
        }
        cudaEventRecord(evYm[l], sB);
        seg_mean<<<ceil_div(NMERCH * 32, 256), 256, 0, sB>>>(xt, 1, ws->mm, NMERCH);
        {
            GemmArgs a = {};
            a.A[0] = ws->mm; a.W[0] = Wl1;
            a.A[1] = xm;     a.W[1] = Wr1;
            a.b0 = bl1;
            a.C = xmn; a.M = NMERCH; a.N = HDIM; a.nseg = 2; a.segK = HDIM;
            a.outscale = 1.0f; a.relu = 1;
            gemm_tf32<<<dim3(ceil_div(NMERCH, BM), HDIM / BN), 256, 0, sB>>>(a);
        }
        cudaEventRecord(evB[l], sB);

        // --- sC: seg_mean(xt->mu) ; xu_new GEMM ---
        seg_mean<<<ceil_div(NUSER * 32, 256), 256, 0, sC>>>(xt, 3, ws->mu, NUSER);
        {
            GemmArgs a = {};
            a.A[0] = ws->mu; a.W[0] = Wl3;
            a.A[1] = xu;     a.W[1] = Wr3;
            a.b0 = bl3;
            a.C = xun; a.M = NUSER; a.N = HDIM; a.nseg = 2; a.segK = HDIM;
            a.outscale = 1.0f; a.relu = 1;
            gemm_tf32<<<dim3(ceil_div(NUSER, BM), HDIM / BN), 256, 0, sC>>>(a);
        }
        cudaEventRecord(evC[l], sC);

        // --- s0: yu = xu@Wl0 ; wait ym ; dual seg-mean ; big xt GEMM ---
        {
            GemmArgs a = {};
            a.A[0] = xu; a.W[0] = Wl0;
            a.C = ws->yu; a.M = NUSER; a.N = HDIM; a.nseg = 1; a.segK = HDIM;
            a.outscale = 1.0f; a.relu = 0;
            gemm_tf32<<<dim3(ceil_div(NUSER, BM), HDIM / BN), 256, 0, s0>>>(a);
        }
        cudaStreamWaitEvent(s0, evYm[l], 0);
        seg_mean_dual<<<ceil_div(NTX * 32, 256), 256, 0, s0>>>(ws->yu, ws->ym, ws->gts);
        {
            GemmArgs a = {};
            a.A[0] = xt; a.W[0] = Wr0;
            a.A[1] = xt; a.W[1] = Wr2;
            a.b0 = bl0; a.b1 = bl2;
            a.E0 = ws->gts;
            a.C = xtn; a.M = NTX; a.N = HDIM; a.nseg = 2; a.segK = HDIM;
            a.outscale = 0.5f; a.relu = 1;
            gemm_tf32<<<dim3(ceil_div(NTX, BM), HDIM / BN), 256, 0, s0>>>(a);
        }

        // join
        cudaStreamWaitEvent(s0, evB[l], 0);
        cudaStreamWaitEvent(s0, evC[l], 0);
        cur ^= 1;
    }

    // ---- heads: h1c (s0) || h1v (sB) ----
    float* xtf = ws->xt[cur];
    cudaEventRecord(evForkH, s0);
    cudaStreamWaitEvent(sB, evForkH, 0);
    {
        GemmArgs a = {};
        a.A[0] = xtf; a.W[0] = Wv1; a.b0 = bv1;
        a.C = ws->h1v; a.M = NTX; a.N = HHALF; a.nseg = 1; a.segK = HDIM;
        a.outscale = 1.0f; a.relu = 1;
        gemm_tf32<<<dim3(ceil_div(NTX, BM), HHALF / BN), 256, 0, sB>>>(a);
    }
    cudaEventRecord(evHv, sB);
    {
        GemmArgs a = {};
        a.A[0] = xtf; a.W[0] = Wc1; a.b0 = bc1;
        a.C = ws->h1c; a.M = NTX; a.N = HHALF; a.nseg = 1; a.segK = HDIM;
        a.outscale = 1.0f; a.relu = 1;
        gemm_tf32<<<dim3(ceil_div(NTX, BM), HHALF / BN), 256, 0, s0>>>(a);
    }
    cudaStreamWaitEvent(s0, evHv, 0);
    head_out<<<ceil_div(NTX * 32, 256), 256, 0, s0>>>(ws->h1c, ws->h1v, Wc2, bc2, Wv2, bv2, out);
}

// round 6
// speedup vs baseline: 2.7063x; 1.2198x over previous
#include <cuda_runtime.h>
#include <cstdint>

#define NTX    100000
#define NUSER  20000
#define NMERCH 5000
#define NEDGE  400000
#define HDIM   256
#define HHALF  128
#define FIN    32
#define NLAYER 2

// ---------------------------------------------------------------------------
// Workspace (single __device__ global; no allocations allowed)
// ---------------------------------------------------------------------------
struct WS {
    float xt[2][NTX * HDIM];
    float xu[2][NUSER * HDIM];
    float xm[2][NMERCH * HDIM];
    float gts[NTX * HDIM];       // mean(xu@Wl0)->tx + mean(xm@Wl2)->tx (summed)
    float mm [NMERCH * HDIM];    // seg-mean of xt into merch
    float mu [NUSER * HDIM];     // seg-mean of xt into user
    float yu [NUSER * HDIM];     // xu @ Wl0
    float ym [NMERCH * HDIM];    // xm @ Wl2
    float h1 [NTX * HDIM];       // [h1c | h1v] concatenated
    float wsum[NLAYER][HDIM * HDIM];  // Wr0 + Wr2 per layer
    float wcat[HDIM * HDIM];          // [Wc1 | Wv1]
    float bcat[HDIM];                 // [bc1 | bv1]
    int deg   [4][NTX];
    int cursor[4][NTX];
    int rowptr[4][NTX + 1];
    int perm  [4][NEDGE];
};
__device__ WS g_ws;

// relations: 0 = user->tx, 1 = tx->merch, 2 = merch->tx, 3 = tx->user
// ---------------------------------------------------------------------------
// CSR build
// ---------------------------------------------------------------------------
__global__ void build_count(const int* __restrict__ d0, const int* __restrict__ d1,
                            const int* __restrict__ d2, const int* __restrict__ d3) {
    int i = blockIdx.x * blockDim.x + threadIdx.x;
    if (i >= NEDGE) return;
    int rel = blockIdx.y;
    const int* d = (rel == 0) ? d0 : (rel == 1) ? d1 : (rel == 2) ? d2 : d3;
    atomicAdd(&g_ws.deg[rel][d[i]], 1);
}

__global__ void scan4(int n0, int n1, int n2, int n3) {
    int rel = blockIdx.x;
    int n = (rel == 0) ? n0 : (rel == 1) ? n1 : (rel == 2) ? n2 : n3;
    const int* deg = g_ws.deg[rel];
    int* rp = g_ws.rowptr[rel];
    __shared__ int wsum[32];
    __shared__ int s_carry;
    int tid = threadIdx.x, lane = tid & 31, wid = tid >> 5;
    if (tid == 0) s_carry = 0;
    __syncthreads();
    for (int base = 0; base < n; base += 1024) {
        int i = base + tid;
        int v = (i < n) ? deg[i] : 0;
        int x = v;
        #pragma unroll
        for (int off = 1; off < 32; off <<= 1) {
            int u = __shfl_up_sync(0xffffffffu, x, off);
            if (lane >= off) x += u;
        }
        if (lane == 31) wsum[wid] = x;
        __syncthreads();
        if (wid == 0) {
            int w = wsum[lane];
            int y = w;
            #pragma unroll
            for (int off = 1; off < 32; off <<= 1) {
                int u = __shfl_up_sync(0xffffffffu, y, off);
                if (lane >= off) y += u;
            }
            wsum[lane] = y - w;
        }
        __syncthreads();
        int incl = x + wsum[wid];
        int c = s_carry;
        __syncthreads();
        if (i < n) rp[i] = c + incl - v;
        if (tid == 1023) s_carry = c + incl;
        __syncthreads();
    }
    if (tid == 0) rp[n] = s_carry;
}

__global__ void build_fill(const int* __restrict__ s0, const int* __restrict__ d0,
                           const int* __restrict__ s1, const int* __restrict__ d1,
                           const int* __restrict__ s2, const int* __restrict__ d2,
                           const int* __restrict__ s3, const int* __restrict__ d3) {
    int i = blockIdx.x * blockDim.x + threadIdx.x;
    if (i >= NEDGE) return;
    int rel = blockIdx.y;
    const int* s = (rel == 0) ? s0 : (rel == 1) ? s1 : (rel == 2) ? s2 : s3;
    const int* d = (rel == 0) ? d0 : (rel == 1) ? d1 : (rel == 2) ? d2 : d3;
    int dst = d[i];
    int pos = g_ws.rowptr[rel][dst] + atomicAdd(&g_ws.cursor[rel][dst], 1);
    g_ws.perm[rel][pos] = s[i];
}

// ---------------------------------------------------------------------------
// Prep kernels: weight-sum and head-concat
// ---------------------------------------------------------------------------
__global__ void prep_wsum(const float* __restrict__ Wr) {
    int i = blockIdx.x * blockDim.x + threadIdx.x;
    if (i >= HDIM * HDIM) return;
    int l = blockIdx.y;
    const float* Wr0 = Wr + ((size_t)(l * 4 + 0)) * HDIM * HDIM;
    const float* Wr2 = Wr + ((size_t)(l * 4 + 2)) * HDIM * HDIM;
    g_ws.wsum[l][i] = Wr0[i] + Wr2[i];
}

__global__ void prep_wcat(const float* __restrict__ Wc1, const float* __restrict__ Wv1,
                          const float* __restrict__ bc1, const float* __restrict__ bv1) {
    int i = blockIdx.x * blockDim.x + threadIdx.x;
    if (i < HDIM * HDIM) {
        int k = i >> 8;          // row (0..255)
        int j = i & 255;         // col (0..255)
        float v = (j < HHALF) ? Wc1[k * HHALF + j] : Wv1[k * HHALF + (j - HHALF)];
        g_ws.wcat[i] = v;
    }
    if (i < HDIM) {
        g_ws.bcat[i] = (i < HHALF) ? bc1[i] : bv1[i - HHALF];
    }
}

// ---------------------------------------------------------------------------
// Segment-mean: warp per destination row, register accumulation
// ---------------------------------------------------------------------------
__global__ void seg_mean(const float* __restrict__ xsrc, int rel,
                         float* __restrict__ outm, int n_dst) {
    int w = (blockIdx.x * blockDim.x + threadIdx.x) >> 5;
    int lane = threadIdx.x & 31;
    if (w >= n_dst) return;
    const int* __restrict__ rp = g_ws.rowptr[rel];
    const int* __restrict__ pm = g_ws.perm[rel];
    int beg = rp[w], end = rp[w + 1];
    float4 a0 = make_float4(0.f, 0.f, 0.f, 0.f);
    float4 a1 = make_float4(0.f, 0.f, 0.f, 0.f);
    for (int e = beg; e < end; e++) {
        int s = pm[e];
        const float4* p = (const float4*)(xsrc + (size_t)s * HDIM);
        float4 v0 = p[lane];
        float4 v1 = p[lane + 32];
        a0.x += v0.x; a0.y += v0.y; a0.z += v0.z; a0.w += v0.w;
        a1.x += v1.x; a1.y += v1.y; a1.z += v1.z; a1.w += v1.w;
    }
    float inv = 1.0f / (float)max(end - beg, 1);
    a0.x *= inv; a0.y *= inv; a0.z *= inv; a0.w *= inv;
    a1.x *= inv; a1.y *= inv; a1.z *= inv; a1.w *= inv;
    float4* o = (float4*)(outm + (size_t)w * HDIM);
    o[lane] = a0;
    o[lane + 32] = a1;
}

// Dual segment-mean into tx: out = mean_rel0(ya) + mean_rel2(yb)
__global__ void seg_mean_dual(const float* __restrict__ ya, const float* __restrict__ yb,
                              float* __restrict__ outm) {
    int w = (blockIdx.x * blockDim.x + threadIdx.x) >> 5;
    int lane = threadIdx.x & 31;
    if (w >= NTX) return;

    float4 r0 = make_float4(0.f, 0.f, 0.f, 0.f);
    float4 r1 = make_float4(0.f, 0.f, 0.f, 0.f);

    {
        const int* __restrict__ rp = g_ws.rowptr[0];
        const int* __restrict__ pm = g_ws.perm[0];
        int beg = rp[w], end = rp[w + 1];
        float4 a0 = make_float4(0.f, 0.f, 0.f, 0.f);
        float4 a1 = make_float4(0.f, 0.f, 0.f, 0.f);
        for (int e = beg; e < end; e++) {
            int s = pm[e];
            const float4* p = (const float4*)(ya + (size_t)s * HDIM);
            float4 v0 = p[lane];
            float4 v1 = p[lane + 32];
            a0.x += v0.x; a0.y += v0.y; a0.z += v0.z; a0.w += v0.w;
            a1.x += v1.x; a1.y += v1.y; a1.z += v1.z; a1.w += v1.w;
        }
        float inv = 1.0f / (float)max(end - beg, 1);
        r0.x += a0.x * inv; r0.y += a0.y * inv; r0.z += a0.z * inv; r0.w += a0.w * inv;
        r1.x += a1.x * inv; r1.y += a1.y * inv; r1.z += a1.z * inv; r1.w += a1.w * inv;
    }
    {
        const int* __restrict__ rp = g_ws.rowptr[2];
        const int* __restrict__ pm = g_ws.perm[2];
        int beg = rp[w], end = rp[w + 1];
        float4 a0 = make_float4(0.f, 0.f, 0.f, 0.f);
        float4 a1 = make_float4(0.f, 0.f, 0.f, 0.f);
        for (int e = beg; e < end; e++) {
            int s = pm[e];
            const float4* p = (const float4*)(yb + (size_t)s * HDIM);
            float4 v0 = p[lane];
            float4 v1 = p[lane + 32];
            a0.x += v0.x; a0.y += v0.y; a0.z += v0.z; a0.w += v0.w;
            a1.x += v1.x; a1.y += v1.y; a1.z += v1.z; a1.w += v1.w;
        }
        float inv = 1.0f / (float)max(end - beg, 1);
        r0.x += a0.x * inv; r0.y += a0.y * inv; r0.z += a0.z * inv; r0.w += a0.w * inv;
        r1.x += a1.x * inv; r1.y += a1.y * inv; r1.z += a1.z * inv; r1.w += a1.w * inv;
    }

    float4* o = (float4*)(outm + (size_t)w * HDIM);
    o[lane] = r0;
    o[lane + 32] = r1;
}

// ---------------------------------------------------------------------------
// Fused multi-segment GEMM on tf32 tensor cores (mma.sync.m16n8k8)
// ---------------------------------------------------------------------------
#define BM 128
#define BN 128
#define BK 32
#define SPAD 4

struct GemmArgs {
    const float* A[4];
    const float* W[4];
    const float* b0;
    const float* b1;
    const float* E0;
    const float* E1;
    float* C;
    int M, N, nseg, segK;
    float outscale;
    int relu;
};

__device__ __forceinline__ uint32_t f2tf32(float f) {
    uint32_t u;
    asm("cvt.rna.tf32.f32 %0, %1;" : "=r"(u) : "f"(f));
    return u;
}

__global__ void __launch_bounds__(256, 2) gemm_tf32(GemmArgs g) {
    __shared__ uint32_t As[BK][BM + SPAD];
    __shared__ uint32_t Ws[BK][BN + SPAD];

    int tid = threadIdx.x;
    int lane = tid & 31;
    int warp = tid >> 5;
    int wm = (warp & 3) * 32;
    int wn = (warp >> 2) * 64;
    int grp = lane >> 2;
    int tg  = lane & 3;

    int m0 = blockIdx.x * BM, n0 = blockIdx.y * BN;

    float acc[2][8][4];
    #pragma unroll
    for (int i = 0; i < 2; i++)
        #pragma unroll
        for (int j = 0; j < 8; j++)
            #pragma unroll
            for (int c = 0; c < 4; c++) acc[i][j][c] = 0.f;

    int arow = tid & 127;
    int ahalf = (tid >> 7) * 16;
    int wk = tid >> 3;
    int wnc = (tid & 7) * 16;

    int ktiles = g.nseg * g.segK / BK;

    for (int kt = 0; kt < ktiles; kt++) {
        int k0 = kt * BK;
        int seg = k0 / g.segK;
        int koff = k0 - seg * g.segK;
        const float* __restrict__ A = g.A[seg];
        const float* __restrict__ W = g.W[seg];

        {
            int grow = m0 + arow;
            if (grow < g.M) {
                const float* p = A + (size_t)grow * g.segK + koff + ahalf;
                float4 v0 = *(const float4*)(p + 0);
                float4 v1 = *(const float4*)(p + 4);
                float4 v2 = *(const float4*)(p + 8);
                float4 v3 = *(const float4*)(p + 12);
                As[ahalf + 0][arow]  = f2tf32(v0.x);
                As[ahalf + 1][arow]  = f2tf32(v0.y);
                As[ahalf + 2][arow]  = f2tf32(v0.z);
                As[ahalf + 3][arow]  = f2tf32(v0.w);
                As[ahalf + 4][arow]  = f2tf32(v1.x);
                As[ahalf + 5][arow]  = f2tf32(v1.y);
                As[ahalf + 6][arow]  = f2tf32(v1.z);
                As[ahalf + 7][arow]  = f2tf32(v1.w);
                As[ahalf + 8][arow]  = f2tf32(v2.x);
                As[ahalf + 9][arow]  = f2tf32(v2.y);
                As[ahalf + 10][arow] = f2tf32(v2.z);
                As[ahalf + 11][arow] = f2tf32(v2.w);
                As[ahalf + 12][arow] = f2tf32(v3.x);
                As[ahalf + 13][arow] = f2tf32(v3.y);
                As[ahalf + 14][arow] = f2tf32(v3.z);
                As[ahalf + 15][arow] = f2tf32(v3.w);
            } else {
                #pragma unroll
                for (int j = 0; j < 16; j++) As[ahalf + j][arow] = 0u;
            }
        }
        {
            const float* q = W + (size_t)(koff + wk) * g.N + n0 + wnc;
            float4 v0 = *(const float4*)(q + 0);
            float4 v1 = *(const float4*)(q + 4);
            float4 v2 = *(const float4*)(q + 8);
            float4 v3 = *(const float4*)(q + 12);
            Ws[wk][wnc + 0]  = f2tf32(v0.x);
            Ws[wk][wnc + 1]  = f2tf32(v0.y);
            Ws[wk][wnc + 2]  = f2tf32(v0.z);
            Ws[wk][wnc + 3]  = f2tf32(v0.w);
            Ws[wk][wnc + 4]  = f2tf32(v1.x);
            Ws[wk][wnc + 5]  = f2tf32(v1.y);
            Ws[wk][wnc + 6]  = f2tf32(v1.z);
            Ws[wk][wnc + 7]  = f2tf32(v1.w);
            Ws[wk][wnc + 8]  = f2tf32(v2.x);
            Ws[wk][wnc + 9]  = f2tf32(v2.y);
            Ws[wk][wnc + 10] = f2tf32(v2.z);
            Ws[wk][wnc + 11] = f2tf32(v2.w);
            Ws[wk][wnc + 12] = f2tf32(v3.x);
            Ws[wk][wnc + 13] = f2tf32(v3.y);
            Ws[wk][wnc + 14] = f2tf32(v3.z);
            Ws[wk][wnc + 15] = f2tf32(v3.w);
        }
        __syncthreads();

        #pragma unroll
        for (int ks = 0; ks < BK / 8; ks++) {
            int k8 = ks * 8;
            uint32_t afr[2][4];
            #pragma unroll
            for (int mi = 0; mi < 2; mi++) {
                int mb = wm + mi * 16;
                afr[mi][0] = As[k8 + tg][mb + grp];
                afr[mi][1] = As[k8 + tg][mb + grp + 8];
                afr[mi][2] = As[k8 + tg + 4][mb + grp];
                afr[mi][3] = As[k8 + tg + 4][mb + grp + 8];
            }
            uint32_t bfr[8][2];
            #pragma unroll
            for (int nt = 0; nt < 8; nt++) {
                int nb = wn + nt * 8 + grp;
                bfr[nt][0] = Ws[k8 + tg][nb];
                bfr[nt][1] = Ws[k8 + tg + 4][nb];
            }
            #pragma unroll
            for (int mi = 0; mi < 2; mi++) {
                #pragma unroll
                for (int nt = 0; nt < 8; nt++) {
                    asm volatile(
                        "mma.sync.aligned.m16n8k8.row.col.f32.tf32.tf32.f32 "
                        "{%0,%1,%2,%3}, {%4,%5,%6,%7}, {%8,%9}, {%0,%1,%2,%3};"
                        : "+f"(acc[mi][nt][0]), "+f"(acc[mi][nt][1]),
                          "+f"(acc[mi][nt][2]), "+f"(acc[mi][nt][3])
                        : "r"(afr[mi][0]), "r"(afr[mi][1]),
                          "r"(afr[mi][2]), "r"(afr[mi][3]),
                          "r"(bfr[nt][0]), "r"(bfr[nt][1]));
                }
            }
        }
        __syncthreads();
    }

    float bias[8][2];
    #pragma unroll
    for (int nt = 0; nt < 8; nt++) {
        int c = n0 + wn + nt * 8 + tg * 2;
        float b0v = 0.f, b1v = 0.f;
        if (g.b0) { b0v = g.b0[c] + (g.b1 ? g.b1[c] : 0.f); }
        if (g.b0) { b1v = g.b0[c + 1] + (g.b1 ? g.b1[c + 1] : 0.f); }
        bias[nt][0] = b0v;
        bias[nt][1] = b1v;
    }

    #pragma unroll
    for (int mi = 0; mi < 2; mi++) {
        int r0 = m0 + wm + mi * 16 + grp;
        int r1 = r0 + 8;
        #pragma unroll
        for (int nt = 0; nt < 8; nt++) {
            int c = n0 + wn + nt * 8 + tg * 2;
            if (r0 < g.M) {
                float e0 = 0.f, e1 = 0.f;
                if (g.E0) {
                    float2 t = *(const float2*)(g.E0 + (size_t)r0 * g.N + c);
                    e0 += t.x; e1 += t.y;
                }
                if (g.E1) {
                    float2 t = *(const float2*)(g.E1 + (size_t)r0 * g.N + c);
                    e0 += t.x; e1 += t.y;
                }
                float v0 = (acc[mi][nt][0] + bias[nt][0] + e0) * g.outscale;
                float v1 = (acc[mi][nt][1] + bias[nt][1] + e1) * g.outscale;
                if (g.relu) { v0 = fmaxf(v0, 0.f); v1 = fmaxf(v1, 0.f); }
                *(float2*)(g.C + (size_t)r0 * g.N + c) = make_float2(v0, v1);
            }
            if (r1 < g.M) {
                float e0 = 0.f, e1 = 0.f;
                if (g.E0) {
                    float2 t = *(const float2*)(g.E0 + (size_t)r1 * g.N + c);
                    e0 += t.x; e1 += t.y;
                }
                if (g.E1) {
                    float2 t = *(const float2*)(g.E1 + (size_t)r1 * g.N + c);
                    e0 += t.x; e1 += t.y;
                }
                float v0 = (acc[mi][nt][2] + bias[nt][0] + e0) * g.outscale;
                float v1 = (acc[mi][nt][3] + bias[nt][1] + e1) * g.outscale;
                if (g.relu) { v0 = fmaxf(v0, 0.f); v1 = fmaxf(v1, 0.f); }
                *(float2*)(g.C + (size_t)r1 * g.N + c) = make_float2(v0, v1);
            }
        }
    }
}

// ---------------------------------------------------------------------------
// Head matvec from concatenated h1 = [h1c | h1v]
// ---------------------------------------------------------------------------
__global__ void head_out(const float* __restrict__ h1,
                         const float* __restrict__ Wc2, const float* __restrict__ bc2,
                         const float* __restrict__ Wv2, const float* __restrict__ bv2,
                         float* __restrict__ out) {
    int row = blockIdx.x * (blockDim.x >> 5) + (threadIdx.x >> 5);
    int lane = threadIdx.x & 31;
    if (row >= NTX) return;

    const float4* hrow = (const float4*)(h1 + (size_t)row * HDIM);
    float4 wc = ((const float4*)Wc2)[lane];
    float4 hc = hrow[lane];
    float sc = hc.x * wc.x + hc.y * wc.y + hc.z * wc.z + hc.w * wc.w;

    float4 wv = ((const float4*)Wv2)[lane];
    float4 hv = hrow[lane + 32];
    float sv = hv.x * wv.x + hv.y * wv.y + hv.z * wv.z + hv.w * wv.w;

    #pragma unroll
    for (int off = 16; off > 0; off >>= 1) {
        sc += __shfl_xor_sync(0xffffffffu, sc, off);
        sv += __shfl_xor_sync(0xffffffffu, sv, off);
    }
    if (lane == 0) {
        out[row]       = sc + bc2[0];
        out[NTX + row] = sv + bv2[0];
    }
}

// ---------------------------------------------------------------------------
// Host orchestration with fork/join stream concurrency (graph-capturable)
// ---------------------------------------------------------------------------
static inline int ceil_div(int a, int b) { return (a + b - 1) / b; }

extern "C" void kernel_launch(void* const* d_in, const int* in_sizes, int n_in,
                              void* d_out, int out_size) {
    const float* x_tx   = (const float*)d_in[0];
    const float* x_user = (const float*)d_in[1];
    const float* x_merch= (const float*)d_in[2];
    const float* Wp     = (const float*)d_in[3];
    const float* bp     = (const float*)d_in[4];
    const float* Wl     = (const float*)d_in[5];
    const float* bl     = (const float*)d_in[6];
    const float* Wr     = (const float*)d_in[7];
    const float* Wc1    = (const float*)d_in[8];
    const float* bc1    = (const float*)d_in[9];
    const float* Wc2    = (const float*)d_in[10];
    const float* bc2    = (const float*)d_in[11];
    const float* Wv1    = (const float*)d_in[12];
    const float* bv1    = (const float*)d_in[13];
    const float* Wv2    = (const float*)d_in[14];
    const float* bv2    = (const float*)d_in[15];
    const int* e_ut_src = (const int*)d_in[16];
    const int* e_ut_dst = (const int*)d_in[17];
    const int* e_tm_src = (const int*)d_in[18];
    const int* e_tm_dst = (const int*)d_in[19];
    const int* e_mt_src = (const int*)d_in[20];
    const int* e_mt_dst = (const int*)d_in[21];
    const int* e_tu_src = (const int*)d_in[22];
    const int* e_tu_dst = (const int*)d_in[23];
    float* out = (float*)d_out;

    WS* ws = nullptr;
    cudaGetSymbolAddress((void**)&ws, g_ws);

    // side streams + events, created once (host resources only)
    static cudaStream_t sB = nullptr, sC = nullptr;
    static cudaEvent_t ev[16];
    if (!sB) {
        cudaStreamCreateWithFlags(&sB, cudaStreamNonBlocking);
        cudaStreamCreateWithFlags(&sC, cudaStreamNonBlocking);
        for (int i = 0; i < 16; i++)
            cudaEventCreateWithFlags(&ev[i], cudaEventDisableTiming);
    }
    cudaStream_t s0 = 0;
    cudaEvent_t evFork0 = ev[0], evCsr = ev[1], evPrep = ev[2];
    cudaEvent_t evForkL[2] = {ev[3], ev[4]};
    cudaEvent_t evYm[2]    = {ev[5], ev[6]};
    cudaEvent_t evB[2]     = {ev[7], ev[8]};
    cudaEvent_t evC[2]     = {ev[9], ev[10]};

    // ---- prologue fork: proj GEMM (s0) || CSR build (sB) || memcpys+prep (sC) ----
    cudaEventRecord(evFork0, s0);
    cudaStreamWaitEvent(sB, evFork0, 0);
    cudaStreamWaitEvent(sC, evFork0, 0);

    {   // s0: xt[0] = x_tx @ Wp + bp
        GemmArgs a = {};
        a.A[0] = x_tx; a.W[0] = Wp; a.b0 = bp;
        a.C = ws->xt[0]; a.M = NTX; a.N = HDIM; a.nseg = 1; a.segK = FIN;
        a.outscale = 1.0f; a.relu = 0;
        gemm_tf32<<<dim3(ceil_div(NTX, BM), HDIM / BN), 256, 0, s0>>>(a);
    }
    // sB: CSR build
    cudaMemsetAsync(ws->deg,    0, sizeof(ws->deg),    sB);
    cudaMemsetAsync(ws->cursor, 0, sizeof(ws->cursor), sB);
    build_count<<<dim3(ceil_div(NEDGE, 256), 4), 256, 0, sB>>>(e_ut_dst, e_tm_dst, e_mt_dst, e_tu_dst);
    scan4<<<4, 1024, 0, sB>>>(NTX, NMERCH, NTX, NUSER);
    build_fill<<<dim3(ceil_div(NEDGE, 256), 4), 256, 0, sB>>>(e_ut_src, e_ut_dst, e_tm_src, e_tm_dst,
                                                              e_mt_src, e_mt_dst, e_tu_src, e_tu_dst);
    cudaEventRecord(evCsr, sB);
    // sC: copy user/merch features + weight prep
    cudaMemcpyAsync(ws->xu[0], x_user,  (size_t)NUSER  * HDIM * sizeof(float), cudaMemcpyDeviceToDevice, sC);
    cudaMemcpyAsync(ws->xm[0], x_merch, (size_t)NMERCH * HDIM * sizeof(float), cudaMemcpyDeviceToDevice, sC);
    prep_wsum<<<dim3(ceil_div(HDIM * HDIM, 256), NLAYER), 256, 0, sC>>>(Wr);
    prep_wcat<<<ceil_div(HDIM * HDIM, 256), 256, 0, sC>>>(Wc1, Wv1, bc1, bv1);
    cudaEventRecord(evPrep, sC);

    cudaStreamWaitEvent(s0, evCsr, 0);
    cudaStreamWaitEvent(s0, evPrep, 0);

    int cur = 0;
    for (int l = 0; l < NLAYER; l++) {
        float* xt  = ws->xt[cur];
        float* xu  = ws->xu[cur];
        float* xm  = ws->xm[cur];
        float* xtn = ws->xt[1 - cur];
        float* xun = ws->xu[1 - cur];
        float* xmn = ws->xm[1 - cur];

        const float* Wl0 = Wl + ((size_t)(l * 4 + 0)) * HDIM * HDIM;
        const float* Wl1 = Wl + ((size_t)(l * 4 + 1)) * HDIM * HDIM;
        const float* Wl2 = Wl + ((size_t)(l * 4 + 2)) * HDIM * HDIM;
        const float* Wl3 = Wl + ((size_t)(l * 4 + 3)) * HDIM * HDIM;
        const float* Wr1 = Wr + ((size_t)(l * 4 + 1)) * HDIM * HDIM;
        const float* Wr3 = Wr + ((size_t)(l * 4 + 3)) * HDIM * HDIM;
        const float* bl0 = bl + (size_t)(l * 4 + 0) * HDIM;
        const float* bl1 = bl + (size_t)(l * 4 + 1) * HDIM;
        const float* bl2 = bl + (size_t)(l * 4 + 2) * HDIM;
        const float* bl3 = bl + (size_t)(l * 4 + 3) * HDIM;

        // fork
        cudaEventRecord(evForkL[l], s0);
        cudaStreamWaitEvent(sB, evForkL[l], 0);
        cudaStreamWaitEvent(sC, evForkL[l], 0);

        // --- sB: ym = xm@Wl2 ; then seg_mean(xt->mm) ; xm_new GEMM ---
        {
            GemmArgs a = {};
            a.A[0] = xm; a.W[0] = Wl2;
            a.C = ws->ym; a.M = NMERCH; a.N = HDIM; a.nseg = 1; a.segK = HDIM;
            a.outscale = 1.0f; a.relu = 0;
            gemm_tf32<<<dim3(ceil_div(NMERCH, BM), HDIM / BN), 256, 0, sB>>>(a);
        }
        cudaEventRecord(evYm[l], sB);
        seg_mean<<<ceil_div(NMERCH * 32, 256), 256, 0, sB>>>(xt, 1, ws->mm, NMERCH);
        {
            GemmArgs a = {};
            a.A[0] = ws->mm; a.W[0] = Wl1;
            a.A[1] = xm;     a.W[1] = Wr1;
            a.b0 = bl1;
            a.C = xmn; a.M = NMERCH; a.N = HDIM; a.nseg = 2; a.segK = HDIM;
            a.outscale = 1.0f; a.relu = 1;
            gemm_tf32<<<dim3(ceil_div(NMERCH, BM), HDIM / BN), 256, 0, sB>>>(a);
        }
        cudaEventRecord(evB[l], sB);

        // --- sC: seg_mean(xt->mu) ; xu_new GEMM ---
        seg_mean<<<ceil_div(NUSER * 32, 256), 256, 0, sC>>>(xt, 3, ws->mu, NUSER);
        {
            GemmArgs a = {};
            a.A[0] = ws->mu; a.W[0] = Wl3;
            a.A[1] = xu;     a.W[1] = Wr3;
            a.b0 = bl3;
            a.C = xun; a.M = NUSER; a.N = HDIM; a.nseg = 2; a.segK = HDIM;
            a.outscale = 1.0f; a.relu = 1;
            gemm_tf32<<<dim3(ceil_div(NUSER, BM), HDIM / BN), 256, 0, sC>>>(a);
        }
        cudaEventRecord(evC[l], sC);

        // --- s0: yu = xu@Wl0 ; wait ym ; dual seg-mean ; big xt GEMM (K=256) ---
        {
            GemmArgs a = {};
            a.A[0] = xu; a.W[0] = Wl0;
            a.C = ws->yu; a.M = NUSER; a.N = HDIM; a.nseg = 1; a.segK = HDIM;
            a.outscale = 1.0f; a.relu = 0;
            gemm_tf32<<<dim3(ceil_div(NUSER, BM), HDIM / BN), 256, 0, s0>>>(a);
        }
        cudaStreamWaitEvent(s0, evYm[l], 0);
        seg_mean_dual<<<ceil_div(NTX * 32, 256), 256, 0, s0>>>(ws->yu, ws->ym, ws->gts);
        {
            GemmArgs a = {};
            a.A[0] = xt; a.W[0] = ws->wsum[l];   // Wr0 + Wr2, precomputed
            a.b0 = bl0; a.b1 = bl2;
            a.E0 = ws->gts;
            a.C = xtn; a.M = NTX; a.N = HDIM; a.nseg = 1; a.segK = HDIM;
            a.outscale = 0.5f; a.relu = 1;
            gemm_tf32<<<dim3(ceil_div(NTX, BM), HDIM / BN), 256, 0, s0>>>(a);
        }

        // join
        cudaStreamWaitEvent(s0, evB[l], 0);
        cudaStreamWaitEvent(s0, evC[l], 0);
        cur ^= 1;
    }

    // ---- heads: single concatenated GEMM, then matvec ----
    float* xtf = ws->xt[cur];
    {
        GemmArgs a = {};
        a.A[0] = xtf; a.W[0] = ws->wcat; a.b0 = ws->bcat;
        a.C = ws->h1; a.M = NTX; a.N = HDIM; a.nseg = 1; a.segK = HDIM;
        a.outscale = 1.0f; a.relu = 1;
        gemm_tf32<<<dim3(ceil_div(NTX, BM), HDIM / BN), 256, 0, s0>>>(a);
    }
    head_out<<<ceil_div(NTX * 32, 256), 256, 0, s0>>>(ws->h1, Wc2, bc2, Wv2, bv2, out);
}

// round 7
// speedup vs baseline: 3.4053x; 1.2583x over previous
#include <cuda_runtime.h>
#include <cstdint>

#define NTX    100000
#define NUSER  20000
#define NMERCH 5000
#define NEDGE  400000
#define HDIM   256
#define HHALF  128
#define FIN    32
#define NLAYER 2

// ---------------------------------------------------------------------------
// Workspace (single __device__ global; no allocations allowed)
// ---------------------------------------------------------------------------
struct WS {
    float xt[2][NTX * HDIM];
    float xu[2][NUSER * HDIM];
    float xm[2][NMERCH * HDIM];
    float gts[NTX * HDIM];
    float mm [NMERCH * HDIM];
    float mu [NUSER * HDIM];
    float yu [NUSER * HDIM];
    float ym [NMERCH * HDIM];
    float h1 [NTX * HDIM];
    float wsum[NLAYER][HDIM * HDIM];
    float wcat[HDIM * HDIM];
    float bcat[HDIM];
    int deg   [4][NTX];
    int cursor[4][NTX];
    int rowptr[4][NTX + 1];
    int perm  [4][NEDGE];
};
__device__ WS g_ws;

// relations: 0 = user->tx, 1 = tx->merch, 2 = merch->tx, 3 = tx->user
// ---------------------------------------------------------------------------
// CSR build
// ---------------------------------------------------------------------------
__global__ void build_count(const int* __restrict__ d0, const int* __restrict__ d1,
                            const int* __restrict__ d2, const int* __restrict__ d3) {
    int i = blockIdx.x * blockDim.x + threadIdx.x;
    if (i >= NEDGE) return;
    int rel = blockIdx.y;
    const int* d = (rel == 0) ? d0 : (rel == 1) ? d1 : (rel == 2) ? d2 : d3;
    atomicAdd(&g_ws.deg[rel][d[i]], 1);
}

__global__ void scan4(int n0, int n1, int n2, int n3) {
    int rel = blockIdx.x;
    int n = (rel == 0) ? n0 : (rel == 1) ? n1 : (rel == 2) ? n2 : n3;
    const int* deg = g_ws.deg[rel];
    int* rp = g_ws.rowptr[rel];
    __shared__ int wsum[32];
    __shared__ int s_carry;
    int tid = threadIdx.x, lane = tid & 31, wid = tid >> 5;
    if (tid == 0) s_carry = 0;
    __syncthreads();
    for (int base = 0; base < n; base += 1024) {
        int i = base + tid;
        int v = (i < n) ? deg[i] : 0;
        int x = v;
        #pragma unroll
        for (int off = 1; off < 32; off <<= 1) {
            int u = __shfl_up_sync(0xffffffffu, x, off);
            if (lane >= off) x += u;
        }
        if (lane == 31) wsum[wid] = x;
        __syncthreads();
        if (wid == 0) {
            int w = wsum[lane];
            int y = w;
            #pragma unroll
            for (int off = 1; off < 32; off <<= 1) {
                int u = __shfl_up_sync(0xffffffffu, y, off);
                if (lane >= off) y += u;
            }
            wsum[lane] = y - w;
        }
        __syncthreads();
        int incl = x + wsum[wid];
        int c = s_carry;
        __syncthreads();
        if (i < n) rp[i] = c + incl - v;
        if (tid == 1023) s_carry = c + incl;
        __syncthreads();
    }
    if (tid == 0) rp[n] = s_carry;
}

__global__ void build_fill(const int* __restrict__ s0, const int* __restrict__ d0,
                           const int* __restrict__ s1, const int* __restrict__ d1,
                           const int* __restrict__ s2, const int* __restrict__ d2,
                           const int* __restrict__ s3, const int* __restrict__ d3) {
    int i = blockIdx.x * blockDim.x + threadIdx.x;
    if (i >= NEDGE) return;
    int rel = blockIdx.y;
    const int* s = (rel == 0) ? s0 : (rel == 1) ? s1 : (rel == 2) ? s2 : s3;
    const int* d = (rel == 0) ? d0 : (rel == 1) ? d1 : (rel == 2) ? d2 : d3;
    int dst = d[i];
    int pos = g_ws.rowptr[rel][dst] + atomicAdd(&g_ws.cursor[rel][dst], 1);
    g_ws.perm[rel][pos] = s[i];
}

// ---------------------------------------------------------------------------
// Prep kernels
// ---------------------------------------------------------------------------
__global__ void prep_wsum(const float* __restrict__ Wr) {
    int i = blockIdx.x * blockDim.x + threadIdx.x;
    if (i >= HDIM * HDIM) return;
    int l = blockIdx.y;
    const float* Wr0 = Wr + ((size_t)(l * 4 + 0)) * HDIM * HDIM;
    const float* Wr2 = Wr + ((size_t)(l * 4 + 2)) * HDIM * HDIM;
    g_ws.wsum[l][i] = Wr0[i] + Wr2[i];
}

__global__ void prep_wcat(const float* __restrict__ Wc1, const float* __restrict__ Wv1,
                          const float* __restrict__ bc1, const float* __restrict__ bv1) {
    int i = blockIdx.x * blockDim.x + threadIdx.x;
    if (i < HDIM * HDIM) {
        int k = i >> 8;
        int j = i & 255;
        float v = (j < HHALF) ? Wc1[k * HHALF + j] : Wv1[k * HHALF + (j - HHALF)];
        g_ws.wcat[i] = v;
    }
    if (i < HDIM) {
        g_ws.bcat[i] = (i < HHALF) ? bc1[i] : bv1[i - HHALF];
    }
}

// ---------------------------------------------------------------------------
// Segment-mean kernels
// ---------------------------------------------------------------------------
__global__ void seg_mean(const float* __restrict__ xsrc, int rel,
                         float* __restrict__ outm, int n_dst) {
    int w = (blockIdx.x * blockDim.x + threadIdx.x) >> 5;
    int lane = threadIdx.x & 31;
    if (w >= n_dst) return;
    const int* __restrict__ rp = g_ws.rowptr[rel];
    const int* __restrict__ pm = g_ws.perm[rel];
    int beg = rp[w], end = rp[w + 1];
    float4 a0 = make_float4(0.f, 0.f, 0.f, 0.f);
    float4 a1 = make_float4(0.f, 0.f, 0.f, 0.f);
    for (int e = beg; e < end; e++) {
        int s = pm[e];
        const float4* p = (const float4*)(xsrc + (size_t)s * HDIM);
        float4 v0 = p[lane];
        float4 v1 = p[lane + 32];
        a0.x += v0.x; a0.y += v0.y; a0.z += v0.z; a0.w += v0.w;
        a1.x += v1.x; a1.y += v1.y; a1.z += v1.z; a1.w += v1.w;
    }
    float inv = 1.0f / (float)max(end - beg, 1);
    a0.x *= inv; a0.y *= inv; a0.z *= inv; a0.w *= inv;
    a1.x *= inv; a1.y *= inv; a1.z *= inv; a1.w *= inv;
    float4* o = (float4*)(outm + (size_t)w * HDIM);
    o[lane] = a0;
    o[lane + 32] = a1;
}

__global__ void seg_mean_dual(const float* __restrict__ ya, const float* __restrict__ yb,
                              float* __restrict__ outm) {
    int w = (blockIdx.x * blockDim.x + threadIdx.x) >> 5;
    int lane = threadIdx.x & 31;
    if (w >= NTX) return;

    float4 r0 = make_float4(0.f, 0.f, 0.f, 0.f);
    float4 r1 = make_float4(0.f, 0.f, 0.f, 0.f);

    {
        const int* __restrict__ rp = g_ws.rowptr[0];
        const int* __restrict__ pm = g_ws.perm[0];
        int beg = rp[w], end = rp[w + 1];
        float4 a0 = make_float4(0.f, 0.f, 0.f, 0.f);
        float4 a1 = make_float4(0.f, 0.f, 0.f, 0.f);
        for (int e = beg; e < end; e++) {
            int s = pm[e];
            const float4* p = (const float4*)(ya + (size_t)s * HDIM);
            float4 v0 = p[lane];
            float4 v1 = p[lane + 32];
            a0.x += v0.x; a0.y += v0.y; a0.z += v0.z; a0.w += v0.w;
            a1.x += v1.x; a1.y += v1.y; a1.z += v1.z; a1.w += v1.w;
        }
        float inv = 1.0f / (float)max(end - beg, 1);
        r0.x += a0.x * inv; r0.y += a0.y * inv; r0.z += a0.z * inv; r0.w += a0.w * inv;
        r1.x += a1.x * inv; r1.y += a1.y * inv; r1.z += a1.z * inv; r1.w += a1.w * inv;
    }
    {
        const int* __restrict__ rp = g_ws.rowptr[2];
        const int* __restrict__ pm = g_ws.perm[2];
        int beg = rp[w], end = rp[w + 1];
        float4 a0 = make_float4(0.f, 0.f, 0.f, 0.f);
        float4 a1 = make_float4(0.f, 0.f, 0.f, 0.f);
        for (int e = beg; e < end; e++) {
            int s = pm[e];
            const float4* p = (const float4*)(yb + (size_t)s * HDIM);
            float4 v0 = p[lane];
            float4 v1 = p[lane + 32];
            a0.x += v0.x; a0.y += v0.y; a0.z += v0.z; a0.w += v0.w;
            a1.x += v1.x; a1.y += v1.y; a1.z += v1.z; a1.w += v1.w;
        }
        float inv = 1.0f / (float)max(end - beg, 1);
        r0.x += a0.x * inv; r0.y += a0.y * inv; r0.z += a0.z * inv; r0.w += a0.w * inv;
        r1.x += a1.x * inv; r1.y += a1.y * inv; r1.z += a1.z * inv; r1.w += a1.w * inv;
    }

    float4* o = (float4*)(outm + (size_t)w * HDIM);
    o[lane] = r0;
    o[lane + 32] = r1;
}

// ---------------------------------------------------------------------------
// Fused multi-segment GEMM on tf32 tensor cores, cp.async double-buffered.
// Block tile 128x128x32, 256 threads = 8 warps (4m x 2n), warp tile 32x64.
// A staged [m][k] stride 36, W staged [k][n] stride 136 (conflict-free reads).
// ---------------------------------------------------------------------------
#define BM 128
#define BN 128
#define BK 32
#define ASTRIDE 36
#define WSTRIDE 136
#define A_FLOATS (BM * ASTRIDE)              // 4608
#define W_FLOATS (BK * WSTRIDE)              // 4352
#define STAGE_FLOATS (A_FLOATS + W_FLOATS)   // 8960
#define GEMM_SMEM_BYTES (2 * STAGE_FLOATS * 4)  // 71680

struct GemmArgs {
    const float* A[4];
    const float* W[4];
    const float* b0;
    const float* b1;
    const float* E0;
    const float* E1;
    float* C;
    int M, N, nseg, segK;
    float outscale;
    int relu;
};

__device__ __forceinline__ uint32_t f2tf32(float f) {
    uint32_t u;
    asm("cvt.rna.tf32.f32 %0, %1;" : "=r"(u) : "f"(f));
    return u;
}

__device__ __forceinline__ void cp_async16(uint32_t smem_addr, const void* gptr, int src_bytes) {
    asm volatile("cp.async.cg.shared.global [%0], [%1], 16, %2;"
                 :: "r"(smem_addr), "l"(gptr), "r"(src_bytes));
}
__device__ __forceinline__ void cp_commit() {
    asm volatile("cp.async.commit_group;");
}
template <int N>
__device__ __forceinline__ void cp_wait() {
    asm volatile("cp.async.wait_group %0;" :: "n"(N));
}

__global__ void __launch_bounds__(256, 2) gemm_tf32(GemmArgs g) {
    extern __shared__ float smem[];

    int tid = threadIdx.x;
    int lane = tid & 31;
    int warp = tid >> 5;
    int wm = (warp & 3) * 32;
    int wn = (warp >> 2) * 64;
    int grp = lane >> 2;
    int tg  = lane & 3;

    int m0 = blockIdx.x * BM, n0 = blockIdx.y * BN;

    // loader mapping
    int a_row   = tid >> 1;            // 0..127
    int a_chunk = (tid & 1) * 4;       // 4 chunks of 16B each (BK=32 floats = 8 chunks/row)
    int w_row   = tid >> 3;            // 0..31
    int w_chunk = (tid & 7) * 4;       // 4 chunks of 16B each (BN=128 floats = 32 chunks/row)

    int a_grow = m0 + a_row;
    bool a_ok = (a_grow < g.M);

    uint32_t smem_base = (uint32_t)__cvta_generic_to_shared(smem);
    int ktiles = g.nseg * g.segK / BK;

    // issue loads for tile kt into stage st
    auto issue_tile = [&](int kt, int st) {
        int k0 = kt * BK;
        int seg = k0 / g.segK;
        int koff = k0 - seg * g.segK;
        const float* A = g.A[seg];
        const float* W = g.W[seg];

        uint32_t a_s = smem_base + (st * STAGE_FLOATS + a_row * ASTRIDE) * 4;
        const float* a_g = A + (size_t)a_grow * g.segK + koff;
        int a_sz = a_ok ? 16 : 0;
        #pragma unroll
        for (int c = 0; c < 4; c++)
            cp_async16(a_s + (a_chunk + c) * 16, a_g + (a_chunk + c) * 4, a_sz);

        uint32_t w_s = smem_base + (st * STAGE_FLOATS + A_FLOATS + w_row * WSTRIDE) * 4;
        const float* w_g = W + (size_t)(koff + w_row) * g.N + n0;
        #pragma unroll
        for (int c = 0; c < 4; c++)
            cp_async16(w_s + (w_chunk + c) * 16, w_g + (w_chunk + c) * 4, 16);

        cp_commit();
    };

    float acc[2][8][4];
    #pragma unroll
    for (int i = 0; i < 2; i++)
        #pragma unroll
        for (int j = 0; j < 8; j++)
            #pragma unroll
            for (int c = 0; c < 4; c++) acc[i][j][c] = 0.f;

    issue_tile(0, 0);

    for (int kt = 0; kt < ktiles; kt++) {
        int st = kt & 1;
        if (kt + 1 < ktiles) {
            issue_tile(kt + 1, (kt + 1) & 1);
            cp_wait<1>();
        } else {
            cp_wait<0>();
        }
        __syncthreads();

        const float* As = smem + st * STAGE_FLOATS;
        const float* Ws = smem + st * STAGE_FLOATS + A_FLOATS;

        #pragma unroll
        for (int ks = 0; ks < BK / 8; ks++) {
            int k8 = ks * 8;
            uint32_t afr[2][4];
            #pragma unroll
            for (int mi = 0; mi < 2; mi++) {
                int mb = wm + mi * 16;
                afr[mi][0] = f2tf32(As[(mb + grp) * ASTRIDE + k8 + tg]);
                afr[mi][1] = f2tf32(As[(mb + grp + 8) * ASTRIDE + k8 + tg]);
                afr[mi][2] = f2tf32(As[(mb + grp) * ASTRIDE + k8 + tg + 4]);
                afr[mi][3] = f2tf32(As[(mb + grp + 8) * ASTRIDE + k8 + tg + 4]);
            }
            uint32_t bfr[8][2];
            #pragma unroll
            for (int nt = 0; nt < 8; nt++) {
                int nb = wn + nt * 8 + grp;
                bfr[nt][0] = f2tf32(Ws[(k8 + tg) * WSTRIDE + nb]);
                bfr[nt][1] = f2tf32(Ws[(k8 + tg + 4) * WSTRIDE + nb]);
            }
            #pragma unroll
            for (int mi = 0; mi < 2; mi++) {
                #pragma unroll
                for (int nt = 0; nt < 8; nt++) {
                    asm volatile(
                        "mma.sync.aligned.m16n8k8.row.col.f32.tf32.tf32.f32 "
                        "{%0,%1,%2,%3}, {%4,%5,%6,%7}, {%8,%9}, {%0,%1,%2,%3};"
                        : "+f"(acc[mi][nt][0]), "+f"(acc[mi][nt][1]),
                          "+f"(acc[mi][nt][2]), "+f"(acc[mi][nt][3])
                        : "r"(afr[mi][0]), "r"(afr[mi][1]),
                          "r"(afr[mi][2]), "r"(afr[mi][3]),
                          "r"(bfr[nt][0]), "r"(bfr[nt][1]));
                }
            }
        }
        __syncthreads();
    }

    float bias[8][2];
    #pragma unroll
    for (int nt = 0; nt < 8; nt++) {
        int c = n0 + wn + nt * 8 + tg * 2;
        float b0v = 0.f, b1v = 0.f;
        if (g.b0) { b0v = g.b0[c] + (g.b1 ? g.b1[c] : 0.f); }
        if (g.b0) { b1v = g.b0[c + 1] + (g.b1 ? g.b1[c + 1] : 0.f); }
        bias[nt][0] = b0v;
        bias[nt][1] = b1v;
    }

    #pragma unroll
    for (int mi = 0; mi < 2; mi++) {
        int r0 = m0 + wm + mi * 16 + grp;
        int r1 = r0 + 8;
        #pragma unroll
        for (int nt = 0; nt < 8; nt++) {
            int c = n0 + wn + nt * 8 + tg * 2;
            if (r0 < g.M) {
                float e0 = 0.f, e1 = 0.f;
                if (g.E0) {
                    float2 t = *(const float2*)(g.E0 + (size_t)r0 * g.N + c);
                    e0 += t.x; e1 += t.y;
                }
                if (g.E1) {
                    float2 t = *(const float2*)(g.E1 + (size_t)r0 * g.N + c);
                    e0 += t.x; e1 += t.y;
                }
                float v0 = (acc[mi][nt][0] + bias[nt][0] + e0) * g.outscale;
                float v1 = (acc[mi][nt][1] + bias[nt][1] + e1) * g.outscale;
                if (g.relu) { v0 = fmaxf(v0, 0.f); v1 = fmaxf(v1, 0.f); }
                *(float2*)(g.C + (size_t)r0 * g.N + c) = make_float2(v0, v1);
            }
            if (r1 < g.M) {
                float e0 = 0.f, e1 = 0.f;
                if (g.E0) {
                    float2 t = *(const float2*)(g.E0 + (size_t)r1 * g.N + c);
                    e0 += t.x; e1 += t.y;
                }
                if (g.E1) {
                    float2 t = *(const float2*)(g.E1 + (size_t)r1 * g.N + c);
                    e0 += t.x; e1 += t.y;
                }
                float v0 = (acc[mi][nt][2] + bias[nt][0] + e0) * g.outscale;
                float v1 = (acc[mi][nt][3] + bias[nt][1] + e1) * g.outscale;
                if (g.relu) { v0 = fmaxf(v0, 0.f); v1 = fmaxf(v1, 0.f); }
                *(float2*)(g.C + (size_t)r1 * g.N + c) = make_float2(v0, v1);
            }
        }
    }
}

// ---------------------------------------------------------------------------
// Head matvec from concatenated h1 = [h1c | h1v]
// ---------------------------------------------------------------------------
__global__ void head_out(const float* __restrict__ h1,
                         const float* __restrict__ Wc2, const float* __restrict__ bc2,
                         const float* __restrict__ Wv2, const float* __restrict__ bv2,
                         float* __restrict__ out) {
    int row = blockIdx.x * (blockDim.x >> 5) + (threadIdx.x >> 5);
    int lane = threadIdx.x & 31;
    if (row >= NTX) return;

    const float4* hrow = (const float4*)(h1 + (size_t)row * HDIM);
    float4 wc = ((const float4*)Wc2)[lane];
    float4 hc = hrow[lane];
    float sc = hc.x * wc.x + hc.y * wc.y + hc.z * wc.z + hc.w * wc.w;

    float4 wv = ((const float4*)Wv2)[lane];
    float4 hv = hrow[lane + 32];
    float sv = hv.x * wv.x + hv.y * wv.y + hv.z * wv.z + hv.w * wv.w;

    #pragma unroll
    for (int off = 16; off > 0; off >>= 1) {
        sc += __shfl_xor_sync(0xffffffffu, sc, off);
        sv += __shfl_xor_sync(0xffffffffu, sv, off);
    }
    if (lane == 0) {
        out[row]       = sc + bc2[0];
        out[NTX + row] = sv + bv2[0];
    }
}

// ---------------------------------------------------------------------------
// Host orchestration with fork/join stream concurrency (graph-capturable)
// ---------------------------------------------------------------------------
static inline int ceil_div(int a, int b) { return (a + b - 1) / b; }

extern "C" void kernel_launch(void* const* d_in, const int* in_sizes, int n_in,
                              void* d_out, int out_size) {
    const float* x_tx   = (const float*)d_in[0];
    const float* x_user = (const float*)d_in[1];
    const float* x_merch= (const float*)d_in[2];
    const float* Wp     = (const float*)d_in[3];
    const float* bp     = (const float*)d_in[4];
    const float* Wl     = (const float*)d_in[5];
    const float* bl     = (const float*)d_in[6];
    const float* Wr     = (const float*)d_in[7];
    const float* Wc1    = (const float*)d_in[8];
    const float* bc1    = (const float*)d_in[9];
    const float* Wc2    = (const float*)d_in[10];
    const float* bc2    = (const float*)d_in[11];
    const float* Wv1    = (const float*)d_in[12];
    const float* bv1    = (const float*)d_in[13];
    const float* Wv2    = (const float*)d_in[14];
    const float* bv2    = (const float*)d_in[15];
    const int* e_ut_src = (const int*)d_in[16];
    const int* e_ut_dst = (const int*)d_in[17];
    const int* e_tm_src = (const int*)d_in[18];
    const int* e_tm_dst = (const int*)d_in[19];
    const int* e_mt_src = (const int*)d_in[20];
    const int* e_mt_dst = (const int*)d_in[21];
    const int* e_tu_src = (const int*)d_in[22];
    const int* e_tu_dst = (const int*)d_in[23];
    float* out = (float*)d_out;

    WS* ws = nullptr;
    cudaGetSymbolAddress((void**)&ws, g_ws);

    static cudaStream_t sB = nullptr, sC = nullptr;
    static cudaEvent_t ev[16];
    if (!sB) {
        cudaStreamCreateWithFlags(&sB, cudaStreamNonBlocking);
        cudaStreamCreateWithFlags(&sC, cudaStreamNonBlocking);
        for (int i = 0; i < 16; i++)
            cudaEventCreateWithFlags(&ev[i], cudaEventDisableTiming);
        cudaFuncSetAttribute(gemm_tf32, cudaFuncAttributeMaxDynamicSharedMemorySize,
                             GEMM_SMEM_BYTES);
    }
    cudaStream_t s0 = 0;
    cudaEvent_t evFork0 = ev[0], evCsr = ev[1], evPrep = ev[2];
    cudaEvent_t evForkL[2] = {ev[3], ev[4]};
    cudaEvent_t evYm[2]    = {ev[5], ev[6]};
    cudaEvent_t evB[2]     = {ev[7], ev[8]};
    cudaEvent_t evC[2]     = {ev[9], ev[10]};

    // ---- prologue fork ----
    cudaEventRecord(evFork0, s0);
    cudaStreamWaitEvent(sB, evFork0, 0);
    cudaStreamWaitEvent(sC, evFork0, 0);

    {   // s0: xt[0] = x_tx @ Wp + bp
        GemmArgs a = {};
        a.A[0] = x_tx; a.W[0] = Wp; a.b0 = bp;
        a.C = ws->xt[0]; a.M = NTX; a.N = HDIM; a.nseg = 1; a.segK = FIN;
        a.outscale = 1.0f; a.relu = 0;
        gemm_tf32<<<dim3(ceil_div(NTX, BM), HDIM / BN), 256, GEMM_SMEM_BYTES, s0>>>(a);
    }
    // sB: CSR build
    cudaMemsetAsync(ws->deg,    0, sizeof(ws->deg),    sB);
    cudaMemsetAsync(ws->cursor, 0, sizeof(ws->cursor), sB);
    build_count<<<dim3(ceil_div(NEDGE, 256), 4), 256, 0, sB>>>(e_ut_dst, e_tm_dst, e_mt_dst, e_tu_dst);
    scan4<<<4, 1024, 0, sB>>>(NTX, NMERCH, NTX, NUSER);
    build_fill<<<dim3(ceil_div(NEDGE, 256), 4), 256, 0, sB>>>(e_ut_src, e_ut_dst, e_tm_src, e_tm_dst,
                                                              e_mt_src, e_mt_dst, e_tu_src, e_tu_dst);
    cudaEventRecord(evCsr, sB);
    // sC: feature copies + weight prep
    cudaMemcpyAsync(ws->xu[0], x_user,  (size_t)NUSER  * HDIM * sizeof(float), cudaMemcpyDeviceToDevice, sC);
    cudaMemcpyAsync(ws->xm[0], x_merch, (size_t)NMERCH * HDIM * sizeof(float), cudaMemcpyDeviceToDevice, sC);
    prep_wsum<<<dim3(ceil_div(HDIM * HDIM, 256), NLAYER), 256, 0, sC>>>(Wr);
    prep_wcat<<<ceil_div(HDIM * HDIM, 256), 256, 0, sC>>>(Wc1, Wv1, bc1, bv1);
    cudaEventRecord(evPrep, sC);

    cudaStreamWaitEvent(s0, evCsr, 0);
    cudaStreamWaitEvent(s0, evPrep, 0);

    int cur = 0;
    for (int l = 0; l < NLAYER; l++) {
        float* xt  = ws->xt[cur];
        float* xu  = ws->xu[cur];
        float* xm  = ws->xm[cur];
        float* xtn = ws->xt[1 - cur];
        float* xun = ws->xu[1 - cur];
        float* xmn = ws->xm[1 - cur];

        const float* Wl0 = Wl + ((size_t)(l * 4 + 0)) * HDIM * HDIM;
        const float* Wl1 = Wl + ((size_t)(l * 4 + 1)) * HDIM * HDIM;
        const float* Wl2 = Wl + ((size_t)(l * 4 + 2)) * HDIM * HDIM;
        const float* Wl3 = Wl + ((size_t)(l * 4 + 3)) * HDIM * HDIM;
        const float* Wr1 = Wr + ((size_t)(l * 4 + 1)) * HDIM * HDIM;
        const float* Wr3 = Wr + ((size_t)(l * 4 + 3)) * HDIM * HDIM;
        const float* bl0 = bl + (size_t)(l * 4 + 0) * HDIM;
        const float* bl1 = bl + (size_t)(l * 4 + 1) * HDIM;
        const float* bl2 = bl + (size_t)(l * 4 + 2) * HDIM;
        const float* bl3 = bl + (size_t)(l * 4 + 3) * HDIM;

        cudaEventRecord(evForkL[l], s0);
        cudaStreamWaitEvent(sB, evForkL[l], 0);
        cudaStreamWaitEvent(sC, evForkL[l], 0);

        // --- sB: ym = xm@Wl2 ; seg_mean(xt->mm) ; xm_new GEMM ---
        {
            GemmArgs a = {};
            a.A[0] = xm; a.W[0] = Wl2;
            a.C = ws->ym; a.M = NMERCH; a.N = HDIM; a.nseg = 1; a.segK = HDIM;
            a.outscale = 1.0f; a.relu = 0;
            gemm_tf32<<<dim3(ceil_div(NMERCH, BM), HDIM / BN), 256, GEMM_SMEM_BYTES, sB>>>(a);
        }
        cudaEventRecord(evYm[l], sB);
        seg_mean<<<ceil_div(NMERCH * 32, 256), 256, 0, sB>>>(xt, 1, ws->mm, NMERCH);
        {
            GemmArgs a = {};
            a.A[0] = ws->mm; a.W[0] = Wl1;
            a.A[1] = xm;     a.W[1] = Wr1;
            a.b0 = bl1;
            a.C = xmn; a.M = NMERCH; a.N = HDIM; a.nseg = 2; a.segK = HDIM;
            a.outscale = 1.0f; a.relu = 1;
            gemm_tf32<<<dim3(ceil_div(NMERCH, BM), HDIM / BN), 256, GEMM_SMEM_BYTES, sB>>>(a);
        }
        cudaEventRecord(evB[l], sB);

        // --- sC: seg_mean(xt->mu) ; xu_new GEMM ---
        seg_mean<<<ceil_div(NUSER * 32, 256), 256, 0, sC>>>(xt, 3, ws->mu, NUSER);
        {
            GemmArgs a = {};
            a.A[0] = ws->mu; a.W[0] = Wl3;
            a.A[1] = xu;     a.W[1] = Wr3;
            a.b0 = bl3;
            a.C = xun; a.M = NUSER; a.N = HDIM; a.nseg = 2; a.segK = HDIM;
            a.outscale = 1.0f; a.relu = 1;
            gemm_tf32<<<dim3(ceil_div(NUSER, BM), HDIM / BN), 256, GEMM_SMEM_BYTES, sC>>>(a);
        }
        cudaEventRecord(evC[l], sC);

        // --- s0: yu = xu@Wl0 ; wait ym ; dual seg-mean ; xt GEMM (K=256) ---
        {
            GemmArgs a = {};
            a.A[0] = xu; a.W[0] = Wl0;
            a.C = ws->yu; a.M = NUSER; a.N = HDIM; a.nseg = 1; a.segK = HDIM;
            a.outscale = 1.0f; a.relu = 0;
            gemm_tf32<<<dim3(ceil_div(NUSER, BM), HDIM / BN), 256, GEMM_SMEM_BYTES, s0>>>(a);
        }
        cudaStreamWaitEvent(s0, evYm[l], 0);
        seg_mean_dual<<<ceil_div(NTX * 32, 256), 256, 0, s0>>>(ws->yu, ws->ym, ws->gts);
        {
            GemmArgs a = {};
            a.A[0] = xt; a.W[0] = ws->wsum[l];
            a.b0 = bl0; a.b1 = bl2;
            a.E0 = ws->gts;
            a.C = xtn; a.M = NTX; a.N = HDIM; a.nseg = 1; a.segK = HDIM;
            a.outscale = 0.5f; a.relu = 1;
            gemm_tf32<<<dim3(ceil_div(NTX, BM), HDIM / BN), 256, GEMM_SMEM_BYTES, s0>>>(a);
        }

        cudaStreamWaitEvent(s0, evB[l], 0);
        cudaStreamWaitEvent(s0, evC[l], 0);
        cur ^= 1;
    }

    // ---- heads ----
    float* xtf = ws->xt[cur];
    {
        GemmArgs a = {};
        a.A[0] = xtf; a.W[0] = ws->wcat; a.b0 = ws->bcat;
        a.C = ws->h1; a.M = NTX; a.N = HDIM; a.nseg = 1; a.segK = HDIM;
        a.outscale = 1.0f; a.relu = 1;
        gemm_tf32<<<dim3(ceil_div(NTX, BM), HDIM / BN), 256, GEMM_SMEM_BYTES, s0>>>(a);
    }
    head_out<<<ceil_div(NTX * 32, 256), 256, 0, s0>>>(ws->h1, Wc2, bc2, Wv2, bv2, out);
}

// round 8
// speedup vs baseline: 4.5606x; 1.3393x over previous
#include <cuda_runtime.h>
#include <cstdint>

#define NTX    100000
#define NUSER  20000
#define NMERCH 5000
#define NEDGE  400000
#define HDIM   256
#define HHALF  128
#define FIN    32

// ---------------------------------------------------------------------------
// Workspace (single __device__ global; no allocations allowed)
// ---------------------------------------------------------------------------
struct WS {
    float xt[2][NTX * HDIM];
    float gts[2][NTX * HDIM];     // per-layer dual seg-mean result
    float mm [NMERCH * HDIM];
    float mu [NUSER * HDIM];
    float yu [2][NUSER * HDIM];   // xu@Wl0 per layer
    float ym [2][NMERCH * HDIM];  // xm@Wl2 per layer
    float xu1[NUSER * HDIM];      // layer-1 user features
    float xm1[NMERCH * HDIM];     // layer-1 merch features
    float wsum[2][HDIM * HDIM];   // Wr0+Wr2 per layer
    float wcat[HDIM * HDIM];      // [Wc1 | Wv1]
    float bcat[HDIM];             // [bc1 | bv1]
    float w2cat[HDIM];            // [Wc2 | Wv2]
    int deg   [4][NTX];
    int cursor[4][NTX];
    int rowptr[4][NTX + 1];
    int perm  [4][NEDGE];
};
__device__ WS g_ws;

// relations: 0 = user->tx, 1 = tx->merch, 2 = merch->tx, 3 = tx->user
// ---------------------------------------------------------------------------
// CSR build
// ---------------------------------------------------------------------------
__global__ void build_count(const int* __restrict__ d0, const int* __restrict__ d1,
                            const int* __restrict__ d2, const int* __restrict__ d3) {
    int i = blockIdx.x * blockDim.x + threadIdx.x;
    if (i >= NEDGE) return;
    int rel = blockIdx.y;
    const int* d = (rel == 0) ? d0 : (rel == 1) ? d1 : (rel == 2) ? d2 : d3;
    atomicAdd(&g_ws.deg[rel][d[i]], 1);
}

__global__ void scan4(int n0, int n1, int n2, int n3) {
    int rel = blockIdx.x;
    int n = (rel == 0) ? n0 : (rel == 1) ? n1 : (rel == 2) ? n2 : n3;
    const int* deg = g_ws.deg[rel];
    int* rp = g_ws.rowptr[rel];
    __shared__ int wsum[32];
    __shared__ int s_carry;
    int tid = threadIdx.x, lane = tid & 31, wid = tid >> 5;
    if (tid == 0) s_carry = 0;
    __syncthreads();
    for (int base = 0; base < n; base += 1024) {
        int i = base + tid;
        int v = (i < n) ? deg[i] : 0;
        int x = v;
        #pragma unroll
        for (int off = 1; off < 32; off <<= 1) {
            int u = __shfl_up_sync(0xffffffffu, x, off);
            if (lane >= off) x += u;
        }
        if (lane == 31) wsum[wid] = x;
        __syncthreads();
        if (wid == 0) {
            int w = wsum[lane];
            int y = w;
            #pragma unroll
            for (int off = 1; off < 32; off <<= 1) {
                int u = __shfl_up_sync(0xffffffffu, y, off);
                if (lane >= off) y += u;
            }
            wsum[lane] = y - w;
        }
        __syncthreads();
        int incl = x + wsum[wid];
        int c = s_carry;
        __syncthreads();
        if (i < n) rp[i] = c + incl - v;
        if (tid == 1023) s_carry = c + incl;
        __syncthreads();
    }
    if (tid == 0) rp[n] = s_carry;
}

__global__ void build_fill(const int* __restrict__ s0, const int* __restrict__ d0,
                           const int* __restrict__ s1, const int* __restrict__ d1,
                           const int* __restrict__ s2, const int* __restrict__ d2,
                           const int* __restrict__ s3, const int* __restrict__ d3) {
    int i = blockIdx.x * blockDim.x + threadIdx.x;
    if (i >= NEDGE) return;
    int rel = blockIdx.y;
    const int* s = (rel == 0) ? s0 : (rel == 1) ? s1 : (rel == 2) ? s2 : s3;
    const int* d = (rel == 0) ? d0 : (rel == 1) ? d1 : (rel == 2) ? d2 : d3;
    int dst = d[i];
    int pos = g_ws.rowptr[rel][dst] + atomicAdd(&g_ws.cursor[rel][dst], 1);
    g_ws.perm[rel][pos] = s[i];
}

// ---------------------------------------------------------------------------
// Prep kernels
// ---------------------------------------------------------------------------
__global__ void prep_wsum(const float* __restrict__ Wr) {
    int i = blockIdx.x * blockDim.x + threadIdx.x;
    if (i >= HDIM * HDIM) return;
    int l = blockIdx.y;
    const float* Wr0 = Wr + ((size_t)(l * 4 + 0)) * HDIM * HDIM;
    const float* Wr2 = Wr + ((size_t)(l * 4 + 2)) * HDIM * HDIM;
    g_ws.wsum[l][i] = Wr0[i] + Wr2[i];
}

__global__ void prep_wcat(const float* __restrict__ Wc1, const float* __restrict__ Wv1,
                          const float* __restrict__ bc1, const float* __restrict__ bv1,
                          const float* __restrict__ Wc2, const float* __restrict__ Wv2) {
    int i = blockIdx.x * blockDim.x + threadIdx.x;
    if (i < HDIM * HDIM) {
        int k = i >> 8;
        int j = i & 255;
        float v = (j < HHALF) ? Wc1[k * HHALF + j] : Wv1[k * HHALF + (j - HHALF)];
        g_ws.wcat[i] = v;
    }
    if (i < HDIM) {
        g_ws.bcat[i]  = (i < HHALF) ? bc1[i] : bv1[i - HHALF];
        g_ws.w2cat[i] = (i < HHALF) ? Wc2[i] : Wv2[i - HHALF];
    }
}

// ---------------------------------------------------------------------------
// Segment-mean kernels
// ---------------------------------------------------------------------------
__global__ void seg_mean(const float* __restrict__ xsrc, int rel,
                         float* __restrict__ outm, int n_dst) {
    int w = (blockIdx.x * blockDim.x + threadIdx.x) >> 5;
    int lane = threadIdx.x & 31;
    if (w >= n_dst) return;
    const int* __restrict__ rp = g_ws.rowptr[rel];
    const int* __restrict__ pm = g_ws.perm[rel];
    int beg = rp[w], end = rp[w + 1];
    float4 a0 = make_float4(0.f, 0.f, 0.f, 0.f);
    float4 a1 = make_float4(0.f, 0.f, 0.f, 0.f);
    for (int e = beg; e < end; e++) {
        int s = pm[e];
        const float4* p = (const float4*)(xsrc + (size_t)s * HDIM);
        float4 v0 = p[lane];
        float4 v1 = p[lane + 32];
        a0.x += v0.x; a0.y += v0.y; a0.z += v0.z; a0.w += v0.w;
        a1.x += v1.x; a1.y += v1.y; a1.z += v1.z; a1.w += v1.w;
    }
    float inv = 1.0f / (float)max(end - beg, 1);
    a0.x *= inv; a0.y *= inv; a0.z *= inv; a0.w *= inv;
    a1.x *= inv; a1.y *= inv; a1.z *= inv; a1.w *= inv;
    float4* o = (float4*)(outm + (size_t)w * HDIM);
    o[lane] = a0;
    o[lane + 32] = a1;
}

__global__ void seg_mean_dual(const float* __restrict__ ya, const float* __restrict__ yb,
                              float* __restrict__ outm) {
    int w = (blockIdx.x * blockDim.x + threadIdx.x) >> 5;
    int lane = threadIdx.x & 31;
    if (w >= NTX) return;

    float4 r0 = make_float4(0.f, 0.f, 0.f, 0.f);
    float4 r1 = make_float4(0.f, 0.f, 0.f, 0.f);

    {
        const int* __restrict__ rp = g_ws.rowptr[0];
        const int* __restrict__ pm = g_ws.perm[0];
        int beg = rp[w], end = rp[w + 1];
        float4 a0 = make_float4(0.f, 0.f, 0.f, 0.f);
        float4 a1 = make_float4(0.f, 0.f, 0.f, 0.f);
        for (int e = beg; e < end; e++) {
            int s = pm[e];
            const float4* p = (const float4*)(ya + (size_t)s * HDIM);
            float4 v0 = p[lane];
            float4 v1 = p[lane + 32];
            a0.x += v0.x; a0.y += v0.y; a0.z += v0.z; a0.w += v0.w;
            a1.x += v1.x; a1.y += v1.y; a1.z += v1.z; a1.w += v1.w;
        }
        float inv = 1.0f / (float)max(end - beg, 1);
        r0.x += a0.x * inv; r0.y += a0.y * inv; r0.z += a0.z * inv; r0.w += a0.w * inv;
        r1.x += a1.x * inv; r1.y += a1.y * inv; r1.z += a1.z * inv; r1.w += a1.w * inv;
    }
    {
        const int* __restrict__ rp = g_ws.rowptr[2];
        const int* __restrict__ pm = g_ws.perm[2];
        int beg = rp[w], end = rp[w + 1];
        float4 a0 = make_float4(0.f, 0.f, 0.f, 0.f);
        float4 a1 = make_float4(0.f, 0.f, 0.f, 0.f);
        for (int e = beg; e < end; e++) {
            int s = pm[e];
            const float4* p = (const float4*)(yb + (size_t)s * HDIM);
            float4 v0 = p[lane];
            float4 v1 = p[lane + 32];
            a0.x += v0.x; a0.y += v0.y; a0.z += v0.z; a0.w += v0.w;
            a1.x += v1.x; a1.y += v1.y; a1.z += v1.z; a1.w += v1.w;
        }
        float inv = 1.0f / (float)max(end - beg, 1);
        r0.x += a0.x * inv; r0.y += a0.y * inv; r0.z += a0.z * inv; r0.w += a0.w * inv;
        r1.x += a1.x * inv; r1.y += a1.y * inv; r1.z += a1.z * inv; r1.w += a1.w * inv;
    }

    float4* o = (float4*)(outm + (size_t)w * HDIM);
    o[lane] = r0;
    o[lane + 32] = r1;
}

// ---------------------------------------------------------------------------
// Fused multi-segment GEMM on tf32 tensor cores, cp.async double-buffered.
// headmode: epilogue computes relu(acc+bias) dotted with w2, reduced per row,
// written straight to out (+bc2/bv2) — no h1 round-trip.
// ---------------------------------------------------------------------------
#define BM 128
#define BN 128
#define BK 32
#define ASTRIDE 36
#define WSTRIDE 136
#define A_FLOATS (BM * ASTRIDE)
#define W_FLOATS (BK * WSTRIDE)
#define STAGE_FLOATS (A_FLOATS + W_FLOATS)
#define GEMM_SMEM_BYTES (2 * STAGE_FLOATS * 4)

struct GemmArgs {
    const float* A[4];
    const float* W[4];
    const float* b0;
    const float* b1;
    const float* E0;
    float* C;
    int M, N, nseg, segK;
    float outscale;
    int relu;
    int headmode;
    const float* w2;     // [Wc2 | Wv2]
    const float* b2c;    // bc2 (1 elem)
    const float* b2v;    // bv2 (1 elem)
};

__device__ __forceinline__ uint32_t f2tf32(float f) {
    uint32_t u;
    asm("cvt.rna.tf32.f32 %0, %1;" : "=r"(u) : "f"(f));
    return u;
}

__device__ __forceinline__ void cp_async16(uint32_t smem_addr, const void* gptr, int src_bytes) {
    asm volatile("cp.async.cg.shared.global [%0], [%1], 16, %2;"
                 :: "r"(smem_addr), "l"(gptr), "r"(src_bytes));
}
__device__ __forceinline__ void cp_commit() {
    asm volatile("cp.async.commit_group;");
}
template <int N>
__device__ __forceinline__ void cp_wait() {
    asm volatile("cp.async.wait_group %0;" :: "n"(N));
}

__global__ void __launch_bounds__(256, 2) gemm_tf32(GemmArgs g) {
    extern __shared__ float smem[];

    int tid = threadIdx.x;
    int lane = tid & 31;
    int warp = tid >> 5;
    int wm = (warp & 3) * 32;
    int wn = (warp >> 2) * 64;
    int grp = lane >> 2;
    int tg  = lane & 3;

    int m0 = blockIdx.x * BM, n0 = blockIdx.y * BN;

    int a_row   = tid >> 1;
    int a_chunk = (tid & 1) * 4;
    int w_row   = tid >> 3;
    int w_chunk = (tid & 7) * 4;

    int a_grow = m0 + a_row;
    bool a_ok = (a_grow < g.M);

    uint32_t smem_base = (uint32_t)__cvta_generic_to_shared(smem);
    int ktiles = g.nseg * g.segK / BK;

    auto issue_tile = [&](int kt, int st) {
        int k0 = kt * BK;
        int seg = k0 / g.segK;
        int koff = k0 - seg * g.segK;
        const float* A = g.A[seg];
        const float* W = g.W[seg];

        uint32_t a_s = smem_base + (st * STAGE_FLOATS + a_row * ASTRIDE) * 4;
        const float* a_g = A + (size_t)a_grow * g.segK + koff;
        int a_sz = a_ok ? 16 : 0;
        #pragma unroll
        for (int c = 0; c < 4; c++)
            cp_async16(a_s + (a_chunk + c) * 16, a_g + (a_chunk + c) * 4, a_sz);

        uint32_t w_s = smem_base + (st * STAGE_FLOATS + A_FLOATS + w_row * WSTRIDE) * 4;
        const float* w_g = W + (size_t)(koff + w_row) * g.N + n0;
        #pragma unroll
        for (int c = 0; c < 4; c++)
            cp_async16(w_s + (w_chunk + c) * 16, w_g + (w_chunk + c) * 4, 16);

        cp_commit();
    };

    float acc[2][8][4];
    #pragma unroll
    for (int i = 0; i < 2; i++)
        #pragma unroll
        for (int j = 0; j < 8; j++)
            #pragma unroll
            for (int c = 0; c < 4; c++) acc[i][j][c] = 0.f;

    issue_tile(0, 0);

    for (int kt = 0; kt < ktiles; kt++) {
        int st = kt & 1;
        if (kt + 1 < ktiles) {
            issue_tile(kt + 1, (kt + 1) & 1);
            cp_wait<1>();
        } else {
            cp_wait<0>();
        }
        __syncthreads();

        const float* As = smem + st * STAGE_FLOATS;
        const float* Ws = smem + st * STAGE_FLOATS + A_FLOATS;

        #pragma unroll
        for (int ks = 0; ks < BK / 8; ks++) {
            int k8 = ks * 8;
            uint32_t afr[2][4];
            #pragma unroll
            for (int mi = 0; mi < 2; mi++) {
                int mb = wm + mi * 16;
                afr[mi][0] = f2tf32(As[(mb + grp) * ASTRIDE + k8 + tg]);
                afr[mi][1] = f2tf32(As[(mb + grp + 8) * ASTRIDE + k8 + tg]);
                afr[mi][2] = f2tf32(As[(mb + grp) * ASTRIDE + k8 + tg + 4]);
                afr[mi][3] = f2tf32(As[(mb + grp + 8) * ASTRIDE + k8 + tg + 4]);
            }
            uint32_t bfr[8][2];
            #pragma unroll
            for (int nt = 0; nt < 8; nt++) {
                int nb = wn + nt * 8 + grp;
                bfr[nt][0] = f2tf32(Ws[(k8 + tg) * WSTRIDE + nb]);
                bfr[nt][1] = f2tf32(Ws[(k8 + tg + 4) * WSTRIDE + nb]);
            }
            #pragma unroll
            for (int mi = 0; mi < 2; mi++) {
                #pragma unroll
                for (int nt = 0; nt < 8; nt++) {
                    asm volatile(
                        "mma.sync.aligned.m16n8k8.row.col.f32.tf32.tf32.f32 "
                        "{%0,%1,%2,%3}, {%4,%5,%6,%7}, {%8,%9}, {%0,%1,%2,%3};"
                        : "+f"(acc[mi][nt][0]), "+f"(acc[mi][nt][1]),
                          "+f"(acc[mi][nt][2]), "+f"(acc[mi][nt][3])
                        : "r"(afr[mi][0]), "r"(afr[mi][1]),
                          "r"(afr[mi][2]), "r"(afr[mi][3]),
                          "r"(bfr[nt][0]), "r"(bfr[nt][1]));
                }
            }
        }
        __syncthreads();
    }

    float bias[8][2];
    #pragma unroll
    for (int nt = 0; nt < 8; nt++) {
        int c = n0 + wn + nt * 8 + tg * 2;
        float b0v = 0.f, b1v = 0.f;
        if (g.b0) { b0v = g.b0[c] + (g.b1 ? g.b1[c] : 0.f); }
        if (g.b0) { b1v = g.b0[c + 1] + (g.b1 ? g.b1[c + 1] : 0.f); }
        bias[nt][0] = b0v;
        bias[nt][1] = b1v;
    }

    if (g.headmode) {
        // fused head: relu(acc+bias) dot w2, reduced per row, write out directly
        float* red = smem;  // reuse stage memory
        for (int i = tid; i < BM; i += 256) red[i] = 0.f;
        __syncthreads();
        #pragma unroll
        for (int mi = 0; mi < 2; mi++) {
            float p0 = 0.f, p1 = 0.f;
            #pragma unroll
            for (int nt = 0; nt < 8; nt++) {
                int c = n0 + wn + nt * 8 + tg * 2;
                float w20 = g.w2[c], w21 = g.w2[c + 1];
                float v00 = fmaxf(acc[mi][nt][0] + bias[nt][0], 0.f);
                float v01 = fmaxf(acc[mi][nt][1] + bias[nt][1], 0.f);
                float v10 = fmaxf(acc[mi][nt][2] + bias[nt][0], 0.f);
                float v11 = fmaxf(acc[mi][nt][3] + bias[nt][1], 0.f);
                p0 += v00 * w20 + v01 * w21;
                p1 += v10 * w20 + v11 * w21;
            }
            atomicAdd(&red[wm + mi * 16 + grp], p0);
            atomicAdd(&red[wm + mi * 16 + grp + 8], p1);
        }
        __syncthreads();
        if (tid < BM) {
            int row = m0 + tid;
            if (row < g.M) {
                int off = (n0 >= HHALF) ? NTX : 0;
                float b2 = (n0 >= HHALF) ? g.b2v[0] : g.b2c[0];
                g.C[off + row] = red[tid] + b2;
            }
        }
        return;
    }

    #pragma unroll
    for (int mi = 0; mi < 2; mi++) {
        int r0 = m0 + wm + mi * 16 + grp;
        int r1 = r0 + 8;
        #pragma unroll
        for (int nt = 0; nt < 8; nt++) {
            int c = n0 + wn + nt * 8 + tg * 2;
            if (r0 < g.M) {
                float e0 = 0.f, e1 = 0.f;
                if (g.E0) {
                    float2 t = *(const float2*)(g.E0 + (size_t)r0 * g.N + c);
                    e0 += t.x; e1 += t.y;
                }
                float v0 = (acc[mi][nt][0] + bias[nt][0] + e0) * g.outscale;
                float v1 = (acc[mi][nt][1] + bias[nt][1] + e1) * g.outscale;
                if (g.relu) { v0 = fmaxf(v0, 0.f); v1 = fmaxf(v1, 0.f); }
                *(float2*)(g.C + (size_t)r0 * g.N + c) = make_float2(v0, v1);
            }
            if (r1 < g.M) {
                float e0 = 0.f, e1 = 0.f;
                if (g.E0) {
                    float2 t = *(const float2*)(g.E0 + (size_t)r1 * g.N + c);
                    e0 += t.x; e1 += t.y;
                }
                float v0 = (acc[mi][nt][2] + bias[nt][0] + e0) * g.outscale;
                float v1 = (acc[mi][nt][3] + bias[nt][1] + e1) * g.outscale;
                if (g.relu) { v0 = fmaxf(v0, 0.f); v1 = fmaxf(v1, 0.f); }
                *(float2*)(g.C + (size_t)r1 * g.N + c) = make_float2(v0, v1);
            }
        }
    }
}

// ---------------------------------------------------------------------------
// Host orchestration: fully unrolled 2-layer DAG with cross-layer pipelining
// ---------------------------------------------------------------------------
static inline int ceil_div(int a, int b) { return (a + b - 1) / b; }

extern "C" void kernel_launch(void* const* d_in, const int* in_sizes, int n_in,
                              void* d_out, int out_size) {
    const float* x_tx   = (const float*)d_in[0];
    const float* x_user = (const float*)d_in[1];
    const float* x_merch= (const float*)d_in[2];
    const float* Wp     = (const float*)d_in[3];
    const float* bp     = (const float*)d_in[4];
    const float* Wl     = (const float*)d_in[5];
    const float* bl     = (const float*)d_in[6];
    const float* Wr     = (const float*)d_in[7];
    const float* Wc1    = (const float*)d_in[8];
    const float* bc1    = (const float*)d_in[9];
    const float* Wc2    = (const float*)d_in[10];
    const float* bc2    = (const float*)d_in[11];
    const float* Wv1    = (const float*)d_in[12];
    const float* bv1    = (const float*)d_in[13];
    const float* Wv2    = (const float*)d_in[14];
    const float* bv2    = (const float*)d_in[15];
    const int* e_ut_src = (const int*)d_in[16];
    const int* e_ut_dst = (const int*)d_in[17];
    const int* e_tm_src = (const int*)d_in[18];
    const int* e_tm_dst = (const int*)d_in[19];
    const int* e_mt_src = (const int*)d_in[20];
    const int* e_mt_dst = (const int*)d_in[21];
    const int* e_tu_src = (const int*)d_in[22];
    const int* e_tu_dst = (const int*)d_in[23];
    float* out = (float*)d_out;

    WS* ws = nullptr;
    cudaGetSymbolAddress((void**)&ws, g_ws);

    static cudaStream_t sB = nullptr, sC = nullptr;
    static cudaEvent_t ev[10];
    if (!sB) {
        cudaStreamCreateWithFlags(&sB, cudaStreamNonBlocking);
        cudaStreamCreateWithFlags(&sC, cudaStreamNonBlocking);
        for (int i = 0; i < 10; i++)
            cudaEventCreateWithFlags(&ev[i], cudaEventDisableTiming);
        cudaFuncSetAttribute(gemm_tf32, cudaFuncAttributeMaxDynamicSharedMemorySize,
                             GEMM_SMEM_BYTES);
    }
    cudaStream_t s0 = 0;
    cudaEvent_t evFork0 = ev[0], evProj = ev[1], evCsr = ev[2];
    cudaEvent_t evY0 = ev[3], evPrep = ev[4], evYm1 = ev[5], evGts1 = ev[6];

    // per-layer weight pointers
    const float* Wl0_0 = Wl + (size_t)0 * HDIM * HDIM;
    const float* Wl1_0 = Wl + (size_t)1 * HDIM * HDIM;
    const float* Wl2_0 = Wl + (size_t)2 * HDIM * HDIM;
    const float* Wl3_0 = Wl + (size_t)3 * HDIM * HDIM;
    const float* Wl0_1 = Wl + (size_t)4 * HDIM * HDIM;
    const float* Wl2_1 = Wl + (size_t)6 * HDIM * HDIM;
    const float* Wr1_0 = Wr + (size_t)1 * HDIM * HDIM;
    const float* Wr3_0 = Wr + (size_t)3 * HDIM * HDIM;
    const float* bl0_0 = bl + 0 * HDIM;
    const float* bl1_0 = bl + 1 * HDIM;
    const float* bl2_0 = bl + 2 * HDIM;
    const float* bl3_0 = bl + 3 * HDIM;
    const float* bl0_1 = bl + 4 * HDIM;
    const float* bl2_1 = bl + 6 * HDIM;

    // ---- fork ----
    cudaEventRecord(evFork0, s0);
    cudaStreamWaitEvent(sB, evFork0, 0);
    cudaStreamWaitEvent(sC, evFork0, 0);

    // ======== s0: proj ========
    {
        GemmArgs a = {};
        a.A[0] = x_tx; a.W[0] = Wp; a.b0 = bp;
        a.C = ws->xt[0]; a.M = NTX; a.N = HDIM; a.nseg = 1; a.segK = FIN;
        a.outscale = 1.0f; a.relu = 0;
        gemm_tf32<<<dim3(ceil_div(NTX, BM), HDIM / BN), 256, GEMM_SMEM_BYTES, s0>>>(a);
    }
    cudaEventRecord(evProj, s0);

    // ======== sB: CSR build, then mm0 -> xm1 -> ym1 ========
    cudaMemsetAsync(ws->deg,    0, sizeof(ws->deg),    sB);
    cudaMemsetAsync(ws->cursor, 0, sizeof(ws->cursor), sB);
    build_count<<<dim3(ceil_div(NEDGE, 256), 4), 256, 0, sB>>>(e_ut_dst, e_tm_dst, e_mt_dst, e_tu_dst);
    scan4<<<4, 1024, 0, sB>>>(NTX, NMERCH, NTX, NUSER);
    build_fill<<<dim3(ceil_div(NEDGE, 256), 4), 256, 0, sB>>>(e_ut_src, e_ut_dst, e_tm_src, e_tm_dst,
                                                              e_mt_src, e_mt_dst, e_tu_src, e_tu_dst);
    cudaEventRecord(evCsr, sB);
    cudaStreamWaitEvent(sB, evProj, 0);
    seg_mean<<<ceil_div(NMERCH * 32, 256), 256, 0, sB>>>(ws->xt[0], 1, ws->mm, NMERCH);
    {   // xm1 = relu(mm@Wl1_0 + bl1_0 + x_merch@Wr1_0)
        GemmArgs a = {};
        a.A[0] = ws->mm;  a.W[0] = Wl1_0;
        a.A[1] = x_merch; a.W[1] = Wr1_0;
        a.b0 = bl1_0;
        a.C = ws->xm1; a.M = NMERCH; a.N = HDIM; a.nseg = 2; a.segK = HDIM;
        a.outscale = 1.0f; a.relu = 1;
        gemm_tf32<<<dim3(ceil_div(NMERCH, BM), HDIM / BN), 256, GEMM_SMEM_BYTES, sB>>>(a);
    }
    {   // ym1 = xm1 @ Wl2_1
        GemmArgs a = {};
        a.A[0] = ws->xm1; a.W[0] = Wl2_1;
        a.C = ws->ym[1]; a.M = NMERCH; a.N = HDIM; a.nseg = 1; a.segK = HDIM;
        a.outscale = 1.0f; a.relu = 0;
        gemm_tf32<<<dim3(ceil_div(NMERCH, BM), HDIM / BN), 256, GEMM_SMEM_BYTES, sB>>>(a);
    }
    cudaEventRecord(evYm1, sB);

    // ======== sC: yu0/ym0, prep, then mu0 -> xu1 -> yu1 -> dual1 ========
    {   // yu0 = x_user @ Wl0_0
        GemmArgs a = {};
        a.A[0] = x_user; a.W[0] = Wl0_0;
        a.C = ws->yu[0]; a.M = NUSER; a.N = HDIM; a.nseg = 1; a.segK = HDIM;
        a.outscale = 1.0f; a.relu = 0;
        gemm_tf32<<<dim3(ceil_div(NUSER, BM), HDIM / BN), 256, GEMM_SMEM_BYTES, sC>>>(a);
    }
    {   // ym0 = x_merch @ Wl2_0
        GemmArgs a = {};
        a.A[0] = x_merch; a.W[0] = Wl2_0;
        a.C = ws->ym[0]; a.M = NMERCH; a.N = HDIM; a.nseg = 1; a.segK = HDIM;
        a.outscale = 1.0f; a.relu = 0;
        gemm_tf32<<<dim3(ceil_div(NMERCH, BM), HDIM / BN), 256, GEMM_SMEM_BYTES, sC>>>(a);
    }
    cudaEventRecord(evY0, sC);
    prep_wsum<<<dim3(ceil_div(HDIM * HDIM, 256), 2), 256, 0, sC>>>(Wr);
    prep_wcat<<<ceil_div(HDIM * HDIM, 256), 256, 0, sC>>>(Wc1, Wv1, bc1, bv1, Wc2, Wv2);
    cudaEventRecord(evPrep, sC);
    cudaStreamWaitEvent(sC, evCsr, 0);
    cudaStreamWaitEvent(sC, evProj, 0);
    seg_mean<<<ceil_div(NUSER * 32, 256), 256, 0, sC>>>(ws->xt[0], 3, ws->mu, NUSER);
    {   // xu1 = relu(mu@Wl3_0 + bl3_0 + x_user@Wr3_0)
        GemmArgs a = {};
        a.A[0] = ws->mu; a.W[0] = Wl3_0;
        a.A[1] = x_user; a.W[1] = Wr3_0;
        a.b0 = bl3_0;
        a.C = ws->xu1; a.M = NUSER; a.N = HDIM; a.nseg = 2; a.segK = HDIM;
        a.outscale = 1.0f; a.relu = 1;
        gemm_tf32<<<dim3(ceil_div(NUSER, BM), HDIM / BN), 256, GEMM_SMEM_BYTES, sC>>>(a);
    }
    {   // yu1 = xu1 @ Wl0_1
        GemmArgs a = {};
        a.A[0] = ws->xu1; a.W[0] = Wl0_1;
        a.C = ws->yu[1]; a.M = NUSER; a.N = HDIM; a.nseg = 1; a.segK = HDIM;
        a.outscale = 1.0f; a.relu = 0;
        gemm_tf32<<<dim3(ceil_div(NUSER, BM), HDIM / BN), 256, GEMM_SMEM_BYTES, sC>>>(a);
    }
    cudaStreamWaitEvent(sC, evYm1, 0);
    seg_mean_dual<<<ceil_div(NTX * 32, 256), 256, 0, sC>>>(ws->yu[1], ws->ym[1], ws->gts[1]);
    cudaEventRecord(evGts1, sC);

    // ======== s0: dual0 -> xtL0 -> xtL1 -> fused head ========
    cudaStreamWaitEvent(s0, evY0, 0);
    cudaStreamWaitEvent(s0, evCsr, 0);
    seg_mean_dual<<<ceil_div(NTX * 32, 256), 256, 0, s0>>>(ws->yu[0], ws->ym[0], ws->gts[0]);
    cudaStreamWaitEvent(s0, evPrep, 0);
    {   // xt1 = relu(0.5*(gts0 + bl0_0 + bl2_0 + xt0@wsum0))
        GemmArgs a = {};
        a.A[0] = ws->xt[0]; a.W[0] = ws->wsum[0];
        a.b0 = bl0_0; a.b1 = bl2_0;
        a.E0 = ws->gts[0];
        a.C = ws->xt[1]; a.M = NTX; a.N = HDIM; a.nseg = 1; a.segK = HDIM;
        a.outscale = 0.5f; a.relu = 1;
        gemm_tf32<<<dim3(ceil_div(NTX, BM), HDIM / BN), 256, GEMM_SMEM_BYTES, s0>>>(a);
    }
    cudaStreamWaitEvent(s0, evGts1, 0);
    {   // xt2 = relu(0.5*(gts1 + bl0_1 + bl2_1 + xt1@wsum1))
        GemmArgs a = {};
        a.A[0] = ws->xt[1]; a.W[0] = ws->wsum[1];
        a.b0 = bl0_1; a.b1 = bl2_1;
        a.E0 = ws->gts[1];
        a.C = ws->xt[0]; a.M = NTX; a.N = HDIM; a.nseg = 1; a.segK = HDIM;
        a.outscale = 0.5f; a.relu = 1;
        gemm_tf32<<<dim3(ceil_div(NTX, BM), HDIM / BN), 256, GEMM_SMEM_BYTES, s0>>>(a);
    }
    {   // fused head: out = [relu(xt2@Wc1+bc1)@Wc2+bc2 | relu(xt2@Wv1+bv1)@Wv2+bv2]
        GemmArgs a = {};
        a.A[0] = ws->xt[0]; a.W[0] = ws->wcat; a.b0 = ws->bcat;
        a.C = out; a.M = NTX; a.N = HDIM; a.nseg = 1; a.segK = HDIM;
        a.outscale = 1.0f; a.relu = 1;
        a.headmode = 1; a.w2 = ws->w2cat; a.b2c = bc2; a.b2v = bv2;
        gemm_tf32<<<dim3(ceil_div(NTX, BM), HDIM / BN), 256, GEMM_SMEM_BYTES, s0>>>(a);
    }
}

// round 9
// speedup vs baseline: 5.5702x; 1.2214x over previous
#include <cuda_runtime.h>
#include <cuda_fp16.h>
#include <cstdint>

#define NTX    100000
#define NUSER  20000
#define NMERCH 5000
#define NEDGE  400000
#define HDIM   256
#define HHALF  128
#define FIN    32

// ---------------------------------------------------------------------------
// Workspace (single __device__ global; no allocations allowed)
// ---------------------------------------------------------------------------
struct WS {
    float xt[2][NTX * HDIM];
    float gts[2][NTX * HDIM];
    float mm [NMERCH * HDIM];
    float mu [NUSER * HDIM];
    float yu [2][NUSER * HDIM];
    float ym [2][NMERCH * HDIM];
    float xu1[NUSER * HDIM];
    float xm1[NMERCH * HDIM];
    float bcat[HDIM];
    float w2cat[HDIM];
    // fp16 weights, transposed to [n][k]
    __half wp_h  [HDIM * FIN];
    __half wl0h[2][HDIM * HDIM];   // Wl0 layer 0,1
    __half wl2h[2][HDIM * HDIM];   // Wl2 layer 0,1
    __half wl1h  [HDIM * HDIM];    // Wl1 layer 0
    __half wr1h  [HDIM * HDIM];    // Wr1 layer 0
    __half wl3h  [HDIM * HDIM];    // Wl3 layer 0
    __half wr3h  [HDIM * HDIM];    // Wr3 layer 0
    __half wsum_h[2][HDIM * HDIM]; // Wr0+Wr2 per layer
    __half wcat_h[HDIM * HDIM];    // [Wc1 | Wv1]
    int deg   [4][NTX];
    int cursor[4][NTX];
    int rowptr[4][NTX + 1];
    int perm  [4][NEDGE];
};
__device__ WS g_ws;

// relations: 0 = user->tx, 1 = tx->merch, 2 = merch->tx, 3 = tx->user
// ---------------------------------------------------------------------------
// CSR build
// ---------------------------------------------------------------------------
__global__ void build_count(const int* __restrict__ d0, const int* __restrict__ d1,
                            const int* __restrict__ d2, const int* __restrict__ d3) {
    int i = blockIdx.x * blockDim.x + threadIdx.x;
    if (i >= NEDGE) return;
    int rel = blockIdx.y;
    const int* d = (rel == 0) ? d0 : (rel == 1) ? d1 : (rel == 2) ? d2 : d3;
    atomicAdd(&g_ws.deg[rel][d[i]], 1);
}

__global__ void scan4(int n0, int n1, int n2, int n3) {
    int rel = blockIdx.x;
    int n = (rel == 0) ? n0 : (rel == 1) ? n1 : (rel == 2) ? n2 : n3;
    const int* deg = g_ws.deg[rel];
    int* rp = g_ws.rowptr[rel];
    __shared__ int wsum[32];
    __shared__ int s_carry;
    int tid = threadIdx.x, lane = tid & 31, wid = tid >> 5;
    if (tid == 0) s_carry = 0;
    __syncthreads();
    for (int base = 0; base < n; base += 1024) {
        int i = base + tid;
        int v = (i < n) ? deg[i] : 0;
        int x = v;
        #pragma unroll
        for (int off = 1; off < 32; off <<= 1) {
            int u = __shfl_up_sync(0xffffffffu, x, off);
            if (lane >= off) x += u;
        }
        if (lane == 31) wsum[wid] = x;
        __syncthreads();
        if (wid == 0) {
            int w = wsum[lane];
            int y = w;
            #pragma unroll
            for (int off = 1; off < 32; off <<= 1) {
                int u = __shfl_up_sync(0xffffffffu, y, off);
                if (lane >= off) y += u;
            }
            wsum[lane] = y - w;
        }
        __syncthreads();
        int incl = x + wsum[wid];
        int c = s_carry;
        __syncthreads();
        if (i < n) rp[i] = c + incl - v;
        if (tid == 1023) s_carry = c + incl;
        __syncthreads();
    }
    if (tid == 0) rp[n] = s_carry;
}

__global__ void build_fill(const int* __restrict__ s0, const int* __restrict__ d0,
                           const int* __restrict__ s1, const int* __restrict__ d1,
                           const int* __restrict__ s2, const int* __restrict__ d2,
                           const int* __restrict__ s3, const int* __restrict__ d3) {
    int i = blockIdx.x * blockDim.x + threadIdx.x;
    if (i >= NEDGE) return;
    int rel = blockIdx.y;
    const int* s = (rel == 0) ? s0 : (rel == 1) ? s1 : (rel == 2) ? s2 : s3;
    const int* d = (rel == 0) ? d0 : (rel == 1) ? d1 : (rel == 2) ? d2 : d3;
    int dst = d[i];
    int pos = g_ws.rowptr[rel][dst] + atomicAdd(&g_ws.cursor[rel][dst], 1);
    g_ws.perm[rel][pos] = s[i];
}

// ---------------------------------------------------------------------------
// Prep kernels: fp16 transposed weights
// ---------------------------------------------------------------------------
__global__ void conv_w(const float* __restrict__ in, __half* __restrict__ out, int K) {
    int i = blockIdx.x * blockDim.x + threadIdx.x;
    if (i >= HDIM * K) return;
    int n = i / K, k = i % K;
    out[i] = __float2half(in[k * HDIM + n]);
}

__global__ void prep_wsum_h(const float* __restrict__ Wr) {
    int i = blockIdx.x * blockDim.x + threadIdx.x;
    if (i >= HDIM * HDIM) return;
    int l = blockIdx.y;
    int n = i >> 8, k = i & 255;
    const float* Wr0 = Wr + ((size_t)(l * 4 + 0)) * HDIM * HDIM;
    const float* Wr2 = Wr + ((size_t)(l * 4 + 2)) * HDIM * HDIM;
    g_ws.wsum_h[l][i] = __float2half(Wr0[k * HDIM + n] + Wr2[k * HDIM + n]);
}

__global__ void prep_wcat_h(const float* __restrict__ Wc1, const float* __restrict__ Wv1,
                            const float* __restrict__ bc1, const float* __restrict__ bv1,
                            const float* __restrict__ Wc2, const float* __restrict__ Wv2) {
    int i = blockIdx.x * blockDim.x + threadIdx.x;
    if (i < HDIM * HDIM) {
        int n = i >> 8, k = i & 255;
        float v = (n < HHALF) ? Wc1[k * HHALF + n] : Wv1[k * HHALF + (n - HHALF)];
        g_ws.wcat_h[i] = __float2half(v);
    }
    if (i < HDIM) {
        g_ws.bcat[i]  = (i < HHALF) ? bc1[i] : bv1[i - HHALF];
        g_ws.w2cat[i] = (i < HHALF) ? Wc2[i] : Wv2[i - HHALF];
    }
}

// ---------------------------------------------------------------------------
// Segment-mean kernels
// ---------------------------------------------------------------------------
__global__ void seg_mean(const float* __restrict__ xsrc, int rel,
                         float* __restrict__ outm, int n_dst) {
    int w = (blockIdx.x * blockDim.x + threadIdx.x) >> 5;
    int lane = threadIdx.x & 31;
    if (w >= n_dst) return;
    const int* __restrict__ rp = g_ws.rowptr[rel];
    const int* __restrict__ pm = g_ws.perm[rel];
    int beg = rp[w], end = rp[w + 1];
    float4 a0 = make_float4(0.f, 0.f, 0.f, 0.f);
    float4 a1 = make_float4(0.f, 0.f, 0.f, 0.f);
    for (int e = beg; e < end; e++) {
        int s = pm[e];
        const float4* p = (const float4*)(xsrc + (size_t)s * HDIM);
        float4 v0 = p[lane];
        float4 v1 = p[lane + 32];
        a0.x += v0.x; a0.y += v0.y; a0.z += v0.z; a0.w += v0.w;
        a1.x += v1.x; a1.y += v1.y; a1.z += v1.z; a1.w += v1.w;
    }
    float inv = 1.0f / (float)max(end - beg, 1);
    a0.x *= inv; a0.y *= inv; a0.z *= inv; a0.w *= inv;
    a1.x *= inv; a1.y *= inv; a1.z *= inv; a1.w *= inv;
    float4* o = (float4*)(outm + (size_t)w * HDIM);
    o[lane] = a0;
    o[lane + 32] = a1;
}

__global__ void seg_mean_dual(const float* __restrict__ ya, const float* __restrict__ yb,
                              float* __restrict__ outm) {
    int w = (blockIdx.x * blockDim.x + threadIdx.x) >> 5;
    int lane = threadIdx.x & 31;
    if (w >= NTX) return;

    float4 r0 = make_float4(0.f, 0.f, 0.f, 0.f);
    float4 r1 = make_float4(0.f, 0.f, 0.f, 0.f);

    {
        const int* __restrict__ rp = g_ws.rowptr[0];
        const int* __restrict__ pm = g_ws.perm[0];
        int beg = rp[w], end = rp[w + 1];
        float4 a0 = make_float4(0.f, 0.f, 0.f, 0.f);
        float4 a1 = make_float4(0.f, 0.f, 0.f, 0.f);
        for (int e = beg; e < end; e++) {
            int s = pm[e];
            const float4* p = (const float4*)(ya + (size_t)s * HDIM);
            float4 v0 = p[lane];
            float4 v1 = p[lane + 32];
            a0.x += v0.x; a0.y += v0.y; a0.z += v0.z; a0.w += v0.w;
            a1.x += v1.x; a1.y += v1.y; a1.z += v1.z; a1.w += v1.w;
        }
        float inv = 1.0f / (float)max(end - beg, 1);
        r0.x += a0.x * inv; r0.y += a0.y * inv; r0.z += a0.z * inv; r0.w += a0.w * inv;
        r1.x += a1.x * inv; r1.y += a1.y * inv; r1.z += a1.z * inv; r1.w += a1.w * inv;
    }
    {
        const int* __restrict__ rp = g_ws.rowptr[2];
        const int* __restrict__ pm = g_ws.perm[2];
        int beg = rp[w], end = rp[w + 1];
        float4 a0 = make_float4(0.f, 0.f, 0.f, 0.f);
        float4 a1 = make_float4(0.f, 0.f, 0.f, 0.f);
        for (int e = beg; e < end; e++) {
            int s = pm[e];
            const float4* p = (const float4*)(yb + (size_t)s * HDIM);
            float4 v0 = p[lane];
            float4 v1 = p[lane + 32];
            a0.x += v0.x; a0.y += v0.y; a0.z += v0.z; a0.w += v0.w;
            a1.x += v1.x; a1.y += v1.y; a1.z += v1.z; a1.w += v1.w;
        }
        float inv = 1.0f / (float)max(end - beg, 1);
        r0.x += a0.x * inv; r0.y += a0.y * inv; r0.z += a0.z * inv; r0.w += a0.w * inv;
        r1.x += a1.x * inv; r1.y += a1.y * inv; r1.z += a1.z * inv; r1.w += a1.w * inv;
    }

    float4* o = (float4*)(outm + (size_t)w * HDIM);
    o[lane] = r0;
    o[lane + 32] = r1;
}

// ---------------------------------------------------------------------------
// Fused multi-segment GEMM: fp16 tensor cores (mma.sync.m16n8k16.f16, fp32 acc),
// cp.async double-buffered. A fp32 [m][k] (cvt at fragment), W fp16 [n][k].
// ---------------------------------------------------------------------------
#define BM 128
#define BN 128
#define BK 32
#define AST 40                       // A smem stride in floats (160B, 16B-aligned)
#define WPAD 56                      // W smem stride in halves (112B, 16B-aligned)
#define A_STAGE_BYTES (BM * AST * 4)     // 20480
#define W_STAGE_BYTES (BN * WPAD * 2)    // 14336
#define STAGE_BYTES (A_STAGE_BYTES + W_STAGE_BYTES)  // 34816
#define GEMM_SMEM_BYTES (2 * STAGE_BYTES)            // 69632

struct GemmArgs {
    const float* A[4];
    const __half* W[4];
    const float* b0;
    const float* b1;
    const float* E0;
    float* C;
    int M, N, nseg, segK;
    float outscale;
    int relu;
    int headmode;
    const float* w2;
    const float* b2c;
    const float* b2v;
};

__device__ __forceinline__ uint32_t packh2(float x, float y) {
    __half2 h = __floats2half2_rn(x, y);
    return *(uint32_t*)&h;
}

__device__ __forceinline__ void cp_async16(uint32_t smem_addr, const void* gptr, int src_bytes) {
    asm volatile("cp.async.cg.shared.global [%0], [%1], 16, %2;"
                 :: "r"(smem_addr), "l"(gptr), "r"(src_bytes));
}
__device__ __forceinline__ void cp_commit() {
    asm volatile("cp.async.commit_group;");
}
template <int N>
__device__ __forceinline__ void cp_wait() {
    asm volatile("cp.async.wait_group %0;" :: "n"(N));
}

__global__ void __launch_bounds__(256, 2) gemm_fp16(GemmArgs g) {
    extern __shared__ char smem_c[];

    int tid = threadIdx.x;
    int lane = tid & 31;
    int warp = tid >> 5;
    int wm = (warp & 3) * 32;
    int wn = (warp >> 2) * 64;
    int grp = lane >> 2;
    int tg  = lane & 3;

    int m0 = blockIdx.x * BM, n0 = blockIdx.y * BN;

    int ld_row = tid >> 1;          // 0..127 (both A row and W row)
    int a_cb = (tid & 1) * 4;       // A: chunks 0-7 of 16B, 4 per thread
    int w_cb = (tid & 1) * 2;       // W: chunks 0-3 of 16B, 2 per thread

    int a_grow = m0 + ld_row;
    bool a_ok = (a_grow < g.M);

    uint32_t smem_base = (uint32_t)__cvta_generic_to_shared(smem_c);
    int ktiles = g.nseg * g.segK / BK;

    auto issue_tile = [&](int kt, int st) {
        int k0 = kt * BK;
        int seg = k0 / g.segK;
        int koff = k0 - seg * g.segK;
        const float* A = g.A[seg];
        const __half* W = g.W[seg];

        uint32_t a_s = smem_base + st * STAGE_BYTES + ld_row * (AST * 4);
        const float* a_g = A + (size_t)a_grow * g.segK + koff;
        int a_sz = a_ok ? 16 : 0;
        #pragma unroll
        for (int c = 0; c < 4; c++)
            cp_async16(a_s + (a_cb + c) * 16, a_g + (a_cb + c) * 4, a_sz);

        uint32_t w_s = smem_base + st * STAGE_BYTES + A_STAGE_BYTES + ld_row * (WPAD * 2);
        const __half* w_g = W + (size_t)(n0 + ld_row) * g.segK + koff;
        #pragma unroll
        for (int c = 0; c < 2; c++)
            cp_async16(w_s + (w_cb + c) * 16, w_g + (w_cb + c) * 8, 16);

        cp_commit();
    };

    float acc[2][8][4];
    #pragma unroll
    for (int i = 0; i < 2; i++)
        #pragma unroll
        for (int j = 0; j < 8; j++)
            #pragma unroll
            for (int c = 0; c < 4; c++) acc[i][j][c] = 0.f;

    issue_tile(0, 0);

    for (int kt = 0; kt < ktiles; kt++) {
        int st = kt & 1;
        if (kt + 1 < ktiles) {
            issue_tile(kt + 1, (kt + 1) & 1);
            cp_wait<1>();
        } else {
            cp_wait<0>();
        }
        __syncthreads();

        const float* As = (const float*)(smem_c + st * STAGE_BYTES);
        const __half* Ws = (const __half*)(smem_c + st * STAGE_BYTES + A_STAGE_BYTES);

        #pragma unroll
        for (int ks = 0; ks < BK / 16; ks++) {
            int kb = ks * 16;
            uint32_t afr[2][4];
            #pragma unroll
            for (int mi = 0; mi < 2; mi++) {
                int r = wm + mi * 16 + grp;
                float2 f00 = *(const float2*)(As + r * AST + kb + 2 * tg);
                float2 f10 = *(const float2*)(As + (r + 8) * AST + kb + 2 * tg);
                float2 f01 = *(const float2*)(As + r * AST + kb + 8 + 2 * tg);
                float2 f11 = *(const float2*)(As + (r + 8) * AST + kb + 8 + 2 * tg);
                afr[mi][0] = packh2(f00.x, f00.y);
                afr[mi][1] = packh2(f10.x, f10.y);
                afr[mi][2] = packh2(f01.x, f01.y);
                afr[mi][3] = packh2(f11.x, f11.y);
            }
            uint32_t bfr[8][2];
            #pragma unroll
            for (int nt = 0; nt < 8; nt++) {
                int nb = wn + nt * 8 + grp;
                bfr[nt][0] = *(const uint32_t*)(Ws + nb * WPAD + kb + 2 * tg);
                bfr[nt][1] = *(const uint32_t*)(Ws + nb * WPAD + kb + 8 + 2 * tg);
            }
            #pragma unroll
            for (int mi = 0; mi < 2; mi++) {
                #pragma unroll
                for (int nt = 0; nt < 8; nt++) {
                    asm volatile(
                        "mma.sync.aligned.m16n8k16.row.col.f32.f16.f16.f32 "
                        "{%0,%1,%2,%3}, {%4,%5,%6,%7}, {%8,%9}, {%0,%1,%2,%3};"
                        : "+f"(acc[mi][nt][0]), "+f"(acc[mi][nt][1]),
                          "+f"(acc[mi][nt][2]), "+f"(acc[mi][nt][3])
                        : "r"(afr[mi][0]), "r"(afr[mi][1]),
                          "r"(afr[mi][2]), "r"(afr[mi][3]),
                          "r"(bfr[nt][0]), "r"(bfr[nt][1]));
                }
            }
        }
        __syncthreads();
    }

    float bias[8][2];
    #pragma unroll
    for (int nt = 0; nt < 8; nt++) {
        int c = n0 + wn + nt * 8 + tg * 2;
        float b0v = 0.f, b1v = 0.f;
        if (g.b0) { b0v = g.b0[c] + (g.b1 ? g.b1[c] : 0.f); }
        if (g.b0) { b1v = g.b0[c + 1] + (g.b1 ? g.b1[c + 1] : 0.f); }
        bias[nt][0] = b0v;
        bias[nt][1] = b1v;
    }

    if (g.headmode) {
        float* red = (float*)smem_c;
        for (int i = tid; i < BM; i += 256) red[i] = 0.f;
        __syncthreads();
        #pragma unroll
        for (int mi = 0; mi < 2; mi++) {
            float p0 = 0.f, p1 = 0.f;
            #pragma unroll
            for (int nt = 0; nt < 8; nt++) {
                int c = n0 + wn + nt * 8 + tg * 2;
                float w20 = g.w2[c], w21 = g.w2[c + 1];
                float v00 = fmaxf(acc[mi][nt][0] + bias[nt][0], 0.f);
                float v01 = fmaxf(acc[mi][nt][1] + bias[nt][1], 0.f);
                float v10 = fmaxf(acc[mi][nt][2] + bias[nt][0], 0.f);
                float v11 = fmaxf(acc[mi][nt][3] + bias[nt][1], 0.f);
                p0 += v00 * w20 + v01 * w21;
                p1 += v10 * w20 + v11 * w21;
            }
            atomicAdd(&red[wm + mi * 16 + grp], p0);
            atomicAdd(&red[wm + mi * 16 + grp + 8], p1);
        }
        __syncthreads();
        if (tid < BM) {
            int row = m0 + tid;
            if (row < g.M) {
                int off = (n0 >= HHALF) ? NTX : 0;
                float b2 = (n0 >= HHALF) ? g.b2v[0] : g.b2c[0];
                g.C[off + row] = red[tid] + b2;
            }
        }
        return;
    }

    #pragma unroll
    for (int mi = 0; mi < 2; mi++) {
        int r0 = m0 + wm + mi * 16 + grp;
        int r1 = r0 + 8;
        #pragma unroll
        for (int nt = 0; nt < 8; nt++) {
            int c = n0 + wn + nt * 8 + tg * 2;
            if (r0 < g.M) {
                float e0 = 0.f, e1 = 0.f;
                if (g.E0) {
                    float2 t = *(const float2*)(g.E0 + (size_t)r0 * g.N + c);
                    e0 += t.x; e1 += t.y;
                }
                float v0 = (acc[mi][nt][0] + bias[nt][0] + e0) * g.outscale;
                float v1 = (acc[mi][nt][1] + bias[nt][1] + e1) * g.outscale;
                if (g.relu) { v0 = fmaxf(v0, 0.f); v1 = fmaxf(v1, 0.f); }
                *(float2*)(g.C + (size_t)r0 * g.N + c) = make_float2(v0, v1);
            }
            if (r1 < g.M) {
                float e0 = 0.f, e1 = 0.f;
                if (g.E0) {
                    float2 t = *(const float2*)(g.E0 + (size_t)r1 * g.N + c);
                    e0 += t.x; e1 += t.y;
                }
                float v0 = (acc[mi][nt][2] + bias[nt][0] + e0) * g.outscale;
                float v1 = (acc[mi][nt][3] + bias[nt][1] + e1) * g.outscale;
                if (g.relu) { v0 = fmaxf(v0, 0.f); v1 = fmaxf(v1, 0.f); }
                *(float2*)(g.C + (size_t)r1 * g.N + c) = make_float2(v0, v1);
            }
        }
    }
}

// ---------------------------------------------------------------------------
// Host orchestration
// ---------------------------------------------------------------------------
static inline int ceil_div(int a, int b) { return (a + b - 1) / b; }

extern "C" void kernel_launch(void* const* d_in, const int* in_sizes, int n_in,
                              void* d_out, int out_size) {
    const float* x_tx   = (const float*)d_in[0];
    const float* x_user = (const float*)d_in[1];
    const float* x_merch= (const float*)d_in[2];
    const float* Wp     = (const float*)d_in[3];
    const float* bp     = (const float*)d_in[4];
    const float* Wl     = (const float*)d_in[5];
    const float* bl     = (const float*)d_in[6];
    const float* Wr     = (const float*)d_in[7];
    const float* Wc1    = (const float*)d_in[8];
    const float* bc1    = (const float*)d_in[9];
    const float* Wc2    = (const float*)d_in[10];
    const float* bc2    = (const float*)d_in[11];
    const float* Wv1    = (const float*)d_in[12];
    const float* bv1    = (const float*)d_in[13];
    const float* Wv2    = (const float*)d_in[14];
    const float* bv2    = (const float*)d_in[15];
    const int* e_ut_src = (const int*)d_in[16];
    const int* e_ut_dst = (const int*)d_in[17];
    const int* e_tm_src = (const int*)d_in[18];
    const int* e_tm_dst = (const int*)d_in[19];
    const int* e_mt_src = (const int*)d_in[20];
    const int* e_mt_dst = (const int*)d_in[21];
    const int* e_tu_src = (const int*)d_in[22];
    const int* e_tu_dst = (const int*)d_in[23];
    float* out = (float*)d_out;

    WS* ws = nullptr;
    cudaGetSymbolAddress((void**)&ws, g_ws);

    static cudaStream_t sB = nullptr, sC = nullptr;
    static cudaEvent_t ev[10];
    if (!sB) {
        cudaStreamCreateWithFlags(&sB, cudaStreamNonBlocking);
        cudaStreamCreateWithFlags(&sC, cudaStreamNonBlocking);
        for (int i = 0; i < 10; i++)
            cudaEventCreateWithFlags(&ev[i], cudaEventDisableTiming);
        cudaFuncSetAttribute(gemm_fp16, cudaFuncAttributeMaxDynamicSharedMemorySize,
                             GEMM_SMEM_BYTES);
    }
    cudaStream_t s0 = 0;
    cudaEvent_t evFork0 = ev[0], evProj = ev[1], evCsr = ev[2];
    cudaEvent_t evY0 = ev[3], evPrep = ev[4], evYm1 = ev[5], evGts1 = ev[6];

    const float* Wl0_0 = Wl + (size_t)0 * HDIM * HDIM;
    const float* Wl1_0 = Wl + (size_t)1 * HDIM * HDIM;
    const float* Wl2_0 = Wl + (size_t)2 * HDIM * HDIM;
    const float* Wl3_0 = Wl + (size_t)3 * HDIM * HDIM;
    const float* Wl0_1 = Wl + (size_t)4 * HDIM * HDIM;
    const float* Wl2_1 = Wl + (size_t)6 * HDIM * HDIM;
    const float* Wr1_0 = Wr + (size_t)1 * HDIM * HDIM;
    const float* Wr3_0 = Wr + (size_t)3 * HDIM * HDIM;
    const float* bl0_0 = bl + 0 * HDIM;
    const float* bl1_0 = bl + 1 * HDIM;
    const float* bl2_0 = bl + 2 * HDIM;
    const float* bl3_0 = bl + 3 * HDIM;
    const float* bl0_1 = bl + 4 * HDIM;
    const float* bl2_1 = bl + 6 * HDIM;

    cudaEventRecord(evFork0, s0);
    cudaStreamWaitEvent(sB, evFork0, 0);
    cudaStreamWaitEvent(sC, evFork0, 0);

    // ======== sC: weight prep (fp16 transposed), then yu0/ym0, mu0 chain ========
    int cg = ceil_div(HDIM * HDIM, 256);
    conv_w<<<ceil_div(HDIM * FIN, 256), 256, 0, sC>>>(Wp, ws->wp_h, FIN);
    conv_w<<<cg, 256, 0, sC>>>(Wl0_0, ws->wl0h[0], HDIM);
    conv_w<<<cg, 256, 0, sC>>>(Wl2_0, ws->wl2h[0], HDIM);
    conv_w<<<cg, 256, 0, sC>>>(Wl0_1, ws->wl0h[1], HDIM);
    conv_w<<<cg, 256, 0, sC>>>(Wl2_1, ws->wl2h[1], HDIM);
    conv_w<<<cg, 256, 0, sC>>>(Wl1_0, ws->wl1h, HDIM);
    conv_w<<<cg, 256, 0, sC>>>(Wr1_0, ws->wr1h, HDIM);
    conv_w<<<cg, 256, 0, sC>>>(Wl3_0, ws->wl3h, HDIM);
    conv_w<<<cg, 256, 0, sC>>>(Wr3_0, ws->wr3h, HDIM);
    prep_wsum_h<<<dim3(cg, 2), 256, 0, sC>>>(Wr);
    prep_wcat_h<<<cg, 256, 0, sC>>>(Wc1, Wv1, bc1, bv1, Wc2, Wv2);
    cudaEventRecord(evPrep, sC);

    // ======== sB: CSR build ========
    cudaMemsetAsync(ws->deg,    0, sizeof(ws->deg),    sB);
    cudaMemsetAsync(ws->cursor, 0, sizeof(ws->cursor), sB);
    build_count<<<dim3(ceil_div(NEDGE, 256), 4), 256, 0, sB>>>(e_ut_dst, e_tm_dst, e_mt_dst, e_tu_dst);
    scan4<<<4, 1024, 0, sB>>>(NTX, NMERCH, NTX, NUSER);
    build_fill<<<dim3(ceil_div(NEDGE, 256), 4), 256, 0, sB>>>(e_ut_src, e_ut_dst, e_tm_src, e_tm_dst,
                                                              e_mt_src, e_mt_dst, e_tu_src, e_tu_dst);
    cudaEventRecord(evCsr, sB);

    // ======== s0: proj ========
    cudaStreamWaitEvent(s0, evPrep, 0);
    {
        GemmArgs a = {};
        a.A[0] = x_tx; a.W[0] = ws->wp_h; a.b0 = bp;
        a.C = ws->xt[0]; a.M = NTX; a.N = HDIM; a.nseg = 1; a.segK = FIN;
        a.outscale = 1.0f; a.relu = 0;
        gemm_fp16<<<dim3(ceil_div(NTX, BM), HDIM / BN), 256, GEMM_SMEM_BYTES, s0>>>(a);
    }
    cudaEventRecord(evProj, s0);

    // ======== sB (cont): mm0 -> xm1 -> ym1 ========
    cudaStreamWaitEvent(sB, evProj, 0);
    seg_mean<<<ceil_div(NMERCH * 32, 256), 256, 0, sB>>>(ws->xt[0], 1, ws->mm, NMERCH);
    {
        GemmArgs a = {};
        a.A[0] = ws->mm;  a.W[0] = ws->wl1h;
        a.A[1] = x_merch; a.W[1] = ws->wr1h;
        a.b0 = bl1_0;
        a.C = ws->xm1; a.M = NMERCH; a.N = HDIM; a.nseg = 2; a.segK = HDIM;
        a.outscale = 1.0f; a.relu = 1;
        gemm_fp16<<<dim3(ceil_div(NMERCH, BM), HDIM / BN), 256, GEMM_SMEM_BYTES, sB>>>(a);
    }
    {
        GemmArgs a = {};
        a.A[0] = ws->xm1; a.W[0] = ws->wl2h[1];
        a.C = ws->ym[1]; a.M = NMERCH; a.N = HDIM; a.nseg = 1; a.segK = HDIM;
        a.outscale = 1.0f; a.relu = 0;
        gemm_fp16<<<dim3(ceil_div(NMERCH, BM), HDIM / BN), 256, GEMM_SMEM_BYTES, sB>>>(a);
    }
    cudaEventRecord(evYm1, sB);

    // ======== sC (cont): yu0/ym0, mu0 -> xu1 -> yu1 -> dual1 ========
    {
        GemmArgs a = {};
        a.A[0] = x_user; a.W[0] = ws->wl0h[0];
        a.C = ws->yu[0]; a.M = NUSER; a.N = HDIM; a.nseg = 1; a.segK = HDIM;
        a.outscale = 1.0f; a.relu = 0;
        gemm_fp16<<<dim3(ceil_div(NUSER, BM), HDIM / BN), 256, GEMM_SMEM_BYTES, sC>>>(a);
    }
    {
        GemmArgs a = {};
        a.A[0] = x_merch; a.W[0] = ws->wl2h[0];
        a.C = ws->ym[0]; a.M = NMERCH; a.N = HDIM; a.nseg = 1; a.segK = HDIM;
        a.outscale = 1.0f; a.relu = 0;
        gemm_fp16<<<dim3(ceil_div(NMERCH, BM), HDIM / BN), 256, GEMM_SMEM_BYTES, sC>>>(a);
    }
    cudaEventRecord(evY0, sC);
    cudaStreamWaitEvent(sC, evCsr, 0);
    cudaStreamWaitEvent(sC, evProj, 0);
    seg_mean<<<ceil_div(NUSER * 32, 256), 256, 0, sC>>>(ws->xt[0], 3, ws->mu, NUSER);
    {
        GemmArgs a = {};
        a.A[0] = ws->mu; a.W[0] = ws->wl3h;
        a.A[1] = x_user; a.W[1] = ws->wr3h;
        a.b0 = bl3_0;
        a.C = ws->xu1; a.M = NUSER; a.N = HDIM; a.nseg = 2; a.segK = HDIM;
        a.outscale = 1.0f; a.relu = 1;
        gemm_fp16<<<dim3(ceil_div(NUSER, BM), HDIM / BN), 256, GEMM_SMEM_BYTES, sC>>>(a);
    }
    {
        GemmArgs a = {};
        a.A[0] = ws->xu1; a.W[0] = ws->wl0h[1];
        a.C = ws->yu[1]; a.M = NUSER; a.N = HDIM; a.nseg = 1; a.segK = HDIM;
        a.outscale = 1.0f; a.relu = 0;
        gemm_fp16<<<dim3(ceil_div(NUSER, BM), HDIM / BN), 256, GEMM_SMEM_BYTES, sC>>>(a);
    }
    cudaStreamWaitEvent(sC, evYm1, 0);
    seg_mean_dual<<<ceil_div(NTX * 32, 256), 256, 0, sC>>>(ws->yu[1], ws->ym[1], ws->gts[1]);
    cudaEventRecord(evGts1, sC);

    // ======== s0: dual0 -> xtL0 -> xtL1 -> fused head ========
    cudaStreamWaitEvent(s0, evY0, 0);
    cudaStreamWaitEvent(s0, evCsr, 0);
    seg_mean_dual<<<ceil_div(NTX * 32, 256), 256, 0, s0>>>(ws->yu[0], ws->ym[0], ws->gts[0]);
    {
        GemmArgs a = {};
        a.A[0] = ws->xt[0]; a.W[0] = ws->wsum_h[0];
        a.b0 = bl0_0; a.b1 = bl2_0;
        a.E0 = ws->gts[0];
        a.C = ws->xt[1]; a.M = NTX; a.N = HDIM; a.nseg = 1; a.segK = HDIM;
        a.outscale = 0.5f; a.relu = 1;
        gemm_fp16<<<dim3(ceil_div(NTX, BM), HDIM / BN), 256, GEMM_SMEM_BYTES, s0>>>(a);
    }
    cudaStreamWaitEvent(s0, evGts1, 0);
    {
        GemmArgs a = {};
        a.A[0] = ws->xt[1]; a.W[0] = ws->wsum_h[1];
        a.b0 = bl0_1; a.b1 = bl2_1;
        a.E0 = ws->gts[1];
        a.C = ws->xt[0]; a.M = NTX; a.N = HDIM; a.nseg = 1; a.segK = HDIM;
        a.outscale = 0.5f; a.relu = 1;
        gemm_fp16<<<dim3(ceil_div(NTX, BM), HDIM / BN), 256, GEMM_SMEM_BYTES, s0>>>(a);
    }
    {
        GemmArgs a = {};
        a.A[0] = ws->xt[0]; a.W[0] = ws->wcat_h; a.b0 = ws->bcat;
        a.C = out; a.M = NTX; a.N = HDIM; a.nseg = 1; a.segK = HDIM;
        a.outscale = 1.0f; a.relu = 1;
        a.headmode = 1; a.w2 = ws->w2cat; a.b2c = bc2; a.b2v = bv2;
        gemm_fp16<<<dim3(ceil_div(NTX, BM), HDIM / BN), 256, GEMM_SMEM_BYTES, s0>>>(a);
    }
}